// round 1
// baseline (speedup 1.0000x reference)
#include <cuda_runtime.h>
#include <math.h>

#define L    2048
#define DM   768
#define H    12
#define HD   64
#define WIN  128
#define TQ   16
#define NROWS 144   // 143 rows used, 144 allocated

static constexpr float SCALE = 0.03608439182435161f;  // 1/sqrt(768)

// ---------------- scratch (static device globals; no allocs allowed) ----------
__device__ float g_qkv[L * 3 * DM];      // raw qkv gemm output  [l][3*768]
__device__ float g_q[H * L * HD];        // rope'd q  [h][l][d]
__device__ float g_k[H * L * HD];        // rope'd k  [h][l][d]
__device__ float g_v[H * L * HD];        // v         [h][l][d]
__device__ float g_attn[L * DM];         // attention out, joined layout [l][h*64+d]

// ---------------- generic tiled fp32 GEMM with bias --------------------------
// C[M,N] = A[M,K] @ B[K,N] + bias[N].  All row-major, dims multiples of tiles.
template<int BM, int BN, int BK, int TM, int TN>
__global__ void __launch_bounds__((BM/TM)*(BN/TN))
sgemm_bias(const float* __restrict__ A, const float* __restrict__ B,
           const float* __restrict__ bias, float* __restrict__ C,
           int M, int N, int K) {
    constexpr int THREADS = (BM/TM)*(BN/TN);
    __shared__ float As[BK][BM];
    __shared__ float Bs[BK][BN];

    const int bm = blockIdx.y, bn = blockIdx.x;
    const int tid = threadIdx.x;
    const int tx = tid % (BN/TN);
    const int ty = tid / (BN/TN);

    float acc[TM][TN] = {};

    const float* Ab = A + (size_t)bm * BM * K;
    const float* Bb = B + (size_t)bn * BN;

    constexpr int AK4 = BK / 4;
    const int arow = tid / AK4;
    const int acol = (tid % AK4) * 4;
    constexpr int AROWS_PER = THREADS / AK4;
    constexpr int BN4 = BN / 4;
    const int brow = tid / BN4;
    const int bcol = (tid % BN4) * 4;
    constexpr int BROWS_PER = THREADS / BN4;

    for (int k0 = 0; k0 < K; k0 += BK) {
        #pragma unroll
        for (int r = 0; r < BM; r += AROWS_PER) {
            int row = r + arow;
            float4 a = *(const float4*)(Ab + (size_t)row * K + k0 + acol);
            As[acol + 0][row] = a.x;
            As[acol + 1][row] = a.y;
            As[acol + 2][row] = a.z;
            As[acol + 3][row] = a.w;
        }
        #pragma unroll
        for (int r = 0; r < BK; r += BROWS_PER) {
            int row = r + brow;
            *(float4*)(&Bs[row][bcol]) = *(const float4*)(Bb + (size_t)(k0 + row) * N + bcol);
        }
        __syncthreads();

        #pragma unroll
        for (int k = 0; k < BK; k++) {
            float ra[TM], rb[TN];
            #pragma unroll
            for (int i = 0; i < TM; i++) ra[i] = As[k][ty*TM + i];
            #pragma unroll
            for (int j = 0; j < TN; j++) rb[j] = Bs[k][tx*TN + j];
            #pragma unroll
            for (int i = 0; i < TM; i++)
                #pragma unroll
                for (int j = 0; j < TN; j++)
                    acc[i][j] += ra[i] * rb[j];
        }
        __syncthreads();
    }

    #pragma unroll
    for (int i = 0; i < TM; i++) {
        int row = bm*BM + ty*TM + i;
        #pragma unroll
        for (int j = 0; j < TN; j += 4) {
            int col = bn*BN + tx*TN + j;
            float4 o;
            o.x = acc[i][j+0] + bias[col+0];
            o.y = acc[i][j+1] + bias[col+1];
            o.z = acc[i][j+2] + bias[col+2];
            o.w = acc[i][j+3] + bias[col+3];
            *(float4*)(C + (size_t)row * N + col) = o;
        }
    }
}

// ---------------- RoPE + head split: g_qkv -> g_q / g_k / g_v -----------------
// grid = L, block = 384 (12 heads * 32 rotation pairs)
__global__ void __launch_bounds__(384) rope_split_kernel() {
    int l = blockIdx.x;
    int t = threadIdx.x;
    int h = t >> 5;        // 0..11
    int i = t & 31;        // 0..31

    const float* row = g_qkv + (size_t)l * (3*DM);
    float invf = powf(10000.0f, -(float)i * (1.0f/32.0f));
    float ang = (float)l * invf;
    float s, c;
    sincosf(ang, &s, &c);

    int qo = h*HD + i;
    float q1 = row[qo],        q2 = row[qo + 32];
    float k1 = row[DM + qo],   k2 = row[DM + qo + 32];
    int o = (h*L + l)*HD + i;
    g_q[o]      = q1*c - q2*s;
    g_q[o + 32] = q1*s + q2*c;
    g_k[o]      = k1*c - k2*s;
    g_k[o + 32] = k1*s + k2*c;
    g_v[o]      = row[2*DM + qo];
    g_v[o + 32] = row[2*DM + qo + 32];
}

// ---------------- sliding-window attention -----------------------------------
// One block handles (head h, 16 consecutive queries). Warp w = query l0+w.
// K/V rows [l0-64, l0+78] staged in smem with stride-65 padding (odd stride ->
// conflict-free for both row-per-lane and col-per-lane access patterns).
__global__ void __launch_bounds__(512) window_attn_kernel(const int* __restrict__ mask) {
    extern __shared__ float sm[];
    float* ks = sm;                        // NROWS * 65
    float* vs = ks + NROWS * 65;           // NROWS * 65
    float* qs = vs + NROWS * 65;           // TQ * 64
    float* ws = qs + TQ * HD;              // TQ * 128 (softmax weights)
    int*   rv = (int*)(ws + TQ * WIN);     // NROWS row-valid flags

    int h  = blockIdx.x / (L / TQ);
    int qt = blockIdx.x % (L / TQ);
    int l0 = qt * TQ;
    int lo = l0 - 64;
    int tid = threadIdx.x;

    for (int idx = tid; idx < NROWS; idx += 512) {
        int lr = lo + idx;
        rv[idx] = (lr >= 0 && lr < L) ? (mask[lr] != 0) : 0;
    }
    for (int idx = tid; idx < NROWS * HD; idx += 512) {
        int r = idx >> 6, d = idx & 63;
        int lr = lo + r;
        bool val = (lr >= 0 && lr < L);
        int g = (h*L + (val ? lr : 0))*HD + d;
        ks[r*65 + d] = val ? g_k[g] : 0.0f;
        vs[r*65 + d] = val ? g_v[g] : 0.0f;
    }
    for (int idx = tid; idx < TQ * HD; idx += 512) {
        qs[idx] = g_q[(h*L + l0)*HD + idx];
    }
    __syncthreads();

    int wq   = tid >> 5;   // warp index = query within tile
    int lane = tid & 31;
    int l = l0 + wq;

    // scores: lane handles window positions lane, lane+32, lane+64, lane+96
    float sc[4];
    #pragma unroll
    for (int w4 = 0; w4 < 4; w4++) {
        int r = wq + lane + w4*32;          // row = (l-l0) + w
        float s = 0.f;
        #pragma unroll
        for (int d = 0; d < HD; d++)
            s += ks[r*65 + d] * qs[wq*HD + d];
        sc[w4] = rv[r] ? s * SCALE : -1e30f;
    }

    float m = fmaxf(fmaxf(sc[0], sc[1]), fmaxf(sc[2], sc[3]));
    #pragma unroll
    for (int o = 16; o > 0; o >>= 1) m = fmaxf(m, __shfl_xor_sync(0xffffffffu, m, o));
    float e[4], sum = 0.f;
    #pragma unroll
    for (int w4 = 0; w4 < 4; w4++) { e[w4] = expf(sc[w4] - m); sum += e[w4]; }
    #pragma unroll
    for (int o = 16; o > 0; o >>= 1) sum += __shfl_xor_sync(0xffffffffu, sum, o);
    float inv = 1.0f / sum;
    #pragma unroll
    for (int w4 = 0; w4 < 4; w4++) ws[wq*WIN + lane + w4*32] = e[w4] * inv;
    __syncwarp();

    // output: lane owns dims lane and lane+32
    float a0 = 0.f, a1 = 0.f;
    #pragma unroll 4
    for (int w = 0; w < WIN; w++) {
        float wt = ws[wq*WIN + w];
        int r = wq + w;
        a0 += wt * vs[r*65 + lane];
        a1 += wt * vs[r*65 + lane + 32];
    }
    g_attn[(size_t)l*DM + h*HD + lane]      = a0;
    g_attn[(size_t)l*DM + h*HD + lane + 32] = a1;
}

// ---------------- CLS row (l=0): full attention over all 2048 keys -----------
// grid = H, block = 256
__global__ void __launch_bounds__(256) cls_attn_kernel(const int* __restrict__ mask) {
    __shared__ float q0[HD];
    __shared__ float wl[L];
    __shared__ float red[256];
    __shared__ float pacc[4 * HD];

    int h = blockIdx.x;
    int tid = threadIdx.x;
    if (tid < HD) q0[tid] = g_q[(h*L + 0)*HD + tid];
    __syncthreads();

    float sc[8];
    float lm = -1e30f;
    #pragma unroll
    for (int c = 0; c < 8; c++) {
        int l = tid + c*256;
        const float* kr = g_k + (size_t)(h*L + l)*HD;
        float s = 0.f;
        #pragma unroll
        for (int d = 0; d < HD; d++) s += kr[d] * q0[d];
        s = (mask[l] != 0) ? s * SCALE : -1e30f;
        sc[c] = s;
        lm = fmaxf(lm, s);
    }
    red[tid] = lm; __syncthreads();
    for (int o = 128; o > 0; o >>= 1) {
        if (tid < o) red[tid] = fmaxf(red[tid], red[tid + o]);
        __syncthreads();
    }
    float m = red[0];
    __syncthreads();

    float ls = 0.f;
    #pragma unroll
    for (int c = 0; c < 8; c++) {
        float e = expf(sc[c] - m);
        wl[tid + c*256] = e;
        ls += e;
    }
    red[tid] = ls; __syncthreads();
    for (int o = 128; o > 0; o >>= 1) {
        if (tid < o) red[tid] += red[tid + o];
        __syncthreads();
    }
    float inv = 1.0f / red[0];
    __syncthreads();

    // output: 4 chunks of 512 keys, 64 dims
    int d = tid & 63;
    int c = tid >> 6;
    float acc = 0.f;
    for (int l = c*512; l < (c+1)*512; l++)
        acc += wl[l] * g_v[(size_t)(h*L + l)*HD + d];
    pacc[c*HD + d] = acc;
    __syncthreads();
    if (tid < HD) {
        float o = (pacc[tid] + pacc[HD + tid] + pacc[2*HD + tid] + pacc[3*HD + tid]) * inv;
        g_attn[(size_t)0*DM + h*HD + tid] = o;
    }
}

// ---------------- launch ------------------------------------------------------
extern "C" void kernel_launch(void* const* d_in, const int* in_sizes, int n_in,
                              void* d_out, int out_size) {
    (void)in_sizes; (void)n_in; (void)out_size;
    const float* emb   = (const float*)d_in[0];
    const int*   mask  = (const int*)  d_in[1];
    const float* W_qkv = (const float*)d_in[2];
    const float* b_qkv = (const float*)d_in[3];
    const float* W_o   = (const float*)d_in[4];
    const float* b_o   = (const float*)d_in[5];
    float* out = (float*)d_out;

    float *p_qkv, *p_attn;
    cudaGetSymbolAddress((void**)&p_qkv,  g_qkv);
    cudaGetSymbolAddress((void**)&p_attn, g_attn);

    // 1. QKV GEMM: [2048,768] x [768,2304]
    sgemm_bias<128,128,16,8,8><<<dim3((3*DM)/128, L/128), 256>>>(
        emb, W_qkv, b_qkv, p_qkv, L, 3*DM, DM);

    // 2. RoPE + head split
    rope_split_kernel<<<L, 384>>>();

    // 3. sliding-window attention
    constexpr int SMEM_WIN = (NROWS*65*2 + TQ*HD + TQ*WIN) * 4 + NROWS * 4;
    cudaFuncSetAttribute(window_attn_kernel,
                         cudaFuncAttributeMaxDynamicSharedMemorySize, SMEM_WIN);
    window_attn_kernel<<<H * (L/TQ), 512, SMEM_WIN>>>(mask);

    // 4. CLS row overwrite (must run after window kernel)
    cls_attn_kernel<<<H, 256>>>(mask);

    // 5. output projection: [2048,768] x [768,768]
    sgemm_bias<64,128,16,8,8><<<dim3(DM/128, L/64), 128>>>(
        p_attn, W_o, b_o, out, L, DM, DM);
}

// round 2
// speedup vs baseline: 1.1870x; 1.1870x over previous
#include <cuda_runtime.h>
#include <math.h>

#define L    2048
#define DM   768
#define H    12
#define HD   64
#define WIN  128
#define TQ   16
#define NROWS 144
#define NCHUNK 16      // cls split-softmax chunks
#define CKEYS  128     // keys per cls chunk

static constexpr float SCALE = 0.03608439182435161f;  // 1/sqrt(768)

// ---------------- scratch ------------------------------------------------------
__device__ float g_qkv[L * 3 * DM];
__device__ float g_q[H * L * HD];
__device__ float g_k[H * L * HD];
__device__ float g_v[H * L * HD];
__device__ float g_attn[L * DM];
__device__ float g_cls_m[H * NCHUNK];
__device__ float g_cls_s[H * NCHUNK];
__device__ float g_cls_o[H * NCHUNK * HD];

// ---------------- double-buffered tiled fp32 GEMM with bias --------------------
template<int BM, int BN, int BK, int TM, int TN>
__global__ void __launch_bounds__((BM/TM)*(BN/TN))
sgemm_bias_db(const float* __restrict__ A, const float* __restrict__ B,
              const float* __restrict__ bias, float* __restrict__ C,
              int M, int N, int K) {
    constexpr int THREADS = (BM/TM)*(BN/TN);
    __shared__ float As[2][BK][BM];
    __shared__ float Bs[2][BK][BN];

    const int bm = blockIdx.y, bn = blockIdx.x;
    const int tid = threadIdx.x;
    const int tx = tid % (BN/TN);
    const int ty = tid / (BN/TN);

    float acc[TM][TN] = {};

    const float* Ab = A + (size_t)bm * BM * K;
    const float* Bb = B + (size_t)bn * BN;

    constexpr int AK4 = BK / 4;
    const int arow = tid / AK4;
    const int acol = (tid % AK4) * 4;
    constexpr int AROWS_PER = THREADS / AK4;
    constexpr int A_ITERS = BM / AROWS_PER;
    constexpr int BN4 = BN / 4;
    const int brow = tid / BN4;
    const int bcol = (tid % BN4) * 4;
    constexpr int BROWS_PER = THREADS / BN4;
    constexpr int B_ITERS = BK / BROWS_PER;

    float4 a_reg[A_ITERS], b_reg[B_ITERS];

    auto load_regs = [&](int k0) {
        #pragma unroll
        for (int i = 0; i < A_ITERS; i++)
            a_reg[i] = *(const float4*)(Ab + (size_t)(i*AROWS_PER + arow) * K + k0 + acol);
        #pragma unroll
        for (int i = 0; i < B_ITERS; i++)
            b_reg[i] = *(const float4*)(Bb + (size_t)(k0 + i*BROWS_PER + brow) * N + bcol);
    };
    auto store_smem = [&](int buf) {
        #pragma unroll
        for (int i = 0; i < A_ITERS; i++) {
            int row = i*AROWS_PER + arow;
            As[buf][acol + 0][row] = a_reg[i].x;
            As[buf][acol + 1][row] = a_reg[i].y;
            As[buf][acol + 2][row] = a_reg[i].z;
            As[buf][acol + 3][row] = a_reg[i].w;
        }
        #pragma unroll
        for (int i = 0; i < B_ITERS; i++)
            *(float4*)(&Bs[buf][i*BROWS_PER + brow][bcol]) = b_reg[i];
    };

    load_regs(0);
    store_smem(0);
    __syncthreads();

    const int ntiles = K / BK;
    for (int t = 0; t < ntiles; t++) {
        const int cur = t & 1;
        if (t + 1 < ntiles) load_regs((t + 1) * BK);

        #pragma unroll
        for (int k = 0; k < BK; k++) {
            float ra[TM], rb[TN];
            #pragma unroll
            for (int i = 0; i < TM; i++) ra[i] = As[cur][k][ty*TM + i];
            #pragma unroll
            for (int j = 0; j < TN; j++) rb[j] = Bs[cur][k][tx*TN + j];
            #pragma unroll
            for (int i = 0; i < TM; i++)
                #pragma unroll
                for (int j = 0; j < TN; j++)
                    acc[i][j] += ra[i] * rb[j];
        }

        if (t + 1 < ntiles) store_smem(cur ^ 1);
        __syncthreads();
    }

    #pragma unroll
    for (int i = 0; i < TM; i++) {
        int row = bm*BM + ty*TM + i;
        #pragma unroll
        for (int j = 0; j < TN; j += 4) {
            int col = bn*BN + tx*TN + j;
            float4 o;
            o.x = acc[i][j+0] + bias[col+0];
            o.y = acc[i][j+1] + bias[col+1];
            o.z = acc[i][j+2] + bias[col+2];
            o.w = acc[i][j+3] + bias[col+3];
            *(float4*)(C + (size_t)row * N + col) = o;
        }
    }
}

// ---------------- RoPE + head split --------------------------------------------
__global__ void __launch_bounds__(384) rope_split_kernel() {
    int l = blockIdx.x;
    int t = threadIdx.x;
    int h = t >> 5;
    int i = t & 31;

    const float* row = g_qkv + (size_t)l * (3*DM);
    float invf = powf(10000.0f, -(float)i * (1.0f/32.0f));
    float ang = (float)l * invf;
    float s, c;
    sincosf(ang, &s, &c);

    int qo = h*HD + i;
    float q1 = row[qo],        q2 = row[qo + 32];
    float k1 = row[DM + qo],   k2 = row[DM + qo + 32];
    int o = (h*L + l)*HD + i;
    g_q[o]      = q1*c - q2*s;
    g_q[o + 32] = q1*s + q2*c;
    g_k[o]      = k1*c - k2*s;
    g_k[o + 32] = k1*s + k2*c;
    g_v[o]      = row[2*DM + qo];
    g_v[o + 32] = row[2*DM + qo + 32];
}

// ---------------- sliding-window attention --------------------------------------
__global__ void __launch_bounds__(512) window_attn_kernel(const int* __restrict__ mask) {
    extern __shared__ float sm[];
    float* ks = sm;
    float* vs = ks + NROWS * 65;
    float* qs = vs + NROWS * 65;
    float* ws = qs + TQ * HD;
    int*   rv = (int*)(ws + TQ * WIN);

    int h  = blockIdx.x / (L / TQ);
    int qt = blockIdx.x % (L / TQ);
    int l0 = qt * TQ;
    int lo = l0 - 64;
    int tid = threadIdx.x;

    for (int idx = tid; idx < NROWS; idx += 512) {
        int lr = lo + idx;
        rv[idx] = (lr >= 0 && lr < L) ? (mask[lr] != 0) : 0;
    }
    for (int idx = tid; idx < NROWS * HD; idx += 512) {
        int r = idx >> 6, d = idx & 63;
        int lr = lo + r;
        bool val = (lr >= 0 && lr < L);
        int g = (h*L + (val ? lr : 0))*HD + d;
        ks[r*65 + d] = val ? g_k[g] : 0.0f;
        vs[r*65 + d] = val ? g_v[g] : 0.0f;
    }
    for (int idx = tid; idx < TQ * HD; idx += 512) {
        qs[idx] = g_q[(h*L + l0)*HD + idx];
    }
    __syncthreads();

    int wq   = tid >> 5;
    int lane = tid & 31;
    int l = l0 + wq;

    float sc[4];
    #pragma unroll
    for (int w4 = 0; w4 < 4; w4++) {
        int r = wq + lane + w4*32;
        float s = 0.f;
        #pragma unroll
        for (int d = 0; d < HD; d++)
            s += ks[r*65 + d] * qs[wq*HD + d];
        sc[w4] = rv[r] ? s * SCALE : -1e30f;
    }

    float m = fmaxf(fmaxf(sc[0], sc[1]), fmaxf(sc[2], sc[3]));
    #pragma unroll
    for (int o = 16; o > 0; o >>= 1) m = fmaxf(m, __shfl_xor_sync(0xffffffffu, m, o));
    float e[4], sum = 0.f;
    #pragma unroll
    for (int w4 = 0; w4 < 4; w4++) { e[w4] = expf(sc[w4] - m); sum += e[w4]; }
    #pragma unroll
    for (int o = 16; o > 0; o >>= 1) sum += __shfl_xor_sync(0xffffffffu, sum, o);
    float inv = 1.0f / sum;
    #pragma unroll
    for (int w4 = 0; w4 < 4; w4++) ws[wq*WIN + lane + w4*32] = e[w4] * inv;
    __syncwarp();

    float a0 = 0.f, a1 = 0.f;
    #pragma unroll 4
    for (int w = 0; w < WIN; w++) {
        float wt = ws[wq*WIN + w];
        int r = wq + w;
        a0 += wt * vs[r*65 + lane];
        a1 += wt * vs[r*65 + lane + 32];
    }
    g_attn[(size_t)l*DM + h*HD + lane]      = a0;
    g_attn[(size_t)l*DM + h*HD + lane + 32] = a1;
}

// ---------------- CLS split-softmax pass 1 --------------------------------------
// grid = (NCHUNK, H), block = 128. Each block: 128 keys of head h.
__global__ void __launch_bounds__(128) cls_part_kernel(const int* __restrict__ mask) {
    extern __shared__ float smc[];
    float* ksm = smc;                  // 128 * 65
    float* vsm = ksm + CKEYS*65;       // 128 * 65
    float* q0  = vsm + CKEYS*65;       // 64
    float* ew  = q0 + HD;              // 128
    float* red = ew + CKEYS;           // 128

    int c = blockIdx.x, h = blockIdx.y;
    int tid = threadIdx.x;
    int base = c * CKEYS;

    if (tid < HD) q0[tid] = g_q[(size_t)(h*L)*HD + tid];
    for (int idx = tid; idx < CKEYS*HD; idx += 128) {
        int key = idx >> 6, d = idx & 63;
        size_t g = (size_t)(h*L + base + key)*HD + d;
        ksm[key*65 + d] = g_k[g];
        vsm[key*65 + d] = g_v[g];
    }
    __syncthreads();

    // score for key = tid
    float s = 0.f;
    #pragma unroll
    for (int d = 0; d < HD; d++) s += ksm[tid*65 + d] * q0[d];
    s = (mask[base + tid] != 0) ? s * SCALE : -1e30f;

    // block max
    red[tid] = s; __syncthreads();
    for (int o = 64; o > 0; o >>= 1) {
        if (tid < o) red[tid] = fmaxf(red[tid], red[tid + o]);
        __syncthreads();
    }
    float m_c = red[0];
    __syncthreads();

    float e = expf(s - m_c);
    ew[tid] = e;
    red[tid] = e; __syncthreads();
    for (int o = 64; o > 0; o >>= 1) {
        if (tid < o) red[tid] += red[tid + o];
        __syncthreads();
    }
    float s_c = red[0];
    __syncthreads();

    // partial output: thread (half, d)
    int d = tid & 63, half = tid >> 6;
    float acc = 0.f;
    #pragma unroll 8
    for (int kk = 0; kk < 64; kk++) {
        int key = half*64 + kk;
        acc += ew[key] * vsm[key*65 + d];
    }
    red[tid] = acc; __syncthreads();
    if (tid < HD) {
        g_cls_o[(size_t)(h*NCHUNK + c)*HD + tid] = red[tid] + red[HD + tid];
        if (tid == 0) { g_cls_m[h*NCHUNK + c] = m_c; g_cls_s[h*NCHUNK + c] = s_c; }
    }
}

// ---------------- CLS combine pass 2: 1 block, 768 threads ----------------------
__global__ void __launch_bounds__(768) cls_combine_kernel() {
    int tid = threadIdx.x;
    int h = tid >> 6, d = tid & 63;
    float m = -1e30f;
    #pragma unroll
    for (int c = 0; c < NCHUNK; c++) m = fmaxf(m, g_cls_m[h*NCHUNK + c]);
    float den = 0.f, num = 0.f;
    #pragma unroll
    for (int c = 0; c < NCHUNK; c++) {
        float w = expf(g_cls_m[h*NCHUNK + c] - m);
        den += g_cls_s[h*NCHUNK + c] * w;
        num += g_cls_o[(size_t)(h*NCHUNK + c)*HD + d] * w;
    }
    g_attn[h*HD + d] = num / den;
}

// ---------------- launch ---------------------------------------------------------
extern "C" void kernel_launch(void* const* d_in, const int* in_sizes, int n_in,
                              void* d_out, int out_size) {
    (void)in_sizes; (void)n_in; (void)out_size;
    const float* emb   = (const float*)d_in[0];
    const int*   mask  = (const int*)  d_in[1];
    const float* W_qkv = (const float*)d_in[2];
    const float* b_qkv = (const float*)d_in[3];
    const float* W_o   = (const float*)d_in[4];
    const float* b_o   = (const float*)d_in[5];
    float* out = (float*)d_out;

    float *p_qkv, *p_attn;
    cudaGetSymbolAddress((void**)&p_qkv,  g_qkv);
    cudaGetSymbolAddress((void**)&p_attn, g_attn);

    // 1. QKV GEMM: [2048,768] x [768,2304]
    sgemm_bias_db<128,128,16,8,8><<<dim3((3*DM)/128, L/128), 256>>>(
        emb, W_qkv, b_qkv, p_qkv, L, 3*DM, DM);

    // 2. RoPE + head split
    rope_split_kernel<<<L, 384>>>();

    // 3. sliding-window attention
    constexpr int SMEM_WIN = (NROWS*65*2 + TQ*HD + TQ*WIN) * 4 + NROWS * 4;
    cudaFuncSetAttribute(window_attn_kernel,
                         cudaFuncAttributeMaxDynamicSharedMemorySize, SMEM_WIN);
    window_attn_kernel<<<H * (L/TQ), 512, SMEM_WIN>>>(mask);

    // 4. CLS row: split-softmax over 16 chunks x 12 heads, then combine
    constexpr int SMEM_CLS = (CKEYS*65*2 + HD + CKEYS + 128) * 4;
    cudaFuncSetAttribute(cls_part_kernel,
                         cudaFuncAttributeMaxDynamicSharedMemorySize, SMEM_CLS);
    cls_part_kernel<<<dim3(NCHUNK, H), 128, SMEM_CLS>>>(mask);
    cls_combine_kernel<<<1, 768>>>();

    // 5. output projection: [2048,768] x [768,768]
    sgemm_bias_db<64,128,16,8,8><<<dim3(DM/128, L/64), 128>>>(
        p_attn, W_o, b_o, out, L, DM, DM);
}

// round 4
// speedup vs baseline: 1.2212x; 1.0288x over previous
#include <cuda_runtime.h>
#include <cuda_bf16.h>
#include <math.h>
#include <stdint.h>

#define L    2048
#define DM   768
#define H    12
#define HD   64
#define WIN  128
#define TQ   16
#define NROWS 144
#define NCHUNK 16
#define CKEYS  128

static constexpr float SCALE = 0.03608439182435161f;  // 1/sqrt(768)

// ====================== scratch ================================================
__device__ float g_qkv[L * 3 * DM];
__device__ float g_q[H * L * HD];
__device__ float g_k[H * L * HD];
__device__ float g_v[H * L * HD];
__device__ float g_attn[L * DM];
__device__ float g_cls_m[H * NCHUNK];
__device__ float g_cls_s[H * NCHUNK];
__device__ float g_cls_o[H * NCHUNK * HD];

__device__ __nv_bfloat16 g_Ahi[L * DM],  g_Alo[L * DM];          // emb split
__device__ __nv_bfloat16 g_Wqhi[3*DM*DM], g_Wqlo[3*DM*DM];       // W_qkv^T split [2304][768]
__device__ __nv_bfloat16 g_Wohi[DM*DM],  g_Wolo[DM*DM];          // W_o^T split   [768][768]
__device__ __nv_bfloat16 g_Chi[L * DM],  g_Clo[L * DM];          // attn-out split

// ====================== prep kernels ==========================================
__global__ void __launch_bounds__(256) split_bf16(const float* __restrict__ x,
        __nv_bfloat16* __restrict__ hi, __nv_bfloat16* __restrict__ lo, int n) {
    int i = blockIdx.x * 256 + threadIdx.x;
    if (i < n) {
        float v = x[i];
        __nv_bfloat16 h = __float2bfloat16(v);
        hi[i] = h;
        lo[i] = __float2bfloat16(v - __bfloat162float(h));
    }
}

// W [K,N] fp32 row-major  ->  Thi/Tlo [N,K] bf16 row-major
__global__ void __launch_bounds__(256) transpose_split(const float* __restrict__ W,
        __nv_bfloat16* __restrict__ Thi, __nv_bfloat16* __restrict__ Tlo, int K, int N) {
    __shared__ float t[32][33];
    int n0 = blockIdx.x * 32, k0 = blockIdx.y * 32;
    int tx = threadIdx.x, ty = threadIdx.y;
    #pragma unroll
    for (int i = ty; i < 32; i += 8)
        t[i][tx] = W[(size_t)(k0 + i) * N + n0 + tx];
    __syncthreads();
    #pragma unroll
    for (int i = ty; i < 32; i += 8) {
        float v = t[tx][i];
        __nv_bfloat16 h = __float2bfloat16(v);
        size_t o = (size_t)(n0 + i) * K + k0 + tx;
        Thi[o] = h;
        Tlo[o] = __float2bfloat16(v - __bfloat162float(h));
    }
}

// ====================== mma.sync helpers ======================================
__device__ __forceinline__ uint32_t smem_u32(const void* p) {
    uint32_t a;
    asm("{ .reg .u64 t; cvta.to.shared.u64 t, %1; cvt.u32.u64 %0, t; }" : "=r"(a) : "l"(p));
    return a;
}
__device__ __forceinline__ void ldsm_x4(uint32_t& r0, uint32_t& r1, uint32_t& r2, uint32_t& r3,
                                        uint32_t addr) {
    asm volatile("ldmatrix.sync.aligned.m8n8.x4.shared.b16 {%0,%1,%2,%3}, [%4];"
                 : "=r"(r0), "=r"(r1), "=r"(r2), "=r"(r3) : "r"(addr));
}
__device__ __forceinline__ void ldsm_x2(uint32_t& r0, uint32_t& r1, uint32_t addr) {
    asm volatile("ldmatrix.sync.aligned.m8n8.x2.shared.b16 {%0,%1}, [%2];"
                 : "=r"(r0), "=r"(r1) : "r"(addr));
}
__device__ __forceinline__ void mma_bf16(float* d, const uint32_t* a, const uint32_t* b) {
    asm volatile("mma.sync.aligned.m16n8k16.row.col.f32.bf16.bf16.f32 "
                 "{%0,%1,%2,%3}, {%4,%5,%6,%7}, {%8,%9}, {%0,%1,%2,%3};"
                 : "+f"(d[0]), "+f"(d[1]), "+f"(d[2]), "+f"(d[3])
                 : "r"(a[0]), "r"(a[1]), "r"(a[2]), "r"(a[3]), "r"(b[0]), "r"(b[1]));
}

// ====================== HMMA bf16 3-pass GEMM =================================
// C[M,N] = (Ahi+Alo)[M,K] @ (Bhi+Blo)[N,K]^T + bias   (drops lo*lo)
// grid = (N/128, M/128), 256 threads (8 warps = 2M x 4N), warp tile 64x32.
#define SMSTRIDE 40   // bf16 elems per smem row (32 data + 8 pad)

__global__ void __launch_bounds__(256)
gemm_bf16_mma(const __nv_bfloat16* __restrict__ Ahi, const __nv_bfloat16* __restrict__ Alo,
              const __nv_bfloat16* __restrict__ Bhi, const __nv_bfloat16* __restrict__ Blo,
              const float* __restrict__ bias, float* __restrict__ C,
              int N, int K) {
    __shared__ __align__(16) __nv_bfloat16 As[2][128][SMSTRIDE];
    __shared__ __align__(16) __nv_bfloat16 Bs[2][128][SMSTRIDE];

    const int tid  = threadIdx.x;
    const int wid  = tid >> 5;
    const int lane = tid & 31;
    const int bn = blockIdx.x, bm = blockIdx.y;
    const int wm = (wid >> 2) * 64;   // warp M offset (0 / 64)
    const int wn = (wid & 3) * 32;    // warp N offset (0/32/64/96)

    const __nv_bfloat16* Ap[3] = {Ahi, Ahi, Alo};
    const __nv_bfloat16* Bp[3] = {Bhi, Blo, Bhi};

    const int KT = K >> 5;            // k-tiles per pass (24 for K=768)
    const int NST = 3 * KT;

    float acc[4][4][4] = {};          // [mi][nj][frag]

    auto load_stage = [&](int s, int buf) {
        int p  = s / KT;
        int kt = s - p * KT;
        const __nv_bfloat16* Ag = Ap[p] + (size_t)bm * 128 * K + kt * 32;
        const __nv_bfloat16* Bg = Bp[p] + (size_t)bn * 128 * K + kt * 32;
        #pragma unroll
        for (int i = 0; i < 2; i++) {
            int ch = tid + i * 256;       // 512 chunks of 16B per matrix
            int r = ch >> 2, c = (ch & 3) * 8;
            *(uint4*)&As[buf][r][c] = *(const uint4*)(Ag + (size_t)r * K + c);
            *(uint4*)&Bs[buf][r][c] = *(const uint4*)(Bg + (size_t)r * K + c);
        }
    };

    load_stage(0, 0);
    __syncthreads();

    for (int s = 0; s < NST; s++) {
        const int buf = s & 1;
        if (s + 1 < NST) load_stage(s + 1, buf ^ 1);

        const uint32_t a_base = smem_u32(&As[buf][0][0]);
        const uint32_t b_base = smem_u32(&Bs[buf][0][0]);

        #pragma unroll
        for (int ks = 0; ks < 2; ks++) {
            uint32_t af[4][4], bf[4][2];
            // A fragments: 4 m16 tiles
            #pragma unroll
            for (int mi = 0; mi < 4; mi++) {
                int row = wm + mi * 16 + (lane & 7) + ((lane & 8) ? 8 : 0);
                int col = ks * 16 + ((lane & 16) ? 8 : 0);
                ldsm_x4(af[mi][0], af[mi][1], af[mi][2], af[mi][3],
                        a_base + (uint32_t)(row * SMSTRIDE + col) * 2);
            }
            // B fragments: 4 n8 tiles
            #pragma unroll
            for (int nj = 0; nj < 4; nj++) {
                int row = wn + nj * 8 + (lane & 7);
                int col = ks * 16 + ((lane & 8) ? 8 : 0);
                ldsm_x2(bf[nj][0], bf[nj][1],
                        b_base + (uint32_t)(row * SMSTRIDE + col) * 2);
            }
            #pragma unroll
            for (int mi = 0; mi < 4; mi++)
                #pragma unroll
                for (int nj = 0; nj < 4; nj++)
                    mma_bf16(acc[mi][nj], af[mi], bf[nj]);
        }
        __syncthreads();
    }

    // ---- epilogue: registers -> gmem with bias ----
    #pragma unroll
    for (int nj = 0; nj < 4; nj++) {
        int gcol = bn * 128 + wn + nj * 8 + (lane & 3) * 2;
        float2 bv = *(const float2*)(bias + gcol);
        #pragma unroll
        for (int mi = 0; mi < 4; mi++) {
            int grow = bm * 128 + wm + mi * 16 + (lane >> 2);
            float2 v0 = { acc[mi][nj][0] + bv.x, acc[mi][nj][1] + bv.y };
            float2 v1 = { acc[mi][nj][2] + bv.x, acc[mi][nj][3] + bv.y };
            *(float2*)(C + (size_t)grow * N + gcol)       = v0;
            *(float2*)(C + (size_t)(grow + 8) * N + gcol) = v1;
        }
    }
}

// ====================== RoPE + head split =====================================
__global__ void __launch_bounds__(384) rope_split_kernel() {
    int l = blockIdx.x;
    int t = threadIdx.x;
    int h = t >> 5;
    int i = t & 31;

    const float* row = g_qkv + (size_t)l * (3*DM);
    float invf = powf(10000.0f, -(float)i * (1.0f/32.0f));
    float ang = (float)l * invf;
    float s, c;
    sincosf(ang, &s, &c);

    int qo = h*HD + i;
    float q1 = row[qo],        q2 = row[qo + 32];
    float k1 = row[DM + qo],   k2 = row[DM + qo + 32];
    int o = (h*L + l)*HD + i;
    g_q[o]      = q1*c - q2*s;
    g_q[o + 32] = q1*s + q2*c;
    g_k[o]      = k1*c - k2*s;
    g_k[o + 32] = k1*s + k2*c;
    g_v[o]      = row[2*DM + qo];
    g_v[o + 32] = row[2*DM + qo + 32];
}

// ====================== sliding-window attention ==============================
__global__ void __launch_bounds__(512) window_attn_kernel(const int* __restrict__ mask) {
    extern __shared__ float sm[];
    float* ks = sm;
    float* vs = ks + NROWS * 65;
    float* qs = vs + NROWS * 65;
    float* ws = qs + TQ * HD;
    int*   rv = (int*)(ws + TQ * WIN);

    int h  = blockIdx.x / (L / TQ);
    int qt = blockIdx.x % (L / TQ);
    int l0 = qt * TQ;
    int lo = l0 - 64;
    int tid = threadIdx.x;

    for (int idx = tid; idx < NROWS; idx += 512) {
        int lr = lo + idx;
        rv[idx] = (lr >= 0 && lr < L) ? (mask[lr] != 0) : 0;
    }
    for (int idx = tid; idx < NROWS * HD; idx += 512) {
        int r = idx >> 6, d = idx & 63;
        int lr = lo + r;
        bool val = (lr >= 0 && lr < L);
        int g = (h*L + (val ? lr : 0))*HD + d;
        ks[r*65 + d] = val ? g_k[g] : 0.0f;
        vs[r*65 + d] = val ? g_v[g] : 0.0f;
    }
    for (int idx = tid; idx < TQ * HD; idx += 512) {
        qs[idx] = g_q[(h*L + l0)*HD + idx];
    }
    __syncthreads();

    int wq   = tid >> 5;
    int lane = tid & 31;
    int l = l0 + wq;

    float sc[4];
    #pragma unroll
    for (int w4 = 0; w4 < 4; w4++) {
        int r = wq + lane + w4*32;
        float s = 0.f;
        #pragma unroll
        for (int d = 0; d < HD; d++)
            s += ks[r*65 + d] * qs[wq*HD + d];
        sc[w4] = rv[r] ? s * SCALE : -1e30f;
    }

    float m = fmaxf(fmaxf(sc[0], sc[1]), fmaxf(sc[2], sc[3]));
    #pragma unroll
    for (int o = 16; o > 0; o >>= 1) m = fmaxf(m, __shfl_xor_sync(0xffffffffu, m, o));
    float e[4], sum = 0.f;
    #pragma unroll
    for (int w4 = 0; w4 < 4; w4++) { e[w4] = expf(sc[w4] - m); sum += e[w4]; }
    #pragma unroll
    for (int o = 16; o > 0; o >>= 1) sum += __shfl_xor_sync(0xffffffffu, sum, o);
    float inv = 1.0f / sum;
    #pragma unroll
    for (int w4 = 0; w4 < 4; w4++) ws[wq*WIN + lane + w4*32] = e[w4] * inv;
    __syncwarp();

    float a0 = 0.f, a1 = 0.f;
    #pragma unroll 4
    for (int w = 0; w < WIN; w++) {
        float wt = ws[wq*WIN + w];
        int r = wq + w;
        a0 += wt * vs[r*65 + lane];
        a1 += wt * vs[r*65 + lane + 32];
    }
    g_attn[(size_t)l*DM + h*HD + lane]      = a0;
    g_attn[(size_t)l*DM + h*HD + lane + 32] = a1;
}

// ====================== CLS split-softmax ======================================
__global__ void __launch_bounds__(128) cls_part_kernel(const int* __restrict__ mask) {
    extern __shared__ float smc[];
    float* ksm = smc;
    float* vsm = ksm + CKEYS*65;
    float* q0  = vsm + CKEYS*65;
    float* ew  = q0 + HD;
    float* red = ew + CKEYS;

    int c = blockIdx.x, h = blockIdx.y;
    int tid = threadIdx.x;
    int base = c * CKEYS;

    if (tid < HD) q0[tid] = g_q[(size_t)(h*L)*HD + tid];
    for (int idx = tid; idx < CKEYS*HD; idx += 128) {
        int key = idx >> 6, d = idx & 63;
        size_t g = (size_t)(h*L + base + key)*HD + d;
        ksm[key*65 + d] = g_k[g];
        vsm[key*65 + d] = g_v[g];
    }
    __syncthreads();

    float s = 0.f;
    #pragma unroll
    for (int d = 0; d < HD; d++) s += ksm[tid*65 + d] * q0[d];
    s = (mask[base + tid] != 0) ? s * SCALE : -1e30f;

    red[tid] = s; __syncthreads();
    for (int o = 64; o > 0; o >>= 1) {
        if (tid < o) red[tid] = fmaxf(red[tid], red[tid + o]);
        __syncthreads();
    }
    float m_c = red[0];
    __syncthreads();

    float e = expf(s - m_c);
    ew[tid] = e;
    red[tid] = e; __syncthreads();
    for (int o = 64; o > 0; o >>= 1) {
        if (tid < o) red[tid] += red[tid + o];
        __syncthreads();
    }
    float s_c = red[0];
    __syncthreads();

    int d = tid & 63, half = tid >> 6;
    float acc = 0.f;
    #pragma unroll 8
    for (int kk = 0; kk < 64; kk++) {
        int key = half*64 + kk;
        acc += ew[key] * vsm[key*65 + d];
    }
    red[tid] = acc; __syncthreads();
    if (tid < HD) {
        g_cls_o[(size_t)(h*NCHUNK + c)*HD + tid] = red[tid] + red[HD + tid];
        if (tid == 0) { g_cls_m[h*NCHUNK + c] = m_c; g_cls_s[h*NCHUNK + c] = s_c; }
    }
}

__global__ void __launch_bounds__(768) cls_combine_kernel() {
    int tid = threadIdx.x;
    int h = tid >> 6, d = tid & 63;
    float m = -1e30f;
    #pragma unroll
    for (int c = 0; c < NCHUNK; c++) m = fmaxf(m, g_cls_m[h*NCHUNK + c]);
    float den = 0.f, num = 0.f;
    #pragma unroll
    for (int c = 0; c < NCHUNK; c++) {
        float w = expf(g_cls_m[h*NCHUNK + c] - m);
        den += g_cls_s[h*NCHUNK + c] * w;
        num += g_cls_o[(size_t)(h*NCHUNK + c)*HD + d] * w;
    }
    g_attn[h*HD + d] = num / den;
}

// ====================== launch =================================================
extern "C" void kernel_launch(void* const* d_in, const int* in_sizes, int n_in,
                              void* d_out, int out_size) {
    (void)in_sizes; (void)n_in; (void)out_size;
    const float* emb   = (const float*)d_in[0];
    const int*   mask  = (const int*)  d_in[1];
    const float* W_qkv = (const float*)d_in[2];
    const float* b_qkv = (const float*)d_in[3];
    const float* W_o   = (const float*)d_in[4];
    const float* b_o   = (const float*)d_in[5];
    float* out = (float*)d_out;

    float *p_qkv, *p_attn;
    cudaGetSymbolAddress((void**)&p_qkv,  g_qkv);
    cudaGetSymbolAddress((void**)&p_attn, g_attn);
    __nv_bfloat16 *p_Ahi, *p_Alo, *p_Wqhi, *p_Wqlo, *p_Wohi, *p_Wolo, *p_Chi, *p_Clo;
    cudaGetSymbolAddress((void**)&p_Ahi,  g_Ahi);
    cudaGetSymbolAddress((void**)&p_Alo,  g_Alo);
    cudaGetSymbolAddress((void**)&p_Wqhi, g_Wqhi);
    cudaGetSymbolAddress((void**)&p_Wqlo, g_Wqlo);
    cudaGetSymbolAddress((void**)&p_Wohi, g_Wohi);
    cudaGetSymbolAddress((void**)&p_Wolo, g_Wolo);
    cudaGetSymbolAddress((void**)&p_Chi,  g_Chi);
    cudaGetSymbolAddress((void**)&p_Clo,  g_Clo);

    // 0. operand prep
    split_bf16<<<(L*DM + 255)/256, 256>>>(emb, p_Ahi, p_Alo, L*DM);
    transpose_split<<<dim3((3*DM)/32, DM/32), dim3(32,8)>>>(W_qkv, p_Wqhi, p_Wqlo, DM, 3*DM);
    transpose_split<<<dim3(DM/32, DM/32), dim3(32,8)>>>(W_o, p_Wohi, p_Wolo, DM, DM);

    // 1. QKV GEMM (HMMA): [2048,768] x [768,2304]
    gemm_bf16_mma<<<dim3((3*DM)/128, L/128), 256>>>(
        p_Ahi, p_Alo, p_Wqhi, p_Wqlo, b_qkv, p_qkv, 3*DM, DM);

    // 2. RoPE + head split
    rope_split_kernel<<<L, 384>>>();

    // 3. sliding-window attention
    constexpr int SMEM_WIN = (NROWS*65*2 + TQ*HD + TQ*WIN) * 4 + NROWS * 4;
    cudaFuncSetAttribute(window_attn_kernel,
                         cudaFuncAttributeMaxDynamicSharedMemorySize, SMEM_WIN);
    window_attn_kernel<<<H * (L/TQ), 512, SMEM_WIN>>>(mask);

    // 4. CLS row
    constexpr int SMEM_CLS = (CKEYS*65*2 + HD + CKEYS + 128) * 4;
    cudaFuncSetAttribute(cls_part_kernel,
                         cudaFuncAttributeMaxDynamicSharedMemorySize, SMEM_CLS);
    cls_part_kernel<<<dim3(NCHUNK, H), 128, SMEM_CLS>>>(mask);
    cls_combine_kernel<<<1, 768>>>();

    // 5. output projection (HMMA): [2048,768] x [768,768]
    split_bf16<<<(L*DM + 255)/256, 256>>>(p_attn, p_Chi, p_Clo, L*DM);
    gemm_bf16_mma<<<dim3(DM/128, L/128), 256>>>(
        p_Chi, p_Clo, p_Wohi, p_Wolo, b_o, out, DM, DM);
}

// round 5
// speedup vs baseline: 1.7668x; 1.4468x over previous
#include <cuda_runtime.h>
#include <cuda_bf16.h>
#include <math.h>
#include <stdint.h>

#define L    2048
#define DM   768
#define H    12
#define HD   64
#define WIN  128
#define TQ   16
#define NROWS 144
#define NCHUNK 16
#define CKEYS  128

static constexpr float SCALE = 0.03608439182435161f;  // 1/sqrt(768)

// ====================== scratch ================================================
__device__ float g_qkv[L * 3 * DM];
__device__ float g_q[H * L * HD];
__device__ float g_k[H * L * HD];
__device__ float g_v[H * L * HD];
__device__ float g_attn[L * DM];
__device__ float g_cls_m[H * NCHUNK];
__device__ float g_cls_s[H * NCHUNK];
__device__ float g_cls_o[H * NCHUNK * HD];

__device__ __nv_bfloat16 g_Ahi[L * DM],  g_Alo[L * DM];          // emb split
__device__ __nv_bfloat16 g_Wqhi[3*DM*DM], g_Wqlo[3*DM*DM];       // W_qkv^T split [2304][768]
__device__ __nv_bfloat16 g_Wohi[DM*DM],  g_Wolo[DM*DM];          // W_o^T split   [768][768]
__device__ __nv_bfloat16 g_Chi[L * DM],  g_Clo[L * DM];          // attn-out split

// ====================== prep kernels ==========================================
__global__ void __launch_bounds__(256) split_bf16(const float* __restrict__ x,
        __nv_bfloat16* __restrict__ hi, __nv_bfloat16* __restrict__ lo, int n) {
    int i = blockIdx.x * 256 + threadIdx.x;
    if (i < n) {
        float v = x[i];
        __nv_bfloat16 h = __float2bfloat16(v);
        hi[i] = h;
        lo[i] = __float2bfloat16(v - __bfloat162float(h));
    }
}

// W [K,N] fp32 row-major  ->  Thi/Tlo [N,K] bf16 row-major
__global__ void __launch_bounds__(256) transpose_split(const float* __restrict__ W,
        __nv_bfloat16* __restrict__ Thi, __nv_bfloat16* __restrict__ Tlo, int K, int N) {
    __shared__ float t[32][33];
    int n0 = blockIdx.x * 32, k0 = blockIdx.y * 32;
    int tx = threadIdx.x, ty = threadIdx.y;
    #pragma unroll
    for (int i = ty; i < 32; i += 8)
        t[i][tx] = W[(size_t)(k0 + i) * N + n0 + tx];
    __syncthreads();
    #pragma unroll
    for (int i = ty; i < 32; i += 8) {
        float v = t[tx][i];
        __nv_bfloat16 h = __float2bfloat16(v);
        size_t o = (size_t)(n0 + i) * K + k0 + tx;
        Thi[o] = h;
        Tlo[o] = __float2bfloat16(v - __bfloat162float(h));
    }
}

// ====================== mma.sync helpers ======================================
__device__ __forceinline__ uint32_t smem_u32(const void* p) {
    uint32_t a;
    asm("{ .reg .u64 t; cvta.to.shared.u64 t, %1; cvt.u32.u64 %0, t; }" : "=r"(a) : "l"(p));
    return a;
}
__device__ __forceinline__ void ldsm_x4(uint32_t& r0, uint32_t& r1, uint32_t& r2, uint32_t& r3,
                                        uint32_t addr) {
    asm volatile("ldmatrix.sync.aligned.m8n8.x4.shared.b16 {%0,%1,%2,%3}, [%4];"
                 : "=r"(r0), "=r"(r1), "=r"(r2), "=r"(r3) : "r"(addr));
}
__device__ __forceinline__ void ldsm_x2(uint32_t& r0, uint32_t& r1, uint32_t addr) {
    asm volatile("ldmatrix.sync.aligned.m8n8.x2.shared.b16 {%0,%1}, [%2];"
                 : "=r"(r0), "=r"(r1) : "r"(addr));
}
__device__ __forceinline__ void mma_bf16(float* d, const uint32_t* a, const uint32_t* b) {
    asm volatile("mma.sync.aligned.m16n8k16.row.col.f32.bf16.bf16.f32 "
                 "{%0,%1,%2,%3}, {%4,%5,%6,%7}, {%8,%9}, {%0,%1,%2,%3};"
                 : "+f"(d[0]), "+f"(d[1]), "+f"(d[2]), "+f"(d[3])
                 : "r"(a[0]), "r"(a[1]), "r"(a[2]), "r"(a[3]), "r"(b[0]), "r"(b[1]));
}
#define CP_ASYNC_16(dst, src) \
    asm volatile("cp.async.cg.shared.global [%0], [%1], 16;" :: "r"(dst), "l"(src))
#define CP_COMMIT() asm volatile("cp.async.commit_group;" ::: "memory")
#define CP_WAIT2()  asm volatile("cp.async.wait_group 2;" ::: "memory")

// ====================== HMMA bf16 3-pass GEMM (cp.async pipelined) ============
// C[M,N] = (Ahi+Alo)[M,K] @ (Bhi+Blo)[N,K]^T + bias   (drops lo*lo)
// grid = (N/128, M/128), 256 threads (8 warps = 2M x 4N), warp tile 64x32.
// 4-stage cp.async pipeline, dynamic smem = 4*2*128*40*2 = 81920 B.
#define SMSTRIDE 40   // bf16 elems per smem row (32 data + 8 pad)
#define STAGE_ELEMS (128 * SMSTRIDE)
#define NSTAGES 4

__global__ void __launch_bounds__(256, 2)
gemm_bf16_mma(const __nv_bfloat16* __restrict__ Ahi, const __nv_bfloat16* __restrict__ Alo,
              const __nv_bfloat16* __restrict__ Bhi, const __nv_bfloat16* __restrict__ Blo,
              const float* __restrict__ bias, float* __restrict__ C,
              int N, int K) {
    extern __shared__ __align__(16) __nv_bfloat16 dsm[];
    __nv_bfloat16* As = dsm;                          // [NSTAGES][128][SMSTRIDE]
    __nv_bfloat16* Bs = dsm + NSTAGES * STAGE_ELEMS;  // [NSTAGES][128][SMSTRIDE]

    const int tid  = threadIdx.x;
    const int wid  = tid >> 5;
    const int lane = tid & 31;
    const int bn = blockIdx.x, bm = blockIdx.y;
    const int wm = (wid >> 2) * 64;   // warp M offset (0 / 64)
    const int wn = (wid & 3) * 32;    // warp N offset (0/32/64/96)

    const __nv_bfloat16* Ap[3] = {Ahi, Ahi, Alo};
    const __nv_bfloat16* Bp[3] = {Bhi, Blo, Bhi};

    const int KT  = K >> 5;           // k-tiles per pass (24 for K=768)
    const int NST = 3 * KT;

    float acc[4][4][4] = {};          // [mi][nj][frag]

    // per-thread load mapping: 2 chunks of 16B per matrix per stage
    const int r0c = tid >> 2,         c0c = (tid & 3) * 8;
    const int r1c = (tid + 256) >> 2, c1c = ((tid + 256) & 3) * 8;

    auto load_stage = [&](int s, int buf) {
        int p  = s / KT;
        int kt = s - p * KT;
        const __nv_bfloat16* Ag = Ap[p] + (size_t)bm * 128 * K + kt * 32;
        const __nv_bfloat16* Bg = Bp[p] + (size_t)bn * 128 * K + kt * 32;
        uint32_t a_s = smem_u32(As + buf * STAGE_ELEMS);
        uint32_t b_s = smem_u32(Bs + buf * STAGE_ELEMS);
        CP_ASYNC_16(a_s + (uint32_t)(r0c * SMSTRIDE + c0c) * 2, Ag + (size_t)r0c * K + c0c);
        CP_ASYNC_16(a_s + (uint32_t)(r1c * SMSTRIDE + c1c) * 2, Ag + (size_t)r1c * K + c1c);
        CP_ASYNC_16(b_s + (uint32_t)(r0c * SMSTRIDE + c0c) * 2, Bg + (size_t)r0c * K + c0c);
        CP_ASYNC_16(b_s + (uint32_t)(r1c * SMSTRIDE + c1c) * 2, Bg + (size_t)r1c * K + c1c);
    };

    // prologue: 3 stages in flight
    #pragma unroll
    for (int s = 0; s < 3; s++) { load_stage(s, s); CP_COMMIT(); }

    for (int s = 0; s < NST; s++) {
        const int buf = s & (NSTAGES - 1);
        CP_WAIT2();              // stage s resident (always exactly 3 groups pending)
        __syncthreads();

        const uint32_t a_base = smem_u32(As + buf * STAGE_ELEMS);
        const uint32_t b_base = smem_u32(Bs + buf * STAGE_ELEMS);

        #pragma unroll
        for (int ks = 0; ks < 2; ks++) {
            uint32_t af[4][4], bf[4][2];
            #pragma unroll
            for (int mi = 0; mi < 4; mi++) {
                int row = wm + mi * 16 + (lane & 7) + ((lane & 8) ? 8 : 0);
                int col = ks * 16 + ((lane & 16) ? 8 : 0);
                ldsm_x4(af[mi][0], af[mi][1], af[mi][2], af[mi][3],
                        a_base + (uint32_t)(row * SMSTRIDE + col) * 2);
            }
            #pragma unroll
            for (int nj = 0; nj < 4; nj++) {
                int row = wn + nj * 8 + (lane & 7);
                int col = ks * 16 + ((lane & 8) ? 8 : 0);
                ldsm_x2(bf[nj][0], bf[nj][1],
                        b_base + (uint32_t)(row * SMSTRIDE + col) * 2);
            }
            #pragma unroll
            for (int mi = 0; mi < 4; mi++)
                #pragma unroll
                for (int nj = 0; nj < 4; nj++)
                    mma_bf16(acc[mi][nj], af[mi], bf[nj]);
        }

        // issue stage s+3 into buffer (s-1)%4 — all threads already passed its compute
        if (s + 3 < NST) load_stage(s + 3, (s + 3) & (NSTAGES - 1));
        CP_COMMIT();             // unconditional: keeps pending-group count uniform
    }

    // ---- epilogue: registers -> gmem with bias ----
    #pragma unroll
    for (int nj = 0; nj < 4; nj++) {
        int gcol = bn * 128 + wn + nj * 8 + (lane & 3) * 2;
        float2 bv = *(const float2*)(bias + gcol);
        #pragma unroll
        for (int mi = 0; mi < 4; mi++) {
            int grow = bm * 128 + wm + mi * 16 + (lane >> 2);
            float2 v0 = { acc[mi][nj][0] + bv.x, acc[mi][nj][1] + bv.y };
            float2 v1 = { acc[mi][nj][2] + bv.x, acc[mi][nj][3] + bv.y };
            *(float2*)(C + (size_t)grow * N + gcol)       = v0;
            *(float2*)(C + (size_t)(grow + 8) * N + gcol) = v1;
        }
    }
}

// ====================== RoPE + head split =====================================
__global__ void __launch_bounds__(384) rope_split_kernel() {
    int l = blockIdx.x;
    int t = threadIdx.x;
    int h = t >> 5;
    int i = t & 31;

    const float* row = g_qkv + (size_t)l * (3*DM);
    float invf = powf(10000.0f, -(float)i * (1.0f/32.0f));
    float ang = (float)l * invf;
    float s, c;
    sincosf(ang, &s, &c);

    int qo = h*HD + i;
    float q1 = row[qo],        q2 = row[qo + 32];
    float k1 = row[DM + qo],   k2 = row[DM + qo + 32];
    int o = (h*L + l)*HD + i;
    g_q[o]      = q1*c - q2*s;
    g_q[o + 32] = q1*s + q2*c;
    g_k[o]      = k1*c - k2*s;
    g_k[o + 32] = k1*s + k2*c;
    g_v[o]      = row[2*DM + qo];
    g_v[o + 32] = row[2*DM + qo + 32];
}

// ====================== sliding-window attention ==============================
__global__ void __launch_bounds__(512) window_attn_kernel(const int* __restrict__ mask) {
    extern __shared__ float sm[];
    float* ks = sm;
    float* vs = ks + NROWS * 65;
    float* qs = vs + NROWS * 65;
    float* ws = qs + TQ * HD;
    int*   rv = (int*)(ws + TQ * WIN);

    int h  = blockIdx.x / (L / TQ);
    int qt = blockIdx.x % (L / TQ);
    int l0 = qt * TQ;
    int lo = l0 - 64;
    int tid = threadIdx.x;

    for (int idx = tid; idx < NROWS; idx += 512) {
        int lr = lo + idx;
        rv[idx] = (lr >= 0 && lr < L) ? (mask[lr] != 0) : 0;
    }
    for (int idx = tid; idx < NROWS * HD; idx += 512) {
        int r = idx >> 6, d = idx & 63;
        int lr = lo + r;
        bool val = (lr >= 0 && lr < L);
        int g = (h*L + (val ? lr : 0))*HD + d;
        ks[r*65 + d] = val ? g_k[g] : 0.0f;
        vs[r*65 + d] = val ? g_v[g] : 0.0f;
    }
    for (int idx = tid; idx < TQ * HD; idx += 512) {
        qs[idx] = g_q[(h*L + l0)*HD + idx];
    }
    __syncthreads();

    int wq   = tid >> 5;
    int lane = tid & 31;
    int l = l0 + wq;

    float sc[4];
    #pragma unroll
    for (int w4 = 0; w4 < 4; w4++) {
        int r = wq + lane + w4*32;
        float s = 0.f;
        #pragma unroll
        for (int d = 0; d < HD; d++)
            s += ks[r*65 + d] * qs[wq*HD + d];
        sc[w4] = rv[r] ? s * SCALE : -1e30f;
    }

    float m = fmaxf(fmaxf(sc[0], sc[1]), fmaxf(sc[2], sc[3]));
    #pragma unroll
    for (int o = 16; o > 0; o >>= 1) m = fmaxf(m, __shfl_xor_sync(0xffffffffu, m, o));
    float e[4], sum = 0.f;
    #pragma unroll
    for (int w4 = 0; w4 < 4; w4++) { e[w4] = expf(sc[w4] - m); sum += e[w4]; }
    #pragma unroll
    for (int o = 16; o > 0; o >>= 1) sum += __shfl_xor_sync(0xffffffffu, sum, o);
    float inv = 1.0f / sum;
    #pragma unroll
    for (int w4 = 0; w4 < 4; w4++) ws[wq*WIN + lane + w4*32] = e[w4] * inv;
    __syncwarp();

    float a0 = 0.f, a1 = 0.f;
    #pragma unroll 4
    for (int w = 0; w < WIN; w++) {
        float wt = ws[wq*WIN + w];
        int r = wq + w;
        a0 += wt * vs[r*65 + lane];
        a1 += wt * vs[r*65 + lane + 32];
    }
    g_attn[(size_t)l*DM + h*HD + lane]      = a0;
    g_attn[(size_t)l*DM + h*HD + lane + 32] = a1;
}

// ====================== CLS split-softmax ======================================
__global__ void __launch_bounds__(128) cls_part_kernel(const int* __restrict__ mask) {
    extern __shared__ float smc[];
    float* ksm = smc;
    float* vsm = ksm + CKEYS*65;
    float* q0  = vsm + CKEYS*65;
    float* ew  = q0 + HD;
    float* red = ew + CKEYS;

    int c = blockIdx.x, h = blockIdx.y;
    int tid = threadIdx.x;
    int base = c * CKEYS;

    if (tid < HD) q0[tid] = g_q[(size_t)(h*L)*HD + tid];
    for (int idx = tid; idx < CKEYS*HD; idx += 128) {
        int key = idx >> 6, d = idx & 63;
        size_t g = (size_t)(h*L + base + key)*HD + d;
        ksm[key*65 + d] = g_k[g];
        vsm[key*65 + d] = g_v[g];
    }
    __syncthreads();

    float s = 0.f;
    #pragma unroll
    for (int d = 0; d < HD; d++) s += ksm[tid*65 + d] * q0[d];
    s = (mask[base + tid] != 0) ? s * SCALE : -1e30f;

    red[tid] = s; __syncthreads();
    for (int o = 64; o > 0; o >>= 1) {
        if (tid < o) red[tid] = fmaxf(red[tid], red[tid + o]);
        __syncthreads();
    }
    float m_c = red[0];
    __syncthreads();

    float e = expf(s - m_c);
    ew[tid] = e;
    red[tid] = e; __syncthreads();
    for (int o = 64; o > 0; o >>= 1) {
        if (tid < o) red[tid] += red[tid + o];
        __syncthreads();
    }
    float s_c = red[0];
    __syncthreads();

    int d = tid & 63, half = tid >> 6;
    float acc = 0.f;
    #pragma unroll 8
    for (int kk = 0; kk < 64; kk++) {
        int key = half*64 + kk;
        acc += ew[key] * vsm[key*65 + d];
    }
    red[tid] = acc; __syncthreads();
    if (tid < HD) {
        g_cls_o[(size_t)(h*NCHUNK + c)*HD + tid] = red[tid] + red[HD + tid];
        if (tid == 0) { g_cls_m[h*NCHUNK + c] = m_c; g_cls_s[h*NCHUNK + c] = s_c; }
    }
}

__global__ void __launch_bounds__(768) cls_combine_kernel() {
    int tid = threadIdx.x;
    int h = tid >> 6, d = tid & 63;
    float m = -1e30f;
    #pragma unroll
    for (int c = 0; c < NCHUNK; c++) m = fmaxf(m, g_cls_m[h*NCHUNK + c]);
    float den = 0.f, num = 0.f;
    #pragma unroll
    for (int c = 0; c < NCHUNK; c++) {
        float w = expf(g_cls_m[h*NCHUNK + c] - m);
        den += g_cls_s[h*NCHUNK + c] * w;
        num += g_cls_o[(size_t)(h*NCHUNK + c)*HD + d] * w;
    }
    g_attn[h*HD + d] = num / den;
}

// ====================== launch =================================================
extern "C" void kernel_launch(void* const* d_in, const int* in_sizes, int n_in,
                              void* d_out, int out_size) {
    (void)in_sizes; (void)n_in; (void)out_size;
    const float* emb   = (const float*)d_in[0];
    const int*   mask  = (const int*)  d_in[1];
    const float* W_qkv = (const float*)d_in[2];
    const float* b_qkv = (const float*)d_in[3];
    const float* W_o   = (const float*)d_in[4];
    const float* b_o   = (const float*)d_in[5];
    float* out = (float*)d_out;

    float *p_qkv, *p_attn;
    cudaGetSymbolAddress((void**)&p_qkv,  g_qkv);
    cudaGetSymbolAddress((void**)&p_attn, g_attn);
    __nv_bfloat16 *p_Ahi, *p_Alo, *p_Wqhi, *p_Wqlo, *p_Wohi, *p_Wolo, *p_Chi, *p_Clo;
    cudaGetSymbolAddress((void**)&p_Ahi,  g_Ahi);
    cudaGetSymbolAddress((void**)&p_Alo,  g_Alo);
    cudaGetSymbolAddress((void**)&p_Wqhi, g_Wqhi);
    cudaGetSymbolAddress((void**)&p_Wqlo, g_Wqlo);
    cudaGetSymbolAddress((void**)&p_Wohi, g_Wohi);
    cudaGetSymbolAddress((void**)&p_Wolo, g_Wolo);
    cudaGetSymbolAddress((void**)&p_Chi,  g_Chi);
    cudaGetSymbolAddress((void**)&p_Clo,  g_Clo);

    constexpr int GSMEM = NSTAGES * 2 * STAGE_ELEMS * 2;  // 81920 B
    cudaFuncSetAttribute(gemm_bf16_mma, cudaFuncAttributeMaxDynamicSharedMemorySize, GSMEM);

    // 0. operand prep
    split_bf16<<<(L*DM + 255)/256, 256>>>(emb, p_Ahi, p_Alo, L*DM);
    transpose_split<<<dim3((3*DM)/32, DM/32), dim3(32,8)>>>(W_qkv, p_Wqhi, p_Wqlo, DM, 3*DM);
    transpose_split<<<dim3(DM/32, DM/32), dim3(32,8)>>>(W_o, p_Wohi, p_Wolo, DM, DM);

    // 1. QKV GEMM (HMMA + cp.async): [2048,768] x [768,2304]
    gemm_bf16_mma<<<dim3((3*DM)/128, L/128), 256, GSMEM>>>(
        p_Ahi, p_Alo, p_Wqhi, p_Wqlo, b_qkv, p_qkv, 3*DM, DM);

    // 2. RoPE + head split
    rope_split_kernel<<<L, 384>>>();

    // 3. sliding-window attention
    constexpr int SMEM_WIN = (NROWS*65*2 + TQ*HD + TQ*WIN) * 4 + NROWS * 4;
    cudaFuncSetAttribute(window_attn_kernel,
                         cudaFuncAttributeMaxDynamicSharedMemorySize, SMEM_WIN);
    window_attn_kernel<<<H * (L/TQ), 512, SMEM_WIN>>>(mask);

    // 4. CLS row
    constexpr int SMEM_CLS = (CKEYS*65*2 + HD + CKEYS + 128) * 4;
    cudaFuncSetAttribute(cls_part_kernel,
                         cudaFuncAttributeMaxDynamicSharedMemorySize, SMEM_CLS);
    cls_part_kernel<<<dim3(NCHUNK, H), 128, SMEM_CLS>>>(mask);
    cls_combine_kernel<<<1, 768>>>();

    // 5. output projection (HMMA + cp.async): [2048,768] x [768,768]
    split_bf16<<<(L*DM + 255)/256, 256>>>(p_attn, p_Chi, p_Clo, L*DM);
    gemm_bf16_mma<<<dim3(DM/128, L/128), 256, GSMEM>>>(
        p_Chi, p_Clo, p_Wohi, p_Wolo, b_o, out, DM, DM);
}

// round 6
// speedup vs baseline: 1.8020x; 1.0199x over previous
#include <cuda_runtime.h>
#include <cuda_bf16.h>
#include <math.h>
#include <stdint.h>

#define L    2048
#define DM   768
#define H    12
#define HD   64
#define WIN  128
#define TQ   16
#define NROWS 144
#define NCHUNK 16
#define CKEYS  128
#define WSTRIDE 68   // floats per K row in window smem (64 data + 4 pad)

static constexpr float SCALE = 0.03608439182435161f;  // 1/sqrt(768)

// ====================== scratch ================================================
__device__ float g_qkv[L * 3 * DM];
__device__ float g_q[H * L * HD];
__device__ float g_k[H * L * HD];
__device__ float g_v[H * L * HD];
__device__ float g_attn[L * DM];
__device__ float g_cls_m[H * NCHUNK];
__device__ float g_cls_s[H * NCHUNK];
__device__ float g_cls_o[H * NCHUNK * HD];

__device__ __nv_bfloat16 g_Ahi[L * DM],  g_Alo[L * DM];          // emb split
__device__ __nv_bfloat16 g_Wqhi[3*DM*DM], g_Wqlo[3*DM*DM];       // W_qkv^T split [2304][768]
__device__ __nv_bfloat16 g_Wohi[DM*DM],  g_Wolo[DM*DM];          // W_o^T split   [768][768]
__device__ __nv_bfloat16 g_Chi[L * DM],  g_Clo[L * DM];          // attn-out split

// ====================== prep kernels ==========================================
__global__ void __launch_bounds__(256) split_bf16(const float* __restrict__ x,
        __nv_bfloat16* __restrict__ hi, __nv_bfloat16* __restrict__ lo, int n) {
    int i = blockIdx.x * 256 + threadIdx.x;
    if (i < n) {
        float v = x[i];
        __nv_bfloat16 h = __float2bfloat16(v);
        hi[i] = h;
        lo[i] = __float2bfloat16(v - __bfloat162float(h));
    }
}

// W [K,N] fp32 row-major  ->  Thi/Tlo [N,K] bf16 row-major
__global__ void __launch_bounds__(256) transpose_split(const float* __restrict__ W,
        __nv_bfloat16* __restrict__ Thi, __nv_bfloat16* __restrict__ Tlo, int K, int N) {
    __shared__ float t[32][33];
    int n0 = blockIdx.x * 32, k0 = blockIdx.y * 32;
    int tx = threadIdx.x, ty = threadIdx.y;
    #pragma unroll
    for (int i = ty; i < 32; i += 8)
        t[i][tx] = W[(size_t)(k0 + i) * N + n0 + tx];
    __syncthreads();
    #pragma unroll
    for (int i = ty; i < 32; i += 8) {
        float v = t[tx][i];
        __nv_bfloat16 h = __float2bfloat16(v);
        size_t o = (size_t)(n0 + i) * K + k0 + tx;
        Thi[o] = h;
        Tlo[o] = __float2bfloat16(v - __bfloat162float(h));
    }
}

// ====================== mma.sync helpers ======================================
__device__ __forceinline__ uint32_t smem_u32(const void* p) {
    uint32_t a;
    asm("{ .reg .u64 t; cvta.to.shared.u64 t, %1; cvt.u32.u64 %0, t; }" : "=r"(a) : "l"(p));
    return a;
}
__device__ __forceinline__ void ldsm_x4(uint32_t& r0, uint32_t& r1, uint32_t& r2, uint32_t& r3,
                                        uint32_t addr) {
    asm volatile("ldmatrix.sync.aligned.m8n8.x4.shared.b16 {%0,%1,%2,%3}, [%4];"
                 : "=r"(r0), "=r"(r1), "=r"(r2), "=r"(r3) : "r"(addr));
}
__device__ __forceinline__ void mma_bf16(float* d, const uint32_t* a, const uint32_t* b) {
    asm volatile("mma.sync.aligned.m16n8k16.row.col.f32.bf16.bf16.f32 "
                 "{%0,%1,%2,%3}, {%4,%5,%6,%7}, {%8,%9}, {%0,%1,%2,%3};"
                 : "+f"(d[0]), "+f"(d[1]), "+f"(d[2]), "+f"(d[3])
                 : "r"(a[0]), "r"(a[1]), "r"(a[2]), "r"(a[3]), "r"(b[0]), "r"(b[1]));
}
#define CP_ASYNC_16(dst, src) \
    asm volatile("cp.async.cg.shared.global [%0], [%1], 16;" :: "r"(dst), "l"(src))
#define CP_COMMIT() asm volatile("cp.async.commit_group;" ::: "memory")
#define CP_WAIT2()  asm volatile("cp.async.wait_group 2;" ::: "memory")

// ====================== HMMA bf16 3-pass GEMM (cp.async pipelined) ============
// C[M,N] = (Ahi+Alo)[M,K] @ (Bhi+Blo)[N,K]^T + bias   (drops lo*lo)
#define SMSTRIDE 40
#define STAGE_ELEMS (128 * SMSTRIDE)
#define NSTAGES 4

__global__ void __launch_bounds__(256, 2)
gemm_bf16_mma(const __nv_bfloat16* __restrict__ Ahi, const __nv_bfloat16* __restrict__ Alo,
              const __nv_bfloat16* __restrict__ Bhi, const __nv_bfloat16* __restrict__ Blo,
              const float* __restrict__ bias, float* __restrict__ C,
              int N, int K) {
    extern __shared__ __align__(16) __nv_bfloat16 dsm[];
    __nv_bfloat16* As = dsm;
    __nv_bfloat16* Bs = dsm + NSTAGES * STAGE_ELEMS;

    const int tid  = threadIdx.x;
    const int wid  = tid >> 5;
    const int lane = tid & 31;
    const int bn = blockIdx.x, bm = blockIdx.y;
    const int wm = (wid >> 2) * 64;
    const int wn = (wid & 3) * 32;

    const __nv_bfloat16* Ap[3] = {Ahi, Ahi, Alo};
    const __nv_bfloat16* Bp[3] = {Bhi, Blo, Bhi};

    const int KT  = K >> 5;
    const int NST = 3 * KT;

    float acc[4][4][4] = {};

    const int r0c = tid >> 2,         c0c = (tid & 3) * 8;
    const int r1c = (tid + 256) >> 2, c1c = ((tid + 256) & 3) * 8;

    auto load_stage = [&](int s, int buf) {
        int p  = s / KT;
        int kt = s - p * KT;
        const __nv_bfloat16* Ag = Ap[p] + (size_t)bm * 128 * K + kt * 32;
        const __nv_bfloat16* Bg = Bp[p] + (size_t)bn * 128 * K + kt * 32;
        uint32_t a_s = smem_u32(As + buf * STAGE_ELEMS);
        uint32_t b_s = smem_u32(Bs + buf * STAGE_ELEMS);
        CP_ASYNC_16(a_s + (uint32_t)(r0c * SMSTRIDE + c0c) * 2, Ag + (size_t)r0c * K + c0c);
        CP_ASYNC_16(a_s + (uint32_t)(r1c * SMSTRIDE + c1c) * 2, Ag + (size_t)r1c * K + c1c);
        CP_ASYNC_16(b_s + (uint32_t)(r0c * SMSTRIDE + c0c) * 2, Bg + (size_t)r0c * K + c0c);
        CP_ASYNC_16(b_s + (uint32_t)(r1c * SMSTRIDE + c1c) * 2, Bg + (size_t)r1c * K + c1c);
    };

    #pragma unroll
    for (int s = 0; s < 3; s++) { load_stage(s, s); CP_COMMIT(); }

    for (int s = 0; s < NST; s++) {
        const int buf = s & (NSTAGES - 1);
        CP_WAIT2();
        __syncthreads();

        const uint32_t a_base = smem_u32(As + buf * STAGE_ELEMS);
        const uint32_t b_base = smem_u32(Bs + buf * STAGE_ELEMS);

        #pragma unroll
        for (int ks = 0; ks < 2; ks++) {
            uint32_t af[4][4], bf[4][2];
            #pragma unroll
            for (int mi = 0; mi < 4; mi++) {
                int row = wm + mi * 16 + (lane & 7) + ((lane & 8) ? 8 : 0);
                int col = ks * 16 + ((lane & 16) ? 8 : 0);
                ldsm_x4(af[mi][0], af[mi][1], af[mi][2], af[mi][3],
                        a_base + (uint32_t)(row * SMSTRIDE + col) * 2);
            }
            // B fragments: one ldsm_x4 covers two n8 tiles (4 8x8 matrices)
            #pragma unroll
            for (int njp = 0; njp < 2; njp++) {
                int grp = lane >> 3;
                int row = wn + (njp * 2 + (grp >> 1)) * 8 + (lane & 7);
                int col = ks * 16 + (grp & 1) * 8;
                uint32_t r0, r1, r2, r3;
                ldsm_x4(r0, r1, r2, r3, b_base + (uint32_t)(row * SMSTRIDE + col) * 2);
                bf[njp*2][0]   = r0;  bf[njp*2][1]   = r1;
                bf[njp*2+1][0] = r2;  bf[njp*2+1][1] = r3;
            }
            #pragma unroll
            for (int mi = 0; mi < 4; mi++)
                #pragma unroll
                for (int nj = 0; nj < 4; nj++)
                    mma_bf16(acc[mi][nj], af[mi], bf[nj]);
        }

        if (s + 3 < NST) load_stage(s + 3, (s + 3) & (NSTAGES - 1));
        CP_COMMIT();
    }

    #pragma unroll
    for (int nj = 0; nj < 4; nj++) {
        int gcol = bn * 128 + wn + nj * 8 + (lane & 3) * 2;
        float2 bv = *(const float2*)(bias + gcol);
        #pragma unroll
        for (int mi = 0; mi < 4; mi++) {
            int grow = bm * 128 + wm + mi * 16 + (lane >> 2);
            float2 v0 = { acc[mi][nj][0] + bv.x, acc[mi][nj][1] + bv.y };
            float2 v1 = { acc[mi][nj][2] + bv.x, acc[mi][nj][3] + bv.y };
            *(float2*)(C + (size_t)grow * N + gcol)       = v0;
            *(float2*)(C + (size_t)(grow + 8) * N + gcol) = v1;
        }
    }
}

// ====================== RoPE + head split =====================================
__global__ void __launch_bounds__(384) rope_split_kernel() {
    int l = blockIdx.x;
    int t = threadIdx.x;
    int h = t >> 5;
    int i = t & 31;

    const float* row = g_qkv + (size_t)l * (3*DM);
    float invf = powf(10000.0f, -(float)i * (1.0f/32.0f));
    float ang = (float)l * invf;
    float s, c;
    sincosf(ang, &s, &c);

    int qo = h*HD + i;
    float q1 = row[qo],        q2 = row[qo + 32];
    float k1 = row[DM + qo],   k2 = row[DM + qo + 32];
    int o = (h*L + l)*HD + i;
    g_q[o]      = q1*c - q2*s;
    g_q[o + 32] = q1*s + q2*c;
    g_k[o]      = k1*c - k2*s;
    g_k[o + 32] = k1*s + k2*c;
    g_v[o]      = row[2*DM + qo];
    g_v[o + 32] = row[2*DM + qo + 32];
}

// ====================== sliding-window attention ==============================
// K staged in smem (stride-68, float4 loads); V read directly from gmem (coalesced).
__global__ void __launch_bounds__(512) window_attn_kernel(const int* __restrict__ mask) {
    extern __shared__ float sm[];
    float* ks = sm;                        // NROWS * WSTRIDE
    float* qs = ks + NROWS * WSTRIDE;      // TQ * 64
    float* ws = qs + TQ * HD;              // TQ * 128
    int*   rv = (int*)(ws + TQ * WIN);     // NROWS

    int h  = blockIdx.x / (L / TQ);
    int qt = blockIdx.x % (L / TQ);
    int l0 = qt * TQ;
    int lo = l0 - 64;
    int tid = threadIdx.x;

    for (int idx = tid; idx < NROWS; idx += 512) {
        int lr = lo + idx;
        rv[idx] = (lr >= 0 && lr < L) ? (mask[lr] != 0) : 0;
    }
    for (int idx = tid; idx < NROWS * HD; idx += 512) {
        int r = idx >> 6, d = idx & 63;
        int lr = lo + r;
        bool val = (lr >= 0 && lr < L);
        ks[r*WSTRIDE + d] = val ? g_k[(h*L + (val ? lr : 0))*HD + d] : 0.0f;
    }
    for (int idx = tid; idx < TQ * HD; idx += 512) {
        qs[idx] = g_q[(h*L + l0)*HD + idx];
    }
    __syncthreads();

    int wq   = tid >> 5;
    int lane = tid & 31;
    int l = l0 + wq;

    // scores: lane handles window positions lane, lane+32, lane+64, lane+96
    const float4* qs4 = (const float4*)(qs + wq*HD);
    float sc[4];
    #pragma unroll
    for (int w4 = 0; w4 < 4; w4++) {
        int r = wq + lane + w4*32;
        const float4* ks4 = (const float4*)(ks + r*WSTRIDE);
        float s = 0.f;
        #pragma unroll
        for (int d4 = 0; d4 < 16; d4++) {
            float4 kk = ks4[d4], qq = qs4[d4];
            s += kk.x*qq.x + kk.y*qq.y + kk.z*qq.z + kk.w*qq.w;
        }
        sc[w4] = rv[r] ? s * SCALE : -1e30f;
    }

    float m = fmaxf(fmaxf(sc[0], sc[1]), fmaxf(sc[2], sc[3]));
    #pragma unroll
    for (int o = 16; o > 0; o >>= 1) m = fmaxf(m, __shfl_xor_sync(0xffffffffu, m, o));
    float e[4], sum = 0.f;
    #pragma unroll
    for (int w4 = 0; w4 < 4; w4++) { e[w4] = expf(sc[w4] - m); sum += e[w4]; }
    #pragma unroll
    for (int o = 16; o > 0; o >>= 1) sum += __shfl_xor_sync(0xffffffffu, sum, o);
    float inv = 1.0f / sum;
    #pragma unroll
    for (int w4 = 0; w4 < 4; w4++) ws[wq*WIN + lane + w4*32] = e[w4] * inv;
    __syncwarp();

    // output: lane owns dims (2*lane, 2*lane+1); V read coalesced from gmem
    float2 a = {0.f, 0.f};
    const float* vbase = g_v + (size_t)h*L*HD + 2*lane;
    #pragma unroll 4
    for (int w = 0; w < WIN; w++) {
        float wt = ws[wq*WIN + w];
        int lr = lo + wq + w;
        lr = lr < 0 ? 0 : (lr > L-1 ? L-1 : lr);
        float2 v = *(const float2*)(vbase + (size_t)lr*HD);
        a.x += wt * v.x;
        a.y += wt * v.y;
    }
    *(float2*)(g_attn + (size_t)l*DM + h*HD + 2*lane) = a;
}

// ====================== CLS split-softmax ======================================
// K staged in smem; V read directly from gmem (coalesced).
__global__ void __launch_bounds__(128) cls_part_kernel(const int* __restrict__ mask) {
    extern __shared__ float smc[];
    float* ksm = smc;                  // 128 * 65
    float* q0  = ksm + CKEYS*65;       // 64
    float* ew  = q0 + HD;              // 128
    float* red = ew + CKEYS;           // 128

    int c = blockIdx.x, h = blockIdx.y;
    int tid = threadIdx.x;
    int base = c * CKEYS;

    if (tid < HD) q0[tid] = g_q[(size_t)(h*L)*HD + tid];
    for (int idx = tid; idx < CKEYS*HD; idx += 128) {
        int key = idx >> 6, d = idx & 63;
        ksm[key*65 + d] = g_k[(size_t)(h*L + base + key)*HD + d];
    }
    __syncthreads();

    float s = 0.f;
    #pragma unroll
    for (int d = 0; d < HD; d++) s += ksm[tid*65 + d] * q0[d];
    s = (mask[base + tid] != 0) ? s * SCALE : -1e30f;

    red[tid] = s; __syncthreads();
    for (int o = 64; o > 0; o >>= 1) {
        if (tid < o) red[tid] = fmaxf(red[tid], red[tid + o]);
        __syncthreads();
    }
    float m_c = red[0];
    __syncthreads();

    float e = expf(s - m_c);
    ew[tid] = e;
    red[tid] = e; __syncthreads();
    for (int o = 64; o > 0; o >>= 1) {
        if (tid < o) red[tid] += red[tid + o];
        __syncthreads();
    }
    float s_c = red[0];
    __syncthreads();

    int d = tid & 63, half = tid >> 6;
    const float* vb = g_v + (size_t)(h*L + base + half*64)*HD + d;
    float acc = 0.f;
    #pragma unroll 8
    for (int kk = 0; kk < 64; kk++)
        acc += ew[half*64 + kk] * vb[(size_t)kk*HD];
    red[tid] = acc; __syncthreads();
    if (tid < HD) {
        g_cls_o[(size_t)(h*NCHUNK + c)*HD + tid] = red[tid] + red[HD + tid];
        if (tid == 0) { g_cls_m[h*NCHUNK + c] = m_c; g_cls_s[h*NCHUNK + c] = s_c; }
    }
}

__global__ void __launch_bounds__(768) cls_combine_kernel() {
    int tid = threadIdx.x;
    int h = tid >> 6, d = tid & 63;
    float m = -1e30f;
    #pragma unroll
    for (int c = 0; c < NCHUNK; c++) m = fmaxf(m, g_cls_m[h*NCHUNK + c]);
    float den = 0.f, num = 0.f;
    #pragma unroll
    for (int c = 0; c < NCHUNK; c++) {
        float w = expf(g_cls_m[h*NCHUNK + c] - m);
        den += g_cls_s[h*NCHUNK + c] * w;
        num += g_cls_o[(size_t)(h*NCHUNK + c)*HD + d] * w;
    }
    g_attn[h*HD + d] = num / den;
}

// ====================== launch =================================================
extern "C" void kernel_launch(void* const* d_in, const int* in_sizes, int n_in,
                              void* d_out, int out_size) {
    (void)in_sizes; (void)n_in; (void)out_size;
    const float* emb   = (const float*)d_in[0];
    const int*   mask  = (const int*)  d_in[1];
    const float* W_qkv = (const float*)d_in[2];
    const float* b_qkv = (const float*)d_in[3];
    const float* W_o   = (const float*)d_in[4];
    const float* b_o   = (const float*)d_in[5];
    float* out = (float*)d_out;

    float *p_qkv, *p_attn;
    cudaGetSymbolAddress((void**)&p_qkv,  g_qkv);
    cudaGetSymbolAddress((void**)&p_attn, g_attn);
    __nv_bfloat16 *p_Ahi, *p_Alo, *p_Wqhi, *p_Wqlo, *p_Wohi, *p_Wolo, *p_Chi, *p_Clo;
    cudaGetSymbolAddress((void**)&p_Ahi,  g_Ahi);
    cudaGetSymbolAddress((void**)&p_Alo,  g_Alo);
    cudaGetSymbolAddress((void**)&p_Wqhi, g_Wqhi);
    cudaGetSymbolAddress((void**)&p_Wqlo, g_Wqlo);
    cudaGetSymbolAddress((void**)&p_Wohi, g_Wohi);
    cudaGetSymbolAddress((void**)&p_Wolo, g_Wolo);
    cudaGetSymbolAddress((void**)&p_Chi,  g_Chi);
    cudaGetSymbolAddress((void**)&p_Clo,  g_Clo);

    constexpr int GSMEM = NSTAGES * 2 * STAGE_ELEMS * 2;  // 81920 B
    cudaFuncSetAttribute(gemm_bf16_mma, cudaFuncAttributeMaxDynamicSharedMemorySize, GSMEM);

    // 0. operand prep
    split_bf16<<<(L*DM + 255)/256, 256>>>(emb, p_Ahi, p_Alo, L*DM);
    transpose_split<<<dim3((3*DM)/32, DM/32), dim3(32,8)>>>(W_qkv, p_Wqhi, p_Wqlo, DM, 3*DM);
    transpose_split<<<dim3(DM/32, DM/32), dim3(32,8)>>>(W_o, p_Wohi, p_Wolo, DM, DM);

    // 1. QKV GEMM (HMMA + cp.async): [2048,768] x [768,2304]
    gemm_bf16_mma<<<dim3((3*DM)/128, L/128), 256, GSMEM>>>(
        p_Ahi, p_Alo, p_Wqhi, p_Wqlo, b_qkv, p_qkv, 3*DM, DM);

    // 2. RoPE + head split
    rope_split_kernel<<<L, 384>>>();

    // 3. sliding-window attention
    constexpr int SMEM_WIN = (NROWS*WSTRIDE + TQ*HD + TQ*WIN) * 4 + NROWS * 4;
    cudaFuncSetAttribute(window_attn_kernel,
                         cudaFuncAttributeMaxDynamicSharedMemorySize, SMEM_WIN);
    window_attn_kernel<<<H * (L/TQ), 512, SMEM_WIN>>>(mask);

    // 4. CLS row
    constexpr int SMEM_CLS = (CKEYS*65 + HD + CKEYS + 128) * 4;
    cudaFuncSetAttribute(cls_part_kernel,
                         cudaFuncAttributeMaxDynamicSharedMemorySize, SMEM_CLS);
    cls_part_kernel<<<dim3(NCHUNK, H), 128, SMEM_CLS>>>(mask);
    cls_combine_kernel<<<1, 768>>>();

    // 5. output projection (HMMA + cp.async): [2048,768] x [768,768]
    split_bf16<<<(L*DM + 255)/256, 256>>>(p_attn, p_Chi, p_Clo, L*DM);
    gemm_bf16_mma<<<dim3(DM/128, L/128), 256, GSMEM>>>(
        p_Chi, p_Clo, p_Wohi, p_Wolo, b_o, out, DM, DM);
}

// round 7
// speedup vs baseline: 1.8262x; 1.0134x over previous
#include <cuda_runtime.h>
#include <cuda_bf16.h>
#include <math.h>
#include <stdint.h>

#define L    2048
#define DM   768
#define H    12
#define HD   64
#define WIN  128
#define TQ   16
#define NROWS 144
#define NCHUNK 16
#define CKEYS  128
#define WSTRIDE 68   // floats per K row in window smem (64 data + 4 pad)

static constexpr float SCALE = 0.03608439182435161f;  // 1/sqrt(768)

// ====================== scratch ================================================
__device__ float g_qkv[L * 3 * DM];
__device__ float g_q[H * L * HD];
__device__ float g_k[H * L * HD];
__device__ float g_v[H * L * HD];
__device__ float g_cls_m[H * NCHUNK];
__device__ float g_cls_s[H * NCHUNK];
__device__ float g_cls_o[H * NCHUNK * HD];

__device__ __nv_bfloat16 g_Ahi[L * DM],  g_Alo[L * DM];          // emb split
__device__ __nv_bfloat16 g_Wqhi[3*DM*DM], g_Wqlo[3*DM*DM];       // W_qkv^T split
__device__ __nv_bfloat16 g_Wohi[DM*DM],  g_Wolo[DM*DM];          // W_o^T split
__device__ __nv_bfloat16 g_Chi[L * DM],  g_Clo[L * DM];          // attn-out split

// ====================== prep kernels ==========================================
__global__ void __launch_bounds__(256) split_bf16(const float* __restrict__ x,
        __nv_bfloat16* __restrict__ hi, __nv_bfloat16* __restrict__ lo, int n) {
    int i = blockIdx.x * 256 + threadIdx.x;
    if (i < n) {
        float v = x[i];
        __nv_bfloat16 h = __float2bfloat16(v);
        hi[i] = h;
        lo[i] = __float2bfloat16(v - __bfloat162float(h));
    }
}

// W [K,N] fp32 row-major  ->  Thi/Tlo [N,K] bf16 row-major
__global__ void __launch_bounds__(256) transpose_split(const float* __restrict__ W,
        __nv_bfloat16* __restrict__ Thi, __nv_bfloat16* __restrict__ Tlo, int K, int N) {
    __shared__ float t[32][33];
    int n0 = blockIdx.x * 32, k0 = blockIdx.y * 32;
    int tx = threadIdx.x, ty = threadIdx.y;
    #pragma unroll
    for (int i = ty; i < 32; i += 8)
        t[i][tx] = W[(size_t)(k0 + i) * N + n0 + tx];
    __syncthreads();
    #pragma unroll
    for (int i = ty; i < 32; i += 8) {
        float v = t[tx][i];
        __nv_bfloat16 h = __float2bfloat16(v);
        size_t o = (size_t)(n0 + i) * K + k0 + tx;
        Thi[o] = h;
        Tlo[o] = __float2bfloat16(v - __bfloat162float(h));
    }
}

// ====================== mma.sync helpers ======================================
__device__ __forceinline__ uint32_t smem_u32(const void* p) {
    uint32_t a;
    asm("{ .reg .u64 t; cvta.to.shared.u64 t, %1; cvt.u32.u64 %0, t; }" : "=r"(a) : "l"(p));
    return a;
}
__device__ __forceinline__ void ldsm_x4(uint32_t& r0, uint32_t& r1, uint32_t& r2, uint32_t& r3,
                                        uint32_t addr) {
    asm volatile("ldmatrix.sync.aligned.m8n8.x4.shared.b16 {%0,%1,%2,%3}, [%4];"
                 : "=r"(r0), "=r"(r1), "=r"(r2), "=r"(r3) : "r"(addr));
}
__device__ __forceinline__ void mma_bf16(float* d, const uint32_t* a, const uint32_t* b) {
    asm volatile("mma.sync.aligned.m16n8k16.row.col.f32.bf16.bf16.f32 "
                 "{%0,%1,%2,%3}, {%4,%5,%6,%7}, {%8,%9}, {%0,%1,%2,%3};"
                 : "+f"(d[0]), "+f"(d[1]), "+f"(d[2]), "+f"(d[3])
                 : "r"(a[0]), "r"(a[1]), "r"(a[2]), "r"(a[3]), "r"(b[0]), "r"(b[1]));
}
#define CP_ASYNC_16(dst, src) \
    asm volatile("cp.async.cg.shared.global [%0], [%1], 16;" :: "r"(dst), "l"(src))
#define CP_COMMIT() asm volatile("cp.async.commit_group;" ::: "memory")
#define CP_WAIT_N(n) asm volatile("cp.async.wait_group %0;" :: "n"(n) : "memory")

// ====================== HMMA bf16 3-pass GEMM (5-stage cp.async) ==============
// C[M,N] = (Ahi+Alo)[M,K] @ (Bhi+Blo)[N,K]^T + bias   (drops lo*lo)
// 256 threads = 8 warps (2M x 4N); warp tile (BM/2) x 32.
#define SMSTRIDE 40
#define NSTAGES 5

template<int BM>
__global__ void __launch_bounds__(256, 2)
gemm_bf16_mma(const __nv_bfloat16* __restrict__ Ahi, const __nv_bfloat16* __restrict__ Alo,
              const __nv_bfloat16* __restrict__ Bhi, const __nv_bfloat16* __restrict__ Blo,
              const float* __restrict__ bias, float* __restrict__ C,
              int N, int K) {
    constexpr int MI  = BM / 32;          // m16 tiles per warp
    constexpr int ACH = BM / 64;          // 16B chunks per thread for A stage
    constexpr int A_STAGE = BM * SMSTRIDE;
    constexpr int B_STAGE = 128 * SMSTRIDE;

    extern __shared__ __align__(16) __nv_bfloat16 dsm[];
    __nv_bfloat16* As = dsm;
    __nv_bfloat16* Bs = dsm + NSTAGES * A_STAGE;

    const int tid  = threadIdx.x;
    const int wid  = tid >> 5;
    const int lane = tid & 31;
    const int bn = blockIdx.x, bm = blockIdx.y;
    const int wm = (wid >> 2) * (BM / 2);
    const int wn = (wid & 3) * 32;

    const __nv_bfloat16* Ap[3] = {Ahi, Ahi, Alo};
    const __nv_bfloat16* Bp[3] = {Bhi, Blo, Bhi};

    const int KT  = K >> 5;
    const int NST = 3 * KT;

    float acc[MI][4][4] = {};

    auto load_stage = [&](int s, int buf) {
        int p  = s / KT;
        int kt = s - p * KT;
        const __nv_bfloat16* Ag = Ap[p] + (size_t)bm * BM * K + kt * 32;
        const __nv_bfloat16* Bg = Bp[p] + (size_t)bn * 128 * K + kt * 32;
        uint32_t a_s = smem_u32(As + buf * A_STAGE);
        uint32_t b_s = smem_u32(Bs + buf * B_STAGE);
        #pragma unroll
        for (int i = 0; i < ACH; i++) {
            int ch = tid + i * 256;
            int r = ch >> 2, cc = (ch & 3) * 8;
            CP_ASYNC_16(a_s + (uint32_t)(r * SMSTRIDE + cc) * 2, Ag + (size_t)r * K + cc);
        }
        #pragma unroll
        for (int i = 0; i < 2; i++) {
            int ch = tid + i * 256;
            int r = ch >> 2, cc = (ch & 3) * 8;
            CP_ASYNC_16(b_s + (uint32_t)(r * SMSTRIDE + cc) * 2, Bg + (size_t)r * K + cc);
        }
    };

    #pragma unroll
    for (int s = 0; s < NSTAGES - 1; s++) { load_stage(s, s); CP_COMMIT(); }

    for (int s = 0; s < NST; s++) {
        const int buf = s % NSTAGES;
        CP_WAIT_N(NSTAGES - 2);
        __syncthreads();

        const uint32_t a_base = smem_u32(As + buf * A_STAGE);
        const uint32_t b_base = smem_u32(Bs + buf * B_STAGE);

        #pragma unroll
        for (int ks = 0; ks < 2; ks++) {
            uint32_t af[MI][4], bf[4][2];
            #pragma unroll
            for (int mi = 0; mi < MI; mi++) {
                int row = wm + mi * 16 + (lane & 7) + ((lane & 8) ? 8 : 0);
                int col = ks * 16 + ((lane & 16) ? 8 : 0);
                ldsm_x4(af[mi][0], af[mi][1], af[mi][2], af[mi][3],
                        a_base + (uint32_t)(row * SMSTRIDE + col) * 2);
            }
            #pragma unroll
            for (int njp = 0; njp < 2; njp++) {
                int grp = lane >> 3;
                int row = wn + (njp * 2 + (grp >> 1)) * 8 + (lane & 7);
                int col = ks * 16 + (grp & 1) * 8;
                uint32_t r0, r1, r2, r3;
                ldsm_x4(r0, r1, r2, r3, b_base + (uint32_t)(row * SMSTRIDE + col) * 2);
                bf[njp*2][0]   = r0;  bf[njp*2][1]   = r1;
                bf[njp*2+1][0] = r2;  bf[njp*2+1][1] = r3;
            }
            #pragma unroll
            for (int mi = 0; mi < MI; mi++)
                #pragma unroll
                for (int nj = 0; nj < 4; nj++)
                    mma_bf16(acc[mi][nj], af[mi], bf[nj]);
        }

        if (s + NSTAGES - 1 < NST) load_stage(s + NSTAGES - 1, (s + NSTAGES - 1) % NSTAGES);
        CP_COMMIT();
    }

    #pragma unroll
    for (int nj = 0; nj < 4; nj++) {
        int gcol = bn * 128 + wn + nj * 8 + (lane & 3) * 2;
        float2 bv = *(const float2*)(bias + gcol);
        #pragma unroll
        for (int mi = 0; mi < MI; mi++) {
            int grow = bm * BM + wm + mi * 16 + (lane >> 2);
            float2 v0 = { acc[mi][nj][0] + bv.x, acc[mi][nj][1] + bv.y };
            float2 v1 = { acc[mi][nj][2] + bv.x, acc[mi][nj][3] + bv.y };
            *(float2*)(C + (size_t)grow * N + gcol)       = v0;
            *(float2*)(C + (size_t)(grow + 8) * N + gcol) = v1;
        }
    }
}

// ====================== RoPE + head split =====================================
__global__ void __launch_bounds__(384) rope_split_kernel() {
    int l = blockIdx.x;
    int t = threadIdx.x;
    int h = t >> 5;
    int i = t & 31;

    const float* row = g_qkv + (size_t)l * (3*DM);
    float invf = powf(10000.0f, -(float)i * (1.0f/32.0f));
    float ang = (float)l * invf;
    float s, c;
    sincosf(ang, &s, &c);

    int qo = h*HD + i;
    float q1 = row[qo],        q2 = row[qo + 32];
    float k1 = row[DM + qo],   k2 = row[DM + qo + 32];
    int o = (h*L + l)*HD + i;
    g_q[o]      = q1*c - q2*s;
    g_q[o + 32] = q1*s + q2*c;
    g_k[o]      = k1*c - k2*s;
    g_k[o + 32] = k1*s + k2*c;
    g_v[o]      = row[2*DM + qo];
    g_v[o + 32] = row[2*DM + qo + 32];
}

// ====================== sliding-window attention ==============================
// Writes attention output directly as split bf16 (hi/lo) for the out-proj GEMM.
__global__ void __launch_bounds__(512) window_attn_kernel(const int* __restrict__ mask) {
    extern __shared__ float sm[];
    float* ks = sm;                        // NROWS * WSTRIDE
    float* qs = ks + NROWS * WSTRIDE;      // TQ * 64
    float* ws = qs + TQ * HD;              // TQ * 128
    int*   rv = (int*)(ws + TQ * WIN);     // NROWS

    int h  = blockIdx.x / (L / TQ);
    int qt = blockIdx.x % (L / TQ);
    int l0 = qt * TQ;
    int lo = l0 - 64;
    int tid = threadIdx.x;

    for (int idx = tid; idx < NROWS; idx += 512) {
        int lr = lo + idx;
        rv[idx] = (lr >= 0 && lr < L) ? (mask[lr] != 0) : 0;
    }
    for (int idx = tid; idx < NROWS * HD; idx += 512) {
        int r = idx >> 6, d = idx & 63;
        int lr = lo + r;
        bool val = (lr >= 0 && lr < L);
        ks[r*WSTRIDE + d] = val ? g_k[(h*L + (val ? lr : 0))*HD + d] : 0.0f;
    }
    for (int idx = tid; idx < TQ * HD; idx += 512) {
        qs[idx] = g_q[(h*L + l0)*HD + idx];
    }
    __syncthreads();

    int wq   = tid >> 5;
    int lane = tid & 31;
    int l = l0 + wq;

    const float4* qs4 = (const float4*)(qs + wq*HD);
    float sc[4];
    #pragma unroll
    for (int w4 = 0; w4 < 4; w4++) {
        int r = wq + lane + w4*32;
        const float4* ks4 = (const float4*)(ks + r*WSTRIDE);
        float s = 0.f;
        #pragma unroll
        for (int d4 = 0; d4 < 16; d4++) {
            float4 kk = ks4[d4], qq = qs4[d4];
            s += kk.x*qq.x + kk.y*qq.y + kk.z*qq.z + kk.w*qq.w;
        }
        sc[w4] = rv[r] ? s * SCALE : -1e30f;
    }

    float m = fmaxf(fmaxf(sc[0], sc[1]), fmaxf(sc[2], sc[3]));
    #pragma unroll
    for (int o = 16; o > 0; o >>= 1) m = fmaxf(m, __shfl_xor_sync(0xffffffffu, m, o));
    float e[4], sum = 0.f;
    #pragma unroll
    for (int w4 = 0; w4 < 4; w4++) { e[w4] = expf(sc[w4] - m); sum += e[w4]; }
    #pragma unroll
    for (int o = 16; o > 0; o >>= 1) sum += __shfl_xor_sync(0xffffffffu, sum, o);
    float inv = 1.0f / sum;
    #pragma unroll
    for (int w4 = 0; w4 < 4; w4++) ws[wq*WIN + lane + w4*32] = e[w4] * inv;
    __syncwarp();

    float2 a = {0.f, 0.f};
    const float* vbase = g_v + (size_t)h*L*HD + 2*lane;
    #pragma unroll 4
    for (int w = 0; w < WIN; w++) {
        float wt = ws[wq*WIN + w];
        int lr = lo + wq + w;
        lr = lr < 0 ? 0 : (lr > L-1 ? L-1 : lr);
        float2 v = *(const float2*)(vbase + (size_t)lr*HD);
        a.x += wt * v.x;
        a.y += wt * v.y;
    }
    // split-store bf16 hi/lo
    __nv_bfloat16 hx = __float2bfloat16(a.x);
    __nv_bfloat16 hy = __float2bfloat16(a.y);
    __nv_bfloat162 hi2; hi2.x = hx; hi2.y = hy;
    __nv_bfloat162 lo2;
    lo2.x = __float2bfloat16(a.x - __bfloat162float(hx));
    lo2.y = __float2bfloat16(a.y - __bfloat162float(hy));
    size_t o = (size_t)l*DM + h*HD + 2*lane;
    *(__nv_bfloat162*)(g_Chi + o) = hi2;
    *(__nv_bfloat162*)(g_Clo + o) = lo2;
}

// ====================== CLS split-softmax ======================================
__global__ void __launch_bounds__(128) cls_part_kernel(const int* __restrict__ mask) {
    extern __shared__ float smc[];
    float* ksm = smc;                  // 128 * 65
    float* q0  = ksm + CKEYS*65;       // 64
    float* ew  = q0 + HD;              // 128
    float* red = ew + CKEYS;           // 128

    int c = blockIdx.x, h = blockIdx.y;
    int tid = threadIdx.x;
    int base = c * CKEYS;

    if (tid < HD) q0[tid] = g_q[(size_t)(h*L)*HD + tid];
    for (int idx = tid; idx < CKEYS*HD; idx += 128) {
        int key = idx >> 6, d = idx & 63;
        ksm[key*65 + d] = g_k[(size_t)(h*L + base + key)*HD + d];
    }
    __syncthreads();

    float s = 0.f;
    #pragma unroll
    for (int d = 0; d < HD; d++) s += ksm[tid*65 + d] * q0[d];
    s = (mask[base + tid] != 0) ? s * SCALE : -1e30f;

    red[tid] = s; __syncthreads();
    for (int o = 64; o > 0; o >>= 1) {
        if (tid < o) red[tid] = fmaxf(red[tid], red[tid + o]);
        __syncthreads();
    }
    float m_c = red[0];
    __syncthreads();

    float e = expf(s - m_c);
    ew[tid] = e;
    red[tid] = e; __syncthreads();
    for (int o = 64; o > 0; o >>= 1) {
        if (tid < o) red[tid] += red[tid + o];
        __syncthreads();
    }
    float s_c = red[0];
    __syncthreads();

    int d = tid & 63, half = tid >> 6;
    const float* vb = g_v + (size_t)(h*L + base + half*64)*HD + d;
    float acc = 0.f;
    #pragma unroll 8
    for (int kk = 0; kk < 64; kk++)
        acc += ew[half*64 + kk] * vb[(size_t)kk*HD];
    red[tid] = acc; __syncthreads();
    if (tid < HD) {
        g_cls_o[(size_t)(h*NCHUNK + c)*HD + tid] = red[tid] + red[HD + tid];
        if (tid == 0) { g_cls_m[h*NCHUNK + c] = m_c; g_cls_s[h*NCHUNK + c] = s_c; }
    }
}

__global__ void __launch_bounds__(768) cls_combine_kernel() {
    int tid = threadIdx.x;
    int h = tid >> 6, d = tid & 63;
    float m = -1e30f;
    #pragma unroll
    for (int c = 0; c < NCHUNK; c++) m = fmaxf(m, g_cls_m[h*NCHUNK + c]);
    float den = 0.f, num = 0.f;
    #pragma unroll
    for (int c = 0; c < NCHUNK; c++) {
        float w = expf(g_cls_m[h*NCHUNK + c] - m);
        den += g_cls_s[h*NCHUNK + c] * w;
        num += g_cls_o[(size_t)(h*NCHUNK + c)*HD + d] * w;
    }
    float o = num / den;
    __nv_bfloat16 hv = __float2bfloat16(o);
    g_Chi[h*HD + d] = hv;
    g_Clo[h*HD + d] = __float2bfloat16(o - __bfloat162float(hv));
}

// ====================== launch =================================================
extern "C" void kernel_launch(void* const* d_in, const int* in_sizes, int n_in,
                              void* d_out, int out_size) {
    (void)in_sizes; (void)n_in; (void)out_size;
    const float* emb   = (const float*)d_in[0];
    const int*   mask  = (const int*)  d_in[1];
    const float* W_qkv = (const float*)d_in[2];
    const float* b_qkv = (const float*)d_in[3];
    const float* W_o   = (const float*)d_in[4];
    const float* b_o   = (const float*)d_in[5];
    float* out = (float*)d_out;

    float* p_qkv;
    cudaGetSymbolAddress((void**)&p_qkv,  g_qkv);
    __nv_bfloat16 *p_Ahi, *p_Alo, *p_Wqhi, *p_Wqlo, *p_Wohi, *p_Wolo, *p_Chi, *p_Clo;
    cudaGetSymbolAddress((void**)&p_Ahi,  g_Ahi);
    cudaGetSymbolAddress((void**)&p_Alo,  g_Alo);
    cudaGetSymbolAddress((void**)&p_Wqhi, g_Wqhi);
    cudaGetSymbolAddress((void**)&p_Wqlo, g_Wqlo);
    cudaGetSymbolAddress((void**)&p_Wohi, g_Wohi);
    cudaGetSymbolAddress((void**)&p_Wolo, g_Wolo);
    cudaGetSymbolAddress((void**)&p_Chi,  g_Chi);
    cudaGetSymbolAddress((void**)&p_Clo,  g_Clo);

    constexpr int GSMEM128 = NSTAGES * (128 + 128) * SMSTRIDE * 2;  // 102400 B
    constexpr int GSMEM64  = NSTAGES * (64  + 128) * SMSTRIDE * 2;  //  76800 B
    cudaFuncSetAttribute(gemm_bf16_mma<128>, cudaFuncAttributeMaxDynamicSharedMemorySize, GSMEM128);
    cudaFuncSetAttribute(gemm_bf16_mma<64>,  cudaFuncAttributeMaxDynamicSharedMemorySize, GSMEM64);

    // 0. operand prep
    split_bf16<<<(L*DM + 255)/256, 256>>>(emb, p_Ahi, p_Alo, L*DM);
    transpose_split<<<dim3((3*DM)/32, DM/32), dim3(32,8)>>>(W_qkv, p_Wqhi, p_Wqlo, DM, 3*DM);
    transpose_split<<<dim3(DM/32, DM/32), dim3(32,8)>>>(W_o, p_Wohi, p_Wolo, DM, DM);

    // 1. QKV GEMM (HMMA + cp.async): [2048,768] x [768,2304]
    gemm_bf16_mma<128><<<dim3((3*DM)/128, L/128), 256, GSMEM128>>>(
        p_Ahi, p_Alo, p_Wqhi, p_Wqlo, b_qkv, p_qkv, 3*DM, DM);

    // 2. RoPE + head split
    rope_split_kernel<<<L, 384>>>();

    // 3. sliding-window attention (writes g_Chi/g_Clo directly)
    constexpr int SMEM_WIN = (NROWS*WSTRIDE + TQ*HD + TQ*WIN) * 4 + NROWS * 4;
    cudaFuncSetAttribute(window_attn_kernel,
                         cudaFuncAttributeMaxDynamicSharedMemorySize, SMEM_WIN);
    window_attn_kernel<<<H * (L/TQ), 512, SMEM_WIN>>>(mask);

    // 4. CLS row (combine overwrites row l=0 of g_Chi/g_Clo)
    constexpr int SMEM_CLS = (CKEYS*65 + HD + CKEYS + 128) * 4;
    cudaFuncSetAttribute(cls_part_kernel,
                         cudaFuncAttributeMaxDynamicSharedMemorySize, SMEM_CLS);
    cls_part_kernel<<<dim3(NCHUNK, H), 128, SMEM_CLS>>>(mask);
    cls_combine_kernel<<<1, 768>>>();

    // 5. output projection (HMMA, BM=64 for full-chip coverage): [2048,768] x [768,768]
    gemm_bf16_mma<64><<<dim3(DM/128, L/64), 256, GSMEM64>>>(
        p_Chi, p_Clo, p_Wohi, p_Wolo, b_o, out, DM, DM);
}

// round 8
// speedup vs baseline: 1.8672x; 1.0224x over previous
#include <cuda_runtime.h>
#include <cuda_bf16.h>
#include <math.h>
#include <stdint.h>

#define L    2048
#define DM   768
#define H    12
#define HD   64
#define WIN  128
#define TQ   32
#define WROWS 160    // 32+127 = 159 rows used
#define NCHUNK 16
#define CKEYS  128
#define WSTRIDE 68   // floats per K row in window smem (64 data + 4 pad)

static constexpr float SCALE = 0.03608439182435161f;  // 1/sqrt(768)

// ====================== scratch ================================================
__device__ float g_qkv[L * 3 * DM];
__device__ float g_q[H * L * HD];
__device__ float g_k[H * L * HD];
__device__ float g_v[H * L * HD];
__device__ float g_cls_m[H * NCHUNK];
__device__ float g_cls_s[H * NCHUNK];
__device__ float g_cls_o[H * NCHUNK * HD];

__device__ __nv_bfloat16 g_Ahi[L * DM],  g_Alo[L * DM];
__device__ __nv_bfloat16 g_Wqhi[3*DM*DM], g_Wqlo[3*DM*DM];
__device__ __nv_bfloat16 g_Wohi[DM*DM],  g_Wolo[DM*DM];
__device__ __nv_bfloat16 g_Chi[L * DM],  g_Clo[L * DM];

// ====================== prep kernels ==========================================
__global__ void __launch_bounds__(256) split_bf16(const float* __restrict__ x,
        __nv_bfloat16* __restrict__ hi, __nv_bfloat16* __restrict__ lo, int n) {
    int i = blockIdx.x * 256 + threadIdx.x;
    if (i < n) {
        float v = x[i];
        __nv_bfloat16 h = __float2bfloat16(v);
        hi[i] = h;
        lo[i] = __float2bfloat16(v - __bfloat162float(h));
    }
}

__global__ void __launch_bounds__(256) transpose_split(const float* __restrict__ W,
        __nv_bfloat16* __restrict__ Thi, __nv_bfloat16* __restrict__ Tlo, int K, int N) {
    __shared__ float t[32][33];
    int n0 = blockIdx.x * 32, k0 = blockIdx.y * 32;
    int tx = threadIdx.x, ty = threadIdx.y;
    #pragma unroll
    for (int i = ty; i < 32; i += 8)
        t[i][tx] = W[(size_t)(k0 + i) * N + n0 + tx];
    __syncthreads();
    #pragma unroll
    for (int i = ty; i < 32; i += 8) {
        float v = t[tx][i];
        __nv_bfloat16 h = __float2bfloat16(v);
        size_t o = (size_t)(n0 + i) * K + k0 + tx;
        Thi[o] = h;
        Tlo[o] = __float2bfloat16(v - __bfloat162float(h));
    }
}

// ====================== mma.sync helpers ======================================
__device__ __forceinline__ uint32_t smem_u32(const void* p) {
    uint32_t a;
    asm("{ .reg .u64 t; cvta.to.shared.u64 t, %1; cvt.u32.u64 %0, t; }" : "=r"(a) : "l"(p));
    return a;
}
__device__ __forceinline__ void ldsm_x4(uint32_t& r0, uint32_t& r1, uint32_t& r2, uint32_t& r3,
                                        uint32_t addr) {
    asm volatile("ldmatrix.sync.aligned.m8n8.x4.shared.b16 {%0,%1,%2,%3}, [%4];"
                 : "=r"(r0), "=r"(r1), "=r"(r2), "=r"(r3) : "r"(addr));
}
__device__ __forceinline__ void mma_bf16(float* d, const uint32_t* a, const uint32_t* b) {
    asm volatile("mma.sync.aligned.m16n8k16.row.col.f32.bf16.bf16.f32 "
                 "{%0,%1,%2,%3}, {%4,%5,%6,%7}, {%8,%9}, {%0,%1,%2,%3};"
                 : "+f"(d[0]), "+f"(d[1]), "+f"(d[2]), "+f"(d[3])
                 : "r"(a[0]), "r"(a[1]), "r"(a[2]), "r"(a[3]), "r"(b[0]), "r"(b[1]));
}
#define CP_ASYNC_16(dst, src) \
    asm volatile("cp.async.cg.shared.global [%0], [%1], 16;" :: "r"(dst), "l"(src))
#define CP_COMMIT() asm volatile("cp.async.commit_group;" ::: "memory")
#define CP_WAIT_1() asm volatile("cp.async.wait_group 1;" ::: "memory")

// ====================== HMMA bf16 merged 3-combo GEMM =========================
// C = (Ahi+Alo)@(Bhi+Blo)^T + bias, dropping lo*lo. Single K sweep; each 32-K
// stage holds all four tiles and issues hi*hi + hi*lo + lo*hi into one acc.
#define SMSTRIDE 40
#define GNST 2          // double-buffered stages

template<int BM>
__global__ void __launch_bounds__(256, 2)
gemm_bf16_mma(const __nv_bfloat16* __restrict__ Ahi, const __nv_bfloat16* __restrict__ Alo,
              const __nv_bfloat16* __restrict__ Bhi, const __nv_bfloat16* __restrict__ Blo,
              const float* __restrict__ bias, float* __restrict__ C,
              int N, int K) {
    constexpr int MI  = BM / 32;
    constexpr int ACH = BM / 64;        // 16B chunks per thread per A region
    constexpr int A_STAGE = BM * SMSTRIDE;
    constexpr int B_STAGE = 128 * SMSTRIDE;

    extern __shared__ __align__(16) __nv_bfloat16 dsm[];
    __nv_bfloat16* As_hi = dsm;
    __nv_bfloat16* As_lo = dsm + GNST * A_STAGE;
    __nv_bfloat16* Bs_hi = dsm + 2 * GNST * A_STAGE;
    __nv_bfloat16* Bs_lo = dsm + 2 * GNST * A_STAGE + GNST * B_STAGE;

    const int tid  = threadIdx.x;
    const int wid  = tid >> 5;
    const int lane = tid & 31;
    const int bn = blockIdx.x, bm = blockIdx.y;
    const int wm = (wid >> 2) * (BM / 2);
    const int wn = (wid & 3) * 32;

    const int KT = K >> 5;   // 24

    float acc[MI][4][4] = {};

    auto load_stage = [&](int kt, int buf) {
        const __nv_bfloat16* Agh = Ahi + (size_t)bm * BM * K + kt * 32;
        const __nv_bfloat16* Agl = Alo + (size_t)bm * BM * K + kt * 32;
        const __nv_bfloat16* Bgh = Bhi + (size_t)bn * 128 * K + kt * 32;
        const __nv_bfloat16* Bgl = Blo + (size_t)bn * 128 * K + kt * 32;
        uint32_t ah = smem_u32(As_hi + buf * A_STAGE);
        uint32_t al = smem_u32(As_lo + buf * A_STAGE);
        uint32_t bh = smem_u32(Bs_hi + buf * B_STAGE);
        uint32_t bl = smem_u32(Bs_lo + buf * B_STAGE);
        #pragma unroll
        for (int i = 0; i < ACH; i++) {
            int ch = tid + i * 256;
            int r = ch >> 2, cc = (ch & 3) * 8;
            uint32_t so = (uint32_t)(r * SMSTRIDE + cc) * 2;
            size_t  go = (size_t)r * K + cc;
            CP_ASYNC_16(ah + so, Agh + go);
            CP_ASYNC_16(al + so, Agl + go);
        }
        #pragma unroll
        for (int i = 0; i < 2; i++) {
            int ch = tid + i * 256;
            int r = ch >> 2, cc = (ch & 3) * 8;
            uint32_t so = (uint32_t)(r * SMSTRIDE + cc) * 2;
            size_t  go = (size_t)r * K + cc;
            CP_ASYNC_16(bh + so, Bgh + go);
            CP_ASYNC_16(bl + so, Bgl + go);
        }
    };

    load_stage(0, 0); CP_COMMIT();
    load_stage(1, 1); CP_COMMIT();

    for (int kt = 0; kt < KT; kt++) {
        const int buf = kt & 1;
        CP_WAIT_1();          // exactly 2 real groups pending -> stage kt resident
        __syncthreads();

        const uint32_t ah = smem_u32(As_hi + buf * A_STAGE);
        const uint32_t al = smem_u32(As_lo + buf * A_STAGE);
        const uint32_t bh = smem_u32(Bs_hi + buf * B_STAGE);
        const uint32_t bl = smem_u32(Bs_lo + buf * B_STAGE);

        #pragma unroll
        for (int ks = 0; ks < 2; ks++) {
            uint32_t af[MI][4], bfh[4][2], bfl[4][2];
            const int acol = ks * 16 + ((lane & 16) ? 8 : 0);
            const int bgrp = lane >> 3;
            // A-hi fragments
            #pragma unroll
            for (int mi = 0; mi < MI; mi++) {
                int row = wm + mi * 16 + (lane & 7) + ((lane & 8) ? 8 : 0);
                ldsm_x4(af[mi][0], af[mi][1], af[mi][2], af[mi][3],
                        ah + (uint32_t)(row * SMSTRIDE + acol) * 2);
            }
            // B-hi fragments
            #pragma unroll
            for (int njp = 0; njp < 2; njp++) {
                int row = wn + (njp * 2 + (bgrp >> 1)) * 8 + (lane & 7);
                int col = ks * 16 + (bgrp & 1) * 8;
                uint32_t r0, r1, r2, r3;
                ldsm_x4(r0, r1, r2, r3, bh + (uint32_t)(row * SMSTRIDE + col) * 2);
                bfh[njp*2][0] = r0;  bfh[njp*2][1] = r1;
                bfh[njp*2+1][0] = r2; bfh[njp*2+1][1] = r3;
            }
            #pragma unroll
            for (int mi = 0; mi < MI; mi++)
                #pragma unroll
                for (int nj = 0; nj < 4; nj++)
                    mma_bf16(acc[mi][nj], af[mi], bfh[nj]);     // hi * hi
            // B-lo fragments
            #pragma unroll
            for (int njp = 0; njp < 2; njp++) {
                int row = wn + (njp * 2 + (bgrp >> 1)) * 8 + (lane & 7);
                int col = ks * 16 + (bgrp & 1) * 8;
                uint32_t r0, r1, r2, r3;
                ldsm_x4(r0, r1, r2, r3, bl + (uint32_t)(row * SMSTRIDE + col) * 2);
                bfl[njp*2][0] = r0;  bfl[njp*2][1] = r1;
                bfl[njp*2+1][0] = r2; bfl[njp*2+1][1] = r3;
            }
            #pragma unroll
            for (int mi = 0; mi < MI; mi++)
                #pragma unroll
                for (int nj = 0; nj < 4; nj++)
                    mma_bf16(acc[mi][nj], af[mi], bfl[nj]);     // hi * lo
            // A-lo fragments (overwrite af)
            #pragma unroll
            for (int mi = 0; mi < MI; mi++) {
                int row = wm + mi * 16 + (lane & 7) + ((lane & 8) ? 8 : 0);
                ldsm_x4(af[mi][0], af[mi][1], af[mi][2], af[mi][3],
                        al + (uint32_t)(row * SMSTRIDE + acol) * 2);
            }
            #pragma unroll
            for (int mi = 0; mi < MI; mi++)
                #pragma unroll
                for (int nj = 0; nj < 4; nj++)
                    mma_bf16(acc[mi][nj], af[mi], bfh[nj]);     // lo * hi
        }

        __syncthreads();      // all reads of buf done before reload
        int nkt = kt + 2 < KT ? kt + 2 : KT - 1;   // clamp: real commit every iter
        load_stage(nkt, buf);
        CP_COMMIT();
    }

    #pragma unroll
    for (int nj = 0; nj < 4; nj++) {
        int gcol = bn * 128 + wn + nj * 8 + (lane & 3) * 2;
        float2 bv = *(const float2*)(bias + gcol);
        #pragma unroll
        for (int mi = 0; mi < MI; mi++) {
            int grow = bm * BM + wm + mi * 16 + (lane >> 2);
            float2 v0 = { acc[mi][nj][0] + bv.x, acc[mi][nj][1] + bv.y };
            float2 v1 = { acc[mi][nj][2] + bv.x, acc[mi][nj][3] + bv.y };
            *(float2*)(C + (size_t)grow * N + gcol)       = v0;
            *(float2*)(C + (size_t)(grow + 8) * N + gcol) = v1;
        }
    }
}

// ====================== RoPE + head split =====================================
__global__ void __launch_bounds__(384) rope_split_kernel() {
    int l = blockIdx.x;
    int t = threadIdx.x;
    int h = t >> 5;
    int i = t & 31;

    const float* row = g_qkv + (size_t)l * (3*DM);
    float invf = powf(10000.0f, -(float)i * (1.0f/32.0f));
    float ang = (float)l * invf;
    float s, c;
    sincosf(ang, &s, &c);

    int qo = h*HD + i;
    float q1 = row[qo],        q2 = row[qo + 32];
    float k1 = row[DM + qo],   k2 = row[DM + qo + 32];
    int o = (h*L + l)*HD + i;
    g_q[o]      = q1*c - q2*s;
    g_q[o + 32] = q1*s + q2*c;
    g_k[o]      = k1*c - k2*s;
    g_k[o + 32] = k1*s + k2*c;
    g_v[o]      = row[2*DM + qo];
    g_v[o + 32] = row[2*DM + qo + 32];
}

// ====================== sliding-window attention (TQ=32, 1024 thr) ============
__global__ void __launch_bounds__(1024) window_attn_kernel(const int* __restrict__ mask) {
    extern __shared__ float sm[];
    float* ks = sm;                        // WROWS * WSTRIDE
    float* qs = ks + WROWS * WSTRIDE;      // TQ * 64
    float* ws = qs + TQ * HD;              // TQ * 128
    int*   rv = (int*)(ws + TQ * WIN);     // WROWS

    int h  = blockIdx.x / (L / TQ);
    int qt = blockIdx.x % (L / TQ);
    int l0 = qt * TQ;
    int lo = l0 - 64;
    int tid = threadIdx.x;

    for (int idx = tid; idx < WROWS; idx += 1024) {
        int lr = lo + idx;
        rv[idx] = (lr >= 0 && lr < L) ? (mask[lr] != 0) : 0;
    }
    for (int idx = tid; idx < WROWS * HD; idx += 1024) {
        int r = idx >> 6, d = idx & 63;
        int lr = lo + r;
        bool val = (lr >= 0 && lr < L);
        ks[r*WSTRIDE + d] = val ? g_k[(h*L + (val ? lr : 0))*HD + d] : 0.0f;
    }
    for (int idx = tid; idx < TQ * HD; idx += 1024) {
        qs[idx] = g_q[(h*L + l0)*HD + idx];
    }
    __syncthreads();

    int wq   = tid >> 5;   // 0..31: query within tile
    int lane = tid & 31;
    int l = l0 + wq;

    const float4* qs4 = (const float4*)(qs + wq*HD);
    float sc[4];
    #pragma unroll
    for (int w4 = 0; w4 < 4; w4++) {
        int r = wq + lane + w4*32;
        const float4* ks4 = (const float4*)(ks + r*WSTRIDE);
        float s = 0.f;
        #pragma unroll
        for (int d4 = 0; d4 < 16; d4++) {
            float4 kk = ks4[d4], qq = qs4[d4];
            s += kk.x*qq.x + kk.y*qq.y + kk.z*qq.z + kk.w*qq.w;
        }
        sc[w4] = rv[r] ? s * SCALE : -1e30f;
    }

    float m = fmaxf(fmaxf(sc[0], sc[1]), fmaxf(sc[2], sc[3]));
    #pragma unroll
    for (int o = 16; o > 0; o >>= 1) m = fmaxf(m, __shfl_xor_sync(0xffffffffu, m, o));
    float e[4], sum = 0.f;
    #pragma unroll
    for (int w4 = 0; w4 < 4; w4++) { e[w4] = expf(sc[w4] - m); sum += e[w4]; }
    #pragma unroll
    for (int o = 16; o > 0; o >>= 1) sum += __shfl_xor_sync(0xffffffffu, sum, o);
    float inv = 1.0f / sum;
    #pragma unroll
    for (int w4 = 0; w4 < 4; w4++) ws[wq*WIN + lane + w4*32] = e[w4] * inv;
    __syncwarp();

    float2 a = {0.f, 0.f};
    const float* vbase = g_v + (size_t)h*L*HD + 2*lane;
    #pragma unroll 4
    for (int w = 0; w < WIN; w++) {
        float wt = ws[wq*WIN + w];
        int lr = lo + wq + w;
        lr = lr < 0 ? 0 : (lr > L-1 ? L-1 : lr);
        float2 v = *(const float2*)(vbase + (size_t)lr*HD);
        a.x += wt * v.x;
        a.y += wt * v.y;
    }
    __nv_bfloat16 hx = __float2bfloat16(a.x);
    __nv_bfloat16 hy = __float2bfloat16(a.y);
    __nv_bfloat162 hi2; hi2.x = hx; hi2.y = hy;
    __nv_bfloat162 lo2;
    lo2.x = __float2bfloat16(a.x - __bfloat162float(hx));
    lo2.y = __float2bfloat16(a.y - __bfloat162float(hy));
    size_t o = (size_t)l*DM + h*HD + 2*lane;
    *(__nv_bfloat162*)(g_Chi + o) = hi2;
    *(__nv_bfloat162*)(g_Clo + o) = lo2;
}

// ====================== CLS split-softmax ======================================
__global__ void __launch_bounds__(128) cls_part_kernel(const int* __restrict__ mask) {
    extern __shared__ float smc[];
    float* ksm = smc;
    float* q0  = ksm + CKEYS*65;
    float* ew  = q0 + HD;
    float* red = ew + CKEYS;

    int c = blockIdx.x, h = blockIdx.y;
    int tid = threadIdx.x;
    int base = c * CKEYS;

    if (tid < HD) q0[tid] = g_q[(size_t)(h*L)*HD + tid];
    for (int idx = tid; idx < CKEYS*HD; idx += 128) {
        int key = idx >> 6, d = idx & 63;
        ksm[key*65 + d] = g_k[(size_t)(h*L + base + key)*HD + d];
    }
    __syncthreads();

    float s = 0.f;
    #pragma unroll
    for (int d = 0; d < HD; d++) s += ksm[tid*65 + d] * q0[d];
    s = (mask[base + tid] != 0) ? s * SCALE : -1e30f;

    red[tid] = s; __syncthreads();
    for (int o = 64; o > 0; o >>= 1) {
        if (tid < o) red[tid] = fmaxf(red[tid], red[tid + o]);
        __syncthreads();
    }
    float m_c = red[0];
    __syncthreads();

    float e = expf(s - m_c);
    ew[tid] = e;
    red[tid] = e; __syncthreads();
    for (int o = 64; o > 0; o >>= 1) {
        if (tid < o) red[tid] += red[tid + o];
        __syncthreads();
    }
    float s_c = red[0];
    __syncthreads();

    int d = tid & 63, half = tid >> 6;
    const float* vb = g_v + (size_t)(h*L + base + half*64)*HD + d;
    float acc = 0.f;
    #pragma unroll 8
    for (int kk = 0; kk < 64; kk++)
        acc += ew[half*64 + kk] * vb[(size_t)kk*HD];
    red[tid] = acc; __syncthreads();
    if (tid < HD) {
        g_cls_o[(size_t)(h*NCHUNK + c)*HD + tid] = red[tid] + red[HD + tid];
        if (tid == 0) { g_cls_m[h*NCHUNK + c] = m_c; g_cls_s[h*NCHUNK + c] = s_c; }
    }
}

__global__ void __launch_bounds__(768) cls_combine_kernel() {
    int tid = threadIdx.x;
    int h = tid >> 6, d = tid & 63;
    float m = -1e30f;
    #pragma unroll
    for (int c = 0; c < NCHUNK; c++) m = fmaxf(m, g_cls_m[h*NCHUNK + c]);
    float den = 0.f, num = 0.f;
    #pragma unroll
    for (int c = 0; c < NCHUNK; c++) {
        float w = expf(g_cls_m[h*NCHUNK + c] - m);
        den += g_cls_s[h*NCHUNK + c] * w;
        num += g_cls_o[(size_t)(h*NCHUNK + c)*HD + d] * w;
    }
    float o = num / den;
    __nv_bfloat16 hv = __float2bfloat16(o);
    g_Chi[h*HD + d] = hv;
    g_Clo[h*HD + d] = __float2bfloat16(o - __bfloat162float(hv));
}

// ====================== launch =================================================
extern "C" void kernel_launch(void* const* d_in, const int* in_sizes, int n_in,
                              void* d_out, int out_size) {
    (void)in_sizes; (void)n_in; (void)out_size;
    const float* emb   = (const float*)d_in[0];
    const int*   mask  = (const int*)  d_in[1];
    const float* W_qkv = (const float*)d_in[2];
    const float* b_qkv = (const float*)d_in[3];
    const float* W_o   = (const float*)d_in[4];
    const float* b_o   = (const float*)d_in[5];
    float* out = (float*)d_out;

    float* p_qkv;
    cudaGetSymbolAddress((void**)&p_qkv,  g_qkv);
    __nv_bfloat16 *p_Ahi, *p_Alo, *p_Wqhi, *p_Wqlo, *p_Wohi, *p_Wolo, *p_Chi, *p_Clo;
    cudaGetSymbolAddress((void**)&p_Ahi,  g_Ahi);
    cudaGetSymbolAddress((void**)&p_Alo,  g_Alo);
    cudaGetSymbolAddress((void**)&p_Wqhi, g_Wqhi);
    cudaGetSymbolAddress((void**)&p_Wqlo, g_Wqlo);
    cudaGetSymbolAddress((void**)&p_Wohi, g_Wohi);
    cudaGetSymbolAddress((void**)&p_Wolo, g_Wolo);
    cudaGetSymbolAddress((void**)&p_Chi,  g_Chi);
    cudaGetSymbolAddress((void**)&p_Clo,  g_Clo);

    constexpr int GSMEM128 = GNST * (2*128 + 2*128) * SMSTRIDE * 2;  // 81920 B
    constexpr int GSMEM64  = GNST * (2*64  + 2*128) * SMSTRIDE * 2;  // 61440 B
    cudaFuncSetAttribute(gemm_bf16_mma<128>, cudaFuncAttributeMaxDynamicSharedMemorySize, GSMEM128);
    cudaFuncSetAttribute(gemm_bf16_mma<64>,  cudaFuncAttributeMaxDynamicSharedMemorySize, GSMEM64);

    // 0. operand prep
    split_bf16<<<(L*DM + 255)/256, 256>>>(emb, p_Ahi, p_Alo, L*DM);
    transpose_split<<<dim3((3*DM)/32, DM/32), dim3(32,8)>>>(W_qkv, p_Wqhi, p_Wqlo, DM, 3*DM);
    transpose_split<<<dim3(DM/32, DM/32), dim3(32,8)>>>(W_o, p_Wohi, p_Wolo, DM, DM);

    // 1. QKV GEMM: [2048,768] x [768,2304]
    gemm_bf16_mma<128><<<dim3((3*DM)/128, L/128), 256, GSMEM128>>>(
        p_Ahi, p_Alo, p_Wqhi, p_Wqlo, b_qkv, p_qkv, 3*DM, DM);

    // 2. RoPE + head split
    rope_split_kernel<<<L, 384>>>();

    // 3. sliding-window attention (writes g_Chi/g_Clo directly)
    constexpr int SMEM_WIN = (WROWS*WSTRIDE + TQ*HD + TQ*WIN) * 4 + WROWS * 4;
    cudaFuncSetAttribute(window_attn_kernel,
                         cudaFuncAttributeMaxDynamicSharedMemorySize, SMEM_WIN);
    window_attn_kernel<<<H * (L/TQ), 1024, SMEM_WIN>>>(mask);

    // 4. CLS row
    constexpr int SMEM_CLS = (CKEYS*65 + HD + CKEYS + 128) * 4;
    cudaFuncSetAttribute(cls_part_kernel,
                         cudaFuncAttributeMaxDynamicSharedMemorySize, SMEM_CLS);
    cls_part_kernel<<<dim3(NCHUNK, H), 128, SMEM_CLS>>>(mask);
    cls_combine_kernel<<<1, 768>>>();

    // 5. output projection: [2048,768] x [768,768]
    gemm_bf16_mma<64><<<dim3(DM/128, L/64), 256, GSMEM64>>>(
        p_Chi, p_Clo, p_Wohi, p_Wolo, b_o, out, DM, DM);
}

// round 9
// speedup vs baseline: 1.9444x; 1.0413x over previous
#include <cuda_runtime.h>
#include <cuda_bf16.h>
#include <math.h>
#include <stdint.h>

#define L    2048
#define DM   768
#define H    12
#define HD   64
#define WIN  128
#define TQ   32
#define WROWS 160    // 32+127 = 159 rows used
#define NCHUNK 16
#define CKEYS  128
#define WSTRIDE 68   // floats per K row in window smem (64 data + 4 pad)

static constexpr float SCALE = 0.03608439182435161f;  // 1/sqrt(768)

// ====================== scratch ================================================
__device__ float g_qkv[L * 3 * DM];
__device__ float g_q[H * L * HD];
__device__ float g_k[H * L * HD];
__device__ float g_v[H * L * HD];
__device__ float g_cls_m[H * NCHUNK];
__device__ float g_cls_s[H * NCHUNK];
__device__ float g_cls_o[H * NCHUNK * HD];

__device__ __nv_bfloat16 g_Ahi[L * DM],  g_Alo[L * DM];
__device__ __nv_bfloat16 g_Wqhi[3*DM*DM], g_Wqlo[3*DM*DM];
__device__ __nv_bfloat16 g_Wohi[DM*DM],  g_Wolo[DM*DM];
__device__ __nv_bfloat16 g_Chi[L * DM],  g_Clo[L * DM];

// ====================== prep kernels ==========================================
__global__ void __launch_bounds__(256) split_bf16(const float* __restrict__ x,
        __nv_bfloat16* __restrict__ hi, __nv_bfloat16* __restrict__ lo, int n) {
    int i = blockIdx.x * 256 + threadIdx.x;
    if (i < n) {
        float v = x[i];
        __nv_bfloat16 h = __float2bfloat16(v);
        hi[i] = h;
        lo[i] = __float2bfloat16(v - __bfloat162float(h));
    }
}

__global__ void __launch_bounds__(256) transpose_split(const float* __restrict__ W,
        __nv_bfloat16* __restrict__ Thi, __nv_bfloat16* __restrict__ Tlo, int K, int N) {
    __shared__ float t[32][33];
    int n0 = blockIdx.x * 32, k0 = blockIdx.y * 32;
    int tx = threadIdx.x, ty = threadIdx.y;
    #pragma unroll
    for (int i = ty; i < 32; i += 8)
        t[i][tx] = W[(size_t)(k0 + i) * N + n0 + tx];
    __syncthreads();
    #pragma unroll
    for (int i = ty; i < 32; i += 8) {
        float v = t[tx][i];
        __nv_bfloat16 h = __float2bfloat16(v);
        size_t o = (size_t)(n0 + i) * K + k0 + tx;
        Thi[o] = h;
        Tlo[o] = __float2bfloat16(v - __bfloat162float(h));
    }
}

// ====================== mma.sync helpers ======================================
__device__ __forceinline__ uint32_t smem_u32(const void* p) {
    uint32_t a;
    asm("{ .reg .u64 t; cvta.to.shared.u64 t, %1; cvt.u32.u64 %0, t; }" : "=r"(a) : "l"(p));
    return a;
}
__device__ __forceinline__ void ldsm_x4(uint32_t& r0, uint32_t& r1, uint32_t& r2, uint32_t& r3,
                                        uint32_t addr) {
    asm volatile("ldmatrix.sync.aligned.m8n8.x4.shared.b16 {%0,%1,%2,%3}, [%4];"
                 : "=r"(r0), "=r"(r1), "=r"(r2), "=r"(r3) : "r"(addr));
}
__device__ __forceinline__ void mma_bf16(float* d, const uint32_t* a, const uint32_t* b) {
    asm volatile("mma.sync.aligned.m16n8k16.row.col.f32.bf16.bf16.f32 "
                 "{%0,%1,%2,%3}, {%4,%5,%6,%7}, {%8,%9}, {%0,%1,%2,%3};"
                 : "+f"(d[0]), "+f"(d[1]), "+f"(d[2]), "+f"(d[3])
                 : "r"(a[0]), "r"(a[1]), "r"(a[2]), "r"(a[3]), "r"(b[0]), "r"(b[1]));
}
#define CP_ASYNC_16(dst, src) \
    asm volatile("cp.async.cg.shared.global [%0], [%1], 16;" :: "r"(dst), "l"(src))
#define CP_COMMIT() asm volatile("cp.async.commit_group;" ::: "memory")
#define CP_WAIT_1() asm volatile("cp.async.wait_group 1;" ::: "memory")

// ====================== HMMA bf16 merged 3-combo GEMM =========================
#define SMSTRIDE 40
#define GNST 2

template<int BM>
__global__ void __launch_bounds__(256, 2)
gemm_bf16_mma(const __nv_bfloat16* __restrict__ Ahi, const __nv_bfloat16* __restrict__ Alo,
              const __nv_bfloat16* __restrict__ Bhi, const __nv_bfloat16* __restrict__ Blo,
              const float* __restrict__ bias, float* __restrict__ C,
              int N, int K) {
    constexpr int MI  = BM / 32;
    constexpr int ACH = BM / 64;
    constexpr int A_STAGE = BM * SMSTRIDE;
    constexpr int B_STAGE = 128 * SMSTRIDE;

    extern __shared__ __align__(16) __nv_bfloat16 dsm[];
    __nv_bfloat16* As_hi = dsm;
    __nv_bfloat16* As_lo = dsm + GNST * A_STAGE;
    __nv_bfloat16* Bs_hi = dsm + 2 * GNST * A_STAGE;
    __nv_bfloat16* Bs_lo = dsm + 2 * GNST * A_STAGE + GNST * B_STAGE;

    const int tid  = threadIdx.x;
    const int wid  = tid >> 5;
    const int lane = tid & 31;
    const int bn = blockIdx.x, bm = blockIdx.y;
    const int wm = (wid >> 2) * (BM / 2);
    const int wn = (wid & 3) * 32;

    const int KT = K >> 5;

    float acc[MI][4][4] = {};

    auto load_stage = [&](int kt, int buf) {
        const __nv_bfloat16* Agh = Ahi + (size_t)bm * BM * K + kt * 32;
        const __nv_bfloat16* Agl = Alo + (size_t)bm * BM * K + kt * 32;
        const __nv_bfloat16* Bgh = Bhi + (size_t)bn * 128 * K + kt * 32;
        const __nv_bfloat16* Bgl = Blo + (size_t)bn * 128 * K + kt * 32;
        uint32_t ah = smem_u32(As_hi + buf * A_STAGE);
        uint32_t al = smem_u32(As_lo + buf * A_STAGE);
        uint32_t bh = smem_u32(Bs_hi + buf * B_STAGE);
        uint32_t bl = smem_u32(Bs_lo + buf * B_STAGE);
        #pragma unroll
        for (int i = 0; i < ACH; i++) {
            int ch = tid + i * 256;
            int r = ch >> 2, cc = (ch & 3) * 8;
            uint32_t so = (uint32_t)(r * SMSTRIDE + cc) * 2;
            size_t  go = (size_t)r * K + cc;
            CP_ASYNC_16(ah + so, Agh + go);
            CP_ASYNC_16(al + so, Agl + go);
        }
        #pragma unroll
        for (int i = 0; i < 2; i++) {
            int ch = tid + i * 256;
            int r = ch >> 2, cc = (ch & 3) * 8;
            uint32_t so = (uint32_t)(r * SMSTRIDE + cc) * 2;
            size_t  go = (size_t)r * K + cc;
            CP_ASYNC_16(bh + so, Bgh + go);
            CP_ASYNC_16(bl + so, Bgl + go);
        }
    };

    load_stage(0, 0); CP_COMMIT();
    load_stage(1, 1); CP_COMMIT();

    for (int kt = 0; kt < KT; kt++) {
        const int buf = kt & 1;
        CP_WAIT_1();
        __syncthreads();

        const uint32_t ah = smem_u32(As_hi + buf * A_STAGE);
        const uint32_t al = smem_u32(As_lo + buf * A_STAGE);
        const uint32_t bh = smem_u32(Bs_hi + buf * B_STAGE);
        const uint32_t bl = smem_u32(Bs_lo + buf * B_STAGE);

        #pragma unroll
        for (int ks = 0; ks < 2; ks++) {
            uint32_t af[MI][4], bfh[4][2], bfl[4][2];
            const int acol = ks * 16 + ((lane & 16) ? 8 : 0);
            const int bgrp = lane >> 3;
            #pragma unroll
            for (int mi = 0; mi < MI; mi++) {
                int row = wm + mi * 16 + (lane & 7) + ((lane & 8) ? 8 : 0);
                ldsm_x4(af[mi][0], af[mi][1], af[mi][2], af[mi][3],
                        ah + (uint32_t)(row * SMSTRIDE + acol) * 2);
            }
            #pragma unroll
            for (int njp = 0; njp < 2; njp++) {
                int row = wn + (njp * 2 + (bgrp >> 1)) * 8 + (lane & 7);
                int col = ks * 16 + (bgrp & 1) * 8;
                uint32_t r0, r1, r2, r3;
                ldsm_x4(r0, r1, r2, r3, bh + (uint32_t)(row * SMSTRIDE + col) * 2);
                bfh[njp*2][0] = r0;  bfh[njp*2][1] = r1;
                bfh[njp*2+1][0] = r2; bfh[njp*2+1][1] = r3;
            }
            #pragma unroll
            for (int mi = 0; mi < MI; mi++)
                #pragma unroll
                for (int nj = 0; nj < 4; nj++)
                    mma_bf16(acc[mi][nj], af[mi], bfh[nj]);
            #pragma unroll
            for (int njp = 0; njp < 2; njp++) {
                int row = wn + (njp * 2 + (bgrp >> 1)) * 8 + (lane & 7);
                int col = ks * 16 + (bgrp & 1) * 8;
                uint32_t r0, r1, r2, r3;
                ldsm_x4(r0, r1, r2, r3, bl + (uint32_t)(row * SMSTRIDE + col) * 2);
                bfl[njp*2][0] = r0;  bfl[njp*2][1] = r1;
                bfl[njp*2+1][0] = r2; bfl[njp*2+1][1] = r3;
            }
            #pragma unroll
            for (int mi = 0; mi < MI; mi++)
                #pragma unroll
                for (int nj = 0; nj < 4; nj++)
                    mma_bf16(acc[mi][nj], af[mi], bfl[nj]);
            #pragma unroll
            for (int mi = 0; mi < MI; mi++) {
                int row = wm + mi * 16 + (lane & 7) + ((lane & 8) ? 8 : 0);
                ldsm_x4(af[mi][0], af[mi][1], af[mi][2], af[mi][3],
                        al + (uint32_t)(row * SMSTRIDE + acol) * 2);
            }
            #pragma unroll
            for (int mi = 0; mi < MI; mi++)
                #pragma unroll
                for (int nj = 0; nj < 4; nj++)
                    mma_bf16(acc[mi][nj], af[mi], bfh[nj]);
        }

        __syncthreads();
        int nkt = kt + 2 < KT ? kt + 2 : KT - 1;
        load_stage(nkt, buf);
        CP_COMMIT();
    }

    #pragma unroll
    for (int nj = 0; nj < 4; nj++) {
        int gcol = bn * 128 + wn + nj * 8 + (lane & 3) * 2;
        float2 bv = *(const float2*)(bias + gcol);
        #pragma unroll
        for (int mi = 0; mi < MI; mi++) {
            int grow = bm * BM + wm + mi * 16 + (lane >> 2);
            float2 v0 = { acc[mi][nj][0] + bv.x, acc[mi][nj][1] + bv.y };
            float2 v1 = { acc[mi][nj][2] + bv.x, acc[mi][nj][3] + bv.y };
            *(float2*)(C + (size_t)grow * N + gcol)       = v0;
            *(float2*)(C + (size_t)(grow + 8) * N + gcol) = v1;
        }
    }
}

// ====================== RoPE + head split =====================================
__global__ void __launch_bounds__(384) rope_split_kernel() {
    int l = blockIdx.x;
    int t = threadIdx.x;
    int h = t >> 5;
    int i = t & 31;

    const float* row = g_qkv + (size_t)l * (3*DM);
    float invf = powf(10000.0f, -(float)i * (1.0f/32.0f));
    float ang = (float)l * invf;
    float s, c;
    sincosf(ang, &s, &c);

    int qo = h*HD + i;
    float q1 = row[qo],        q2 = row[qo + 32];
    float k1 = row[DM + qo],   k2 = row[DM + qo + 32];
    int o = (h*L + l)*HD + i;
    g_q[o]      = q1*c - q2*s;
    g_q[o + 32] = q1*s + q2*c;
    g_k[o]      = k1*c - k2*s;
    g_k[o + 32] = k1*s + k2*c;
    g_v[o]      = row[2*DM + qo];
    g_v[o + 32] = row[2*DM + qo + 32];
}

// ====================== sliding-window attention (TQ=32) ======================
// Scores: d4-outer loop (Q float4 reused across 4 window rows).
// V: paired-lane float4 gather (16 lanes x float4 chunks, 2 w-positions/iter).
__global__ void __launch_bounds__(1024) window_attn_kernel(const int* __restrict__ mask) {
    extern __shared__ float sm[];
    float* ks = sm;                        // WROWS * WSTRIDE
    float* qs = ks + WROWS * WSTRIDE;      // TQ * 64
    float* ws = qs + TQ * HD;              // TQ * 128
    int*   rv = (int*)(ws + TQ * WIN);     // WROWS

    int h  = blockIdx.x / (L / TQ);
    int qt = blockIdx.x % (L / TQ);
    int l0 = qt * TQ;
    int lo = l0 - 64;
    int tid = threadIdx.x;

    for (int idx = tid; idx < WROWS; idx += 1024) {
        int lr = lo + idx;
        rv[idx] = (lr >= 0 && lr < L) ? (mask[lr] != 0) : 0;
    }
    for (int idx = tid; idx < WROWS * HD; idx += 1024) {
        int r = idx >> 6, d = idx & 63;
        int lr = lo + r;
        bool val = (lr >= 0 && lr < L);
        ks[r*WSTRIDE + d] = val ? g_k[(h*L + (val ? lr : 0))*HD + d] : 0.0f;
    }
    for (int idx = tid; idx < TQ * HD; idx += 1024) {
        qs[idx] = g_q[(h*L + l0)*HD + idx];
    }
    __syncthreads();

    int wq   = tid >> 5;   // query within tile
    int lane = tid & 31;
    int l = l0 + wq;

    // ---- scores: d4 outer, 4 window rows inner ----
    const float4* qs4 = (const float4*)(qs + wq*HD);
    const float4* kp0 = (const float4*)(ks + (wq + lane      )*WSTRIDE);
    const float4* kp1 = (const float4*)(ks + (wq + lane +  32)*WSTRIDE);
    const float4* kp2 = (const float4*)(ks + (wq + lane +  64)*WSTRIDE);
    const float4* kp3 = (const float4*)(ks + (wq + lane +  96)*WSTRIDE);
    float sc[4] = {0.f, 0.f, 0.f, 0.f};
    #pragma unroll
    for (int d4 = 0; d4 < 16; d4++) {
        float4 qq = qs4[d4];
        float4 k0 = kp0[d4], k1 = kp1[d4], k2 = kp2[d4], k3 = kp3[d4];
        sc[0] += k0.x*qq.x + k0.y*qq.y + k0.z*qq.z + k0.w*qq.w;
        sc[1] += k1.x*qq.x + k1.y*qq.y + k1.z*qq.z + k1.w*qq.w;
        sc[2] += k2.x*qq.x + k2.y*qq.y + k2.z*qq.z + k2.w*qq.w;
        sc[3] += k3.x*qq.x + k3.y*qq.y + k3.z*qq.z + k3.w*qq.w;
    }
    #pragma unroll
    for (int w4 = 0; w4 < 4; w4++)
        sc[w4] = rv[wq + lane + w4*32] ? sc[w4] * SCALE : -1e30f;

    float m = fmaxf(fmaxf(sc[0], sc[1]), fmaxf(sc[2], sc[3]));
    #pragma unroll
    for (int o = 16; o > 0; o >>= 1) m = fmaxf(m, __shfl_xor_sync(0xffffffffu, m, o));
    float e[4], sum = 0.f;
    #pragma unroll
    for (int w4 = 0; w4 < 4; w4++) { e[w4] = expf(sc[w4] - m); sum += e[w4]; }
    #pragma unroll
    for (int o = 16; o > 0; o >>= 1) sum += __shfl_xor_sync(0xffffffffu, sum, o);
    float inv = 1.0f / sum;
    #pragma unroll
    for (int w4 = 0; w4 < 4; w4++) ws[wq*WIN + lane + w4*32] = e[w4] * inv;
    __syncwarp();

    // ---- output: 16 lanes own float4 chunks, 2 window positions per iter ----
    const int wpair = lane >> 4;        // 0 or 1
    const int chunk = lane & 15;        // float4 chunk of HD
    float4 a4 = {0.f, 0.f, 0.f, 0.f};
    const float* vbase = g_v + (size_t)h*L*HD + chunk*4;
    #pragma unroll 4
    for (int w = 0; w < WIN; w += 2) {
        float wt = ws[wq*WIN + w + wpair];
        int lr = lo + wq + w + wpair;
        lr = lr < 0 ? 0 : (lr > L-1 ? L-1 : lr);
        float4 v = *(const float4*)(vbase + (size_t)lr*HD);
        a4.x += wt * v.x;
        a4.y += wt * v.y;
        a4.z += wt * v.z;
        a4.w += wt * v.w;
    }
    a4.x += __shfl_xor_sync(0xffffffffu, a4.x, 16);
    a4.y += __shfl_xor_sync(0xffffffffu, a4.y, 16);
    a4.z += __shfl_xor_sync(0xffffffffu, a4.z, 16);
    a4.w += __shfl_xor_sync(0xffffffffu, a4.w, 16);

    if (wpair == 0) {
        __nv_bfloat16 h0 = __float2bfloat16(a4.x);
        __nv_bfloat16 h1 = __float2bfloat16(a4.y);
        __nv_bfloat16 h2 = __float2bfloat16(a4.z);
        __nv_bfloat16 h3 = __float2bfloat16(a4.w);
        __nv_bfloat162 hiA; hiA.x = h0; hiA.y = h1;
        __nv_bfloat162 hiB; hiB.x = h2; hiB.y = h3;
        __nv_bfloat162 loA, loB;
        loA.x = __float2bfloat16(a4.x - __bfloat162float(h0));
        loA.y = __float2bfloat16(a4.y - __bfloat162float(h1));
        loB.x = __float2bfloat16(a4.z - __bfloat162float(h2));
        loB.y = __float2bfloat16(a4.w - __bfloat162float(h3));
        size_t o = (size_t)l*DM + h*HD + chunk*4;
        *(__nv_bfloat162*)(g_Chi + o)     = hiA;
        *(__nv_bfloat162*)(g_Chi + o + 2) = hiB;
        *(__nv_bfloat162*)(g_Clo + o)     = loA;
        *(__nv_bfloat162*)(g_Clo + o + 2) = loB;
    }
}

// ====================== CLS split-softmax ======================================
__global__ void __launch_bounds__(128) cls_part_kernel(const int* __restrict__ mask) {
    extern __shared__ float smc[];
    float* ksm = smc;
    float* q0  = ksm + CKEYS*65;
    float* ew  = q0 + HD;
    float* red = ew + CKEYS;

    int c = blockIdx.x, h = blockIdx.y;
    int tid = threadIdx.x;
    int base = c * CKEYS;

    if (tid < HD) q0[tid] = g_q[(size_t)(h*L)*HD + tid];
    for (int idx = tid; idx < CKEYS*HD; idx += 128) {
        int key = idx >> 6, d = idx & 63;
        ksm[key*65 + d] = g_k[(size_t)(h*L + base + key)*HD + d];
    }
    __syncthreads();

    float s = 0.f;
    #pragma unroll
    for (int d = 0; d < HD; d++) s += ksm[tid*65 + d] * q0[d];
    s = (mask[base + tid] != 0) ? s * SCALE : -1e30f;

    red[tid] = s; __syncthreads();
    for (int o = 64; o > 0; o >>= 1) {
        if (tid < o) red[tid] = fmaxf(red[tid], red[tid + o]);
        __syncthreads();
    }
    float m_c = red[0];
    __syncthreads();

    float e = expf(s - m_c);
    ew[tid] = e;
    red[tid] = e; __syncthreads();
    for (int o = 64; o > 0; o >>= 1) {
        if (tid < o) red[tid] += red[tid + o];
        __syncthreads();
    }
    float s_c = red[0];
    __syncthreads();

    int d = tid & 63, half = tid >> 6;
    const float* vb = g_v + (size_t)(h*L + base + half*64)*HD + d;
    float acc = 0.f;
    #pragma unroll 8
    for (int kk = 0; kk < 64; kk++)
        acc += ew[half*64 + kk] * vb[(size_t)kk*HD];
    red[tid] = acc; __syncthreads();
    if (tid < HD) {
        g_cls_o[(size_t)(h*NCHUNK + c)*HD + tid] = red[tid] + red[HD + tid];
        if (tid == 0) { g_cls_m[h*NCHUNK + c] = m_c; g_cls_s[h*NCHUNK + c] = s_c; }
    }
}

__global__ void __launch_bounds__(768) cls_combine_kernel() {
    int tid = threadIdx.x;
    int h = tid >> 6, d = tid & 63;
    float m = -1e30f;
    #pragma unroll
    for (int c = 0; c < NCHUNK; c++) m = fmaxf(m, g_cls_m[h*NCHUNK + c]);
    float den = 0.f, num = 0.f;
    #pragma unroll
    for (int c = 0; c < NCHUNK; c++) {
        float w = expf(g_cls_m[h*NCHUNK + c] - m);
        den += g_cls_s[h*NCHUNK + c] * w;
        num += g_cls_o[(size_t)(h*NCHUNK + c)*HD + d] * w;
    }
    float o = num / den;
    __nv_bfloat16 hv = __float2bfloat16(o);
    g_Chi[h*HD + d] = hv;
    g_Clo[h*HD + d] = __float2bfloat16(o - __bfloat162float(hv));
}

// ====================== launch =================================================
extern "C" void kernel_launch(void* const* d_in, const int* in_sizes, int n_in,
                              void* d_out, int out_size) {
    (void)in_sizes; (void)n_in; (void)out_size;
    const float* emb   = (const float*)d_in[0];
    const int*   mask  = (const int*)  d_in[1];
    const float* W_qkv = (const float*)d_in[2];
    const float* b_qkv = (const float*)d_in[3];
    const float* W_o   = (const float*)d_in[4];
    const float* b_o   = (const float*)d_in[5];
    float* out = (float*)d_out;

    float* p_qkv;
    cudaGetSymbolAddress((void**)&p_qkv,  g_qkv);
    __nv_bfloat16 *p_Ahi, *p_Alo, *p_Wqhi, *p_Wqlo, *p_Wohi, *p_Wolo, *p_Chi, *p_Clo;
    cudaGetSymbolAddress((void**)&p_Ahi,  g_Ahi);
    cudaGetSymbolAddress((void**)&p_Alo,  g_Alo);
    cudaGetSymbolAddress((void**)&p_Wqhi, g_Wqhi);
    cudaGetSymbolAddress((void**)&p_Wqlo, g_Wqlo);
    cudaGetSymbolAddress((void**)&p_Wohi, g_Wohi);
    cudaGetSymbolAddress((void**)&p_Wolo, g_Wolo);
    cudaGetSymbolAddress((void**)&p_Chi,  g_Chi);
    cudaGetSymbolAddress((void**)&p_Clo,  g_Clo);

    constexpr int GSMEM128 = GNST * (2*128 + 2*128) * SMSTRIDE * 2;  // 81920 B
    constexpr int GSMEM64  = GNST * (2*64  + 2*128) * SMSTRIDE * 2;  // 61440 B
    cudaFuncSetAttribute(gemm_bf16_mma<128>, cudaFuncAttributeMaxDynamicSharedMemorySize, GSMEM128);
    cudaFuncSetAttribute(gemm_bf16_mma<64>,  cudaFuncAttributeMaxDynamicSharedMemorySize, GSMEM64);

    // 0. operand prep
    split_bf16<<<(L*DM + 255)/256, 256>>>(emb, p_Ahi, p_Alo, L*DM);
    transpose_split<<<dim3((3*DM)/32, DM/32), dim3(32,8)>>>(W_qkv, p_Wqhi, p_Wqlo, DM, 3*DM);
    transpose_split<<<dim3(DM/32, DM/32), dim3(32,8)>>>(W_o, p_Wohi, p_Wolo, DM, DM);

    // 1. QKV GEMM: [2048,768] x [768,2304]
    gemm_bf16_mma<128><<<dim3((3*DM)/128, L/128), 256, GSMEM128>>>(
        p_Ahi, p_Alo, p_Wqhi, p_Wqlo, b_qkv, p_qkv, 3*DM, DM);

    // 2. RoPE + head split
    rope_split_kernel<<<L, 384>>>();

    // 3. sliding-window attention (writes g_Chi/g_Clo directly)
    constexpr int SMEM_WIN = (WROWS*WSTRIDE + TQ*HD + TQ*WIN) * 4 + WROWS * 4;
    cudaFuncSetAttribute(window_attn_kernel,
                         cudaFuncAttributeMaxDynamicSharedMemorySize, SMEM_WIN);
    window_attn_kernel<<<H * (L/TQ), 1024, SMEM_WIN>>>(mask);

    // 4. CLS row
    constexpr int SMEM_CLS = (CKEYS*65 + HD + CKEYS + 128) * 4;
    cudaFuncSetAttribute(cls_part_kernel,
                         cudaFuncAttributeMaxDynamicSharedMemorySize, SMEM_CLS);
    cls_part_kernel<<<dim3(NCHUNK, H), 128, SMEM_CLS>>>(mask);
    cls_combine_kernel<<<1, 768>>>();

    // 5. output projection: [2048,768] x [768,768]
    gemm_bf16_mma<64><<<dim3(DM/128, L/64), 256, GSMEM64>>>(
        p_Chi, p_Clo, p_Wohi, p_Wolo, b_o, out, DM, DM);
}

// round 10
// speedup vs baseline: 2.0387x; 1.0485x over previous
#include <cuda_runtime.h>
#include <cuda_bf16.h>
#include <math.h>
#include <stdint.h>

#define L    2048
#define DM   768
#define H    12
#define HD   64
#define WIN  128
#define TQ   32
#define WROWS 160    // 32+127 = 159 rows used
#define NCHUNK 16
#define CKEYS  128
#define WSTRIDE 68   // floats per K row in window smem (64 data + 4 pad)

static constexpr float SCALE = 0.03608439182435161f;  // 1/sqrt(768)

// ====================== scratch ================================================
__device__ float g_qkv[L * 3 * DM];
__device__ float g_q[H * L * HD];
__device__ float g_k[H * L * HD];
__device__ float g_v[H * L * HD];
__device__ float g_cls_m[H * NCHUNK];
__device__ float g_cls_s[H * NCHUNK];
__device__ float g_cls_o[H * NCHUNK * HD];

__device__ __nv_bfloat16 g_Ahi[L * DM],  g_Alo[L * DM];
__device__ __nv_bfloat16 g_Wqhi[3*DM*DM], g_Wqlo[3*DM*DM];
__device__ __nv_bfloat16 g_Wohi[DM*DM],  g_Wolo[DM*DM];
__device__ __nv_bfloat16 g_Chi[L * DM],  g_Clo[L * DM];

// ====================== prep kernels ==========================================
__global__ void __launch_bounds__(256) split_bf16(const float* __restrict__ x,
        __nv_bfloat16* __restrict__ hi, __nv_bfloat16* __restrict__ lo, int n) {
    int i = blockIdx.x * 256 + threadIdx.x;
    if (i < n) {
        float v = x[i];
        __nv_bfloat16 h = __float2bfloat16(v);
        hi[i] = h;
        lo[i] = __float2bfloat16(v - __bfloat162float(h));
    }
}

__global__ void __launch_bounds__(256) transpose_split(const float* __restrict__ W,
        __nv_bfloat16* __restrict__ Thi, __nv_bfloat16* __restrict__ Tlo, int K, int N) {
    __shared__ float t[32][33];
    int n0 = blockIdx.x * 32, k0 = blockIdx.y * 32;
    int tx = threadIdx.x, ty = threadIdx.y;
    #pragma unroll
    for (int i = ty; i < 32; i += 8)
        t[i][tx] = W[(size_t)(k0 + i) * N + n0 + tx];
    __syncthreads();
    #pragma unroll
    for (int i = ty; i < 32; i += 8) {
        float v = t[tx][i];
        __nv_bfloat16 h = __float2bfloat16(v);
        size_t o = (size_t)(n0 + i) * K + k0 + tx;
        Thi[o] = h;
        Tlo[o] = __float2bfloat16(v - __bfloat162float(h));
    }
}

// ====================== mma.sync helpers ======================================
__device__ __forceinline__ uint32_t smem_u32(const void* p) {
    uint32_t a;
    asm("{ .reg .u64 t; cvta.to.shared.u64 t, %1; cvt.u32.u64 %0, t; }" : "=r"(a) : "l"(p));
    return a;
}
__device__ __forceinline__ void ldsm_x4(uint32_t& r0, uint32_t& r1, uint32_t& r2, uint32_t& r3,
                                        uint32_t addr) {
    asm volatile("ldmatrix.sync.aligned.m8n8.x4.shared.b16 {%0,%1,%2,%3}, [%4];"
                 : "=r"(r0), "=r"(r1), "=r"(r2), "=r"(r3) : "r"(addr));
}
__device__ __forceinline__ void mma_bf16(float* d, const uint32_t* a, const uint32_t* b) {
    asm volatile("mma.sync.aligned.m16n8k16.row.col.f32.bf16.bf16.f32 "
                 "{%0,%1,%2,%3}, {%4,%5,%6,%7}, {%8,%9}, {%0,%1,%2,%3};"
                 : "+f"(d[0]), "+f"(d[1]), "+f"(d[2]), "+f"(d[3])
                 : "r"(a[0]), "r"(a[1]), "r"(a[2]), "r"(a[3]), "r"(b[0]), "r"(b[1]));
}
#define CP_ASYNC_16(dst, src) \
    asm volatile("cp.async.cg.shared.global [%0], [%1], 16;" :: "r"(dst), "l"(src))
#define CP_COMMIT() asm volatile("cp.async.commit_group;" ::: "memory")
#define CP_WAIT_1() asm volatile("cp.async.wait_group 1;" ::: "memory")

// ====================== HMMA bf16 merged 3-combo GEMM =========================
#define SMSTRIDE 40
#define GNST 2

template<int BM>
__global__ void __launch_bounds__(256, 2)
gemm_bf16_mma(const __nv_bfloat16* __restrict__ Ahi, const __nv_bfloat16* __restrict__ Alo,
              const __nv_bfloat16* __restrict__ Bhi, const __nv_bfloat16* __restrict__ Blo,
              const float* __restrict__ bias, float* __restrict__ C,
              int N, int K) {
    constexpr int MI  = BM / 32;
    constexpr int ACH = BM / 64;
    constexpr int A_STAGE = BM * SMSTRIDE;
    constexpr int B_STAGE = 128 * SMSTRIDE;

    extern __shared__ __align__(16) __nv_bfloat16 dsm[];
    __nv_bfloat16* As_hi = dsm;
    __nv_bfloat16* As_lo = dsm + GNST * A_STAGE;
    __nv_bfloat16* Bs_hi = dsm + 2 * GNST * A_STAGE;
    __nv_bfloat16* Bs_lo = dsm + 2 * GNST * A_STAGE + GNST * B_STAGE;

    const int tid  = threadIdx.x;
    const int wid  = tid >> 5;
    const int lane = tid & 31;
    const int bn = blockIdx.x, bm = blockIdx.y;
    const int wm = (wid >> 2) * (BM / 2);
    const int wn = (wid & 3) * 32;

    const int KT = K >> 5;

    float acc[MI][4][4] = {};

    auto load_stage = [&](int kt, int buf) {
        const __nv_bfloat16* Agh = Ahi + (size_t)bm * BM * K + kt * 32;
        const __nv_bfloat16* Agl = Alo + (size_t)bm * BM * K + kt * 32;
        const __nv_bfloat16* Bgh = Bhi + (size_t)bn * 128 * K + kt * 32;
        const __nv_bfloat16* Bgl = Blo + (size_t)bn * 128 * K + kt * 32;
        uint32_t ah = smem_u32(As_hi + buf * A_STAGE);
        uint32_t al = smem_u32(As_lo + buf * A_STAGE);
        uint32_t bh = smem_u32(Bs_hi + buf * B_STAGE);
        uint32_t bl = smem_u32(Bs_lo + buf * B_STAGE);
        #pragma unroll
        for (int i = 0; i < ACH; i++) {
            int ch = tid + i * 256;
            int r = ch >> 2, cc = (ch & 3) * 8;
            uint32_t so = (uint32_t)(r * SMSTRIDE + cc) * 2;
            size_t  go = (size_t)r * K + cc;
            CP_ASYNC_16(ah + so, Agh + go);
            CP_ASYNC_16(al + so, Agl + go);
        }
        #pragma unroll
        for (int i = 0; i < 2; i++) {
            int ch = tid + i * 256;
            int r = ch >> 2, cc = (ch & 3) * 8;
            uint32_t so = (uint32_t)(r * SMSTRIDE + cc) * 2;
            size_t  go = (size_t)r * K + cc;
            CP_ASYNC_16(bh + so, Bgh + go);
            CP_ASYNC_16(bl + so, Bgl + go);
        }
    };

    load_stage(0, 0); CP_COMMIT();
    load_stage(1, 1); CP_COMMIT();

    for (int kt = 0; kt < KT; kt++) {
        const int buf = kt & 1;
        CP_WAIT_1();
        __syncthreads();

        const uint32_t ah = smem_u32(As_hi + buf * A_STAGE);
        const uint32_t al = smem_u32(As_lo + buf * A_STAGE);
        const uint32_t bh = smem_u32(Bs_hi + buf * B_STAGE);
        const uint32_t bl = smem_u32(Bs_lo + buf * B_STAGE);

        #pragma unroll
        for (int ks = 0; ks < 2; ks++) {
            uint32_t af[MI][4], bfh[4][2], bfl[4][2];
            const int acol = ks * 16 + ((lane & 16) ? 8 : 0);
            const int bgrp = lane >> 3;
            #pragma unroll
            for (int mi = 0; mi < MI; mi++) {
                int row = wm + mi * 16 + (lane & 7) + ((lane & 8) ? 8 : 0);
                ldsm_x4(af[mi][0], af[mi][1], af[mi][2], af[mi][3],
                        ah + (uint32_t)(row * SMSTRIDE + acol) * 2);
            }
            #pragma unroll
            for (int njp = 0; njp < 2; njp++) {
                int row = wn + (njp * 2 + (bgrp >> 1)) * 8 + (lane & 7);
                int col = ks * 16 + (bgrp & 1) * 8;
                uint32_t r0, r1, r2, r3;
                ldsm_x4(r0, r1, r2, r3, bh + (uint32_t)(row * SMSTRIDE + col) * 2);
                bfh[njp*2][0] = r0;  bfh[njp*2][1] = r1;
                bfh[njp*2+1][0] = r2; bfh[njp*2+1][1] = r3;
            }
            #pragma unroll
            for (int mi = 0; mi < MI; mi++)
                #pragma unroll
                for (int nj = 0; nj < 4; nj++)
                    mma_bf16(acc[mi][nj], af[mi], bfh[nj]);
            #pragma unroll
            for (int njp = 0; njp < 2; njp++) {
                int row = wn + (njp * 2 + (bgrp >> 1)) * 8 + (lane & 7);
                int col = ks * 16 + (bgrp & 1) * 8;
                uint32_t r0, r1, r2, r3;
                ldsm_x4(r0, r1, r2, r3, bl + (uint32_t)(row * SMSTRIDE + col) * 2);
                bfl[njp*2][0] = r0;  bfl[njp*2][1] = r1;
                bfl[njp*2+1][0] = r2; bfl[njp*2+1][1] = r3;
            }
            #pragma unroll
            for (int mi = 0; mi < MI; mi++)
                #pragma unroll
                for (int nj = 0; nj < 4; nj++)
                    mma_bf16(acc[mi][nj], af[mi], bfl[nj]);
            #pragma unroll
            for (int mi = 0; mi < MI; mi++) {
                int row = wm + mi * 16 + (lane & 7) + ((lane & 8) ? 8 : 0);
                ldsm_x4(af[mi][0], af[mi][1], af[mi][2], af[mi][3],
                        al + (uint32_t)(row * SMSTRIDE + acol) * 2);
            }
            #pragma unroll
            for (int mi = 0; mi < MI; mi++)
                #pragma unroll
                for (int nj = 0; nj < 4; nj++)
                    mma_bf16(acc[mi][nj], af[mi], bfh[nj]);
        }

        __syncthreads();
        int nkt = kt + 2 < KT ? kt + 2 : KT - 1;
        load_stage(nkt, buf);
        CP_COMMIT();
    }

    #pragma unroll
    for (int nj = 0; nj < 4; nj++) {
        int gcol = bn * 128 + wn + nj * 8 + (lane & 3) * 2;
        float2 bv = *(const float2*)(bias + gcol);
        #pragma unroll
        for (int mi = 0; mi < MI; mi++) {
            int grow = bm * BM + wm + mi * 16 + (lane >> 2);
            float2 v0 = { acc[mi][nj][0] + bv.x, acc[mi][nj][1] + bv.y };
            float2 v1 = { acc[mi][nj][2] + bv.x, acc[mi][nj][3] + bv.y };
            *(float2*)(C + (size_t)grow * N + gcol)       = v0;
            *(float2*)(C + (size_t)(grow + 8) * N + gcol) = v1;
        }
    }
}

// ====================== RoPE + head split =====================================
__global__ void __launch_bounds__(384) rope_split_kernel() {
    int l = blockIdx.x;
    int t = threadIdx.x;
    int h = t >> 5;
    int i = t & 31;

    const float* row = g_qkv + (size_t)l * (3*DM);
    // 1/10000^(i/32) = 2^(-i*log2(10000)/32)
    float invf = exp2f(-(float)i * 0.41524101186092029f);
    float ang = (float)l * invf;
    float s, c;
    sincosf(ang, &s, &c);

    int qo = h*HD + i;
    float q1 = row[qo],        q2 = row[qo + 32];
    float k1 = row[DM + qo],   k2 = row[DM + qo + 32];
    int o = (h*L + l)*HD + i;
    g_q[o]      = q1*c - q2*s;
    g_q[o + 32] = q1*s + q2*c;
    g_k[o]      = k1*c - k2*s;
    g_k[o + 32] = k1*s + k2*c;
    g_v[o]      = row[2*DM + qo];
    g_v[o + 32] = row[2*DM + qo + 32];
}

// ====================== sliding-window attention (TQ=32) ======================
__global__ void __launch_bounds__(1024) window_attn_kernel(const int* __restrict__ mask) {
    extern __shared__ float sm[];
    float* ks = sm;                        // WROWS * WSTRIDE
    float* qs = ks + WROWS * WSTRIDE;      // TQ * 64
    float* ws = qs + TQ * HD;              // TQ * 128
    int*   rv = (int*)(ws + TQ * WIN);     // WROWS

    int h  = blockIdx.x / (L / TQ);
    int qt = blockIdx.x % (L / TQ);
    int l0 = qt * TQ;
    int lo = l0 - 64;
    int tid = threadIdx.x;

    for (int idx = tid; idx < WROWS; idx += 1024) {
        int lr = lo + idx;
        rv[idx] = (lr >= 0 && lr < L) ? (mask[lr] != 0) : 0;
    }
    for (int idx = tid; idx < WROWS * HD; idx += 1024) {
        int r = idx >> 6, d = idx & 63;
        int lr = lo + r;
        bool val = (lr >= 0 && lr < L);
        ks[r*WSTRIDE + d] = val ? g_k[(h*L + (val ? lr : 0))*HD + d] : 0.0f;
    }
    for (int idx = tid; idx < TQ * HD; idx += 1024) {
        qs[idx] = g_q[(h*L + l0)*HD + idx];
    }
    __syncthreads();

    int wq   = tid >> 5;
    int lane = tid & 31;
    int l = l0 + wq;

    const float4* qs4 = (const float4*)(qs + wq*HD);
    const float4* kp0 = (const float4*)(ks + (wq + lane      )*WSTRIDE);
    const float4* kp1 = (const float4*)(ks + (wq + lane +  32)*WSTRIDE);
    const float4* kp2 = (const float4*)(ks + (wq + lane +  64)*WSTRIDE);
    const float4* kp3 = (const float4*)(ks + (wq + lane +  96)*WSTRIDE);
    float sc[4] = {0.f, 0.f, 0.f, 0.f};
    #pragma unroll
    for (int d4 = 0; d4 < 16; d4++) {
        float4 qq = qs4[d4];
        float4 k0 = kp0[d4], k1 = kp1[d4], k2 = kp2[d4], k3 = kp3[d4];
        sc[0] += k0.x*qq.x + k0.y*qq.y + k0.z*qq.z + k0.w*qq.w;
        sc[1] += k1.x*qq.x + k1.y*qq.y + k1.z*qq.z + k1.w*qq.w;
        sc[2] += k2.x*qq.x + k2.y*qq.y + k2.z*qq.z + k2.w*qq.w;
        sc[3] += k3.x*qq.x + k3.y*qq.y + k3.z*qq.z + k3.w*qq.w;
    }
    #pragma unroll
    for (int w4 = 0; w4 < 4; w4++)
        sc[w4] = rv[wq + lane + w4*32] ? sc[w4] * SCALE : -1e30f;

    float m = fmaxf(fmaxf(sc[0], sc[1]), fmaxf(sc[2], sc[3]));
    #pragma unroll
    for (int o = 16; o > 0; o >>= 1) m = fmaxf(m, __shfl_xor_sync(0xffffffffu, m, o));
    float e[4], sum = 0.f;
    #pragma unroll
    for (int w4 = 0; w4 < 4; w4++) { e[w4] = expf(sc[w4] - m); sum += e[w4]; }
    #pragma unroll
    for (int o = 16; o > 0; o >>= 1) sum += __shfl_xor_sync(0xffffffffu, sum, o);
    float inv = 1.0f / sum;
    #pragma unroll
    for (int w4 = 0; w4 < 4; w4++) ws[wq*WIN + lane + w4*32] = e[w4] * inv;
    __syncwarp();

    const int wpair = lane >> 4;
    const int chunk = lane & 15;
    float4 a4 = {0.f, 0.f, 0.f, 0.f};
    const float* vbase = g_v + (size_t)h*L*HD + chunk*4;
    #pragma unroll 4
    for (int w = 0; w < WIN; w += 2) {
        float wt = ws[wq*WIN + w + wpair];
        int lr = lo + wq + w + wpair;
        lr = lr < 0 ? 0 : (lr > L-1 ? L-1 : lr);
        float4 v = *(const float4*)(vbase + (size_t)lr*HD);
        a4.x += wt * v.x;
        a4.y += wt * v.y;
        a4.z += wt * v.z;
        a4.w += wt * v.w;
    }
    a4.x += __shfl_xor_sync(0xffffffffu, a4.x, 16);
    a4.y += __shfl_xor_sync(0xffffffffu, a4.y, 16);
    a4.z += __shfl_xor_sync(0xffffffffu, a4.z, 16);
    a4.w += __shfl_xor_sync(0xffffffffu, a4.w, 16);

    if (wpair == 0) {
        __nv_bfloat16 h0 = __float2bfloat16(a4.x);
        __nv_bfloat16 h1 = __float2bfloat16(a4.y);
        __nv_bfloat16 h2 = __float2bfloat16(a4.z);
        __nv_bfloat16 h3 = __float2bfloat16(a4.w);
        __nv_bfloat162 hiA; hiA.x = h0; hiA.y = h1;
        __nv_bfloat162 hiB; hiB.x = h2; hiB.y = h3;
        __nv_bfloat162 loA, loB;
        loA.x = __float2bfloat16(a4.x - __bfloat162float(h0));
        loA.y = __float2bfloat16(a4.y - __bfloat162float(h1));
        loB.x = __float2bfloat16(a4.z - __bfloat162float(h2));
        loB.y = __float2bfloat16(a4.w - __bfloat162float(h3));
        size_t o = (size_t)l*DM + h*HD + chunk*4;
        *(__nv_bfloat162*)(g_Chi + o)     = hiA;
        *(__nv_bfloat162*)(g_Chi + o + 2) = hiB;
        *(__nv_bfloat162*)(g_Clo + o)     = loA;
        *(__nv_bfloat162*)(g_Clo + o + 2) = loB;
    }
}

// ====================== CLS split-softmax ======================================
__global__ void __launch_bounds__(128) cls_part_kernel(const int* __restrict__ mask) {
    extern __shared__ float smc[];
    float* ksm = smc;
    float* q0  = ksm + CKEYS*65;
    float* ew  = q0 + HD;
    float* red = ew + CKEYS;

    int c = blockIdx.x, h = blockIdx.y;
    int tid = threadIdx.x;
    int base = c * CKEYS;

    if (tid < HD) q0[tid] = g_q[(size_t)(h*L)*HD + tid];
    for (int idx = tid; idx < CKEYS*HD; idx += 128) {
        int key = idx >> 6, d = idx & 63;
        ksm[key*65 + d] = g_k[(size_t)(h*L + base + key)*HD + d];
    }
    __syncthreads();

    float s = 0.f;
    #pragma unroll
    for (int d = 0; d < HD; d++) s += ksm[tid*65 + d] * q0[d];
    s = (mask[base + tid] != 0) ? s * SCALE : -1e30f;

    red[tid] = s; __syncthreads();
    for (int o = 64; o > 0; o >>= 1) {
        if (tid < o) red[tid] = fmaxf(red[tid], red[tid + o]);
        __syncthreads();
    }
    float m_c = red[0];
    __syncthreads();

    float e = expf(s - m_c);
    ew[tid] = e;
    red[tid] = e; __syncthreads();
    for (int o = 64; o > 0; o >>= 1) {
        if (tid < o) red[tid] += red[tid + o];
        __syncthreads();
    }
    float s_c = red[0];
    __syncthreads();

    int d = tid & 63, half = tid >> 6;
    const float* vb = g_v + (size_t)(h*L + base + half*64)*HD + d;
    float acc = 0.f;
    #pragma unroll 8
    for (int kk = 0; kk < 64; kk++)
        acc += ew[half*64 + kk] * vb[(size_t)kk*HD];
    red[tid] = acc; __syncthreads();
    if (tid < HD) {
        g_cls_o[(size_t)(h*NCHUNK + c)*HD + tid] = red[tid] + red[HD + tid];
        if (tid == 0) { g_cls_m[h*NCHUNK + c] = m_c; g_cls_s[h*NCHUNK + c] = s_c; }
    }
}

__global__ void __launch_bounds__(768) cls_combine_kernel() {
    int tid = threadIdx.x;
    int h = tid >> 6, d = tid & 63;
    float m = -1e30f;
    #pragma unroll
    for (int c = 0; c < NCHUNK; c++) m = fmaxf(m, g_cls_m[h*NCHUNK + c]);
    float den = 0.f, num = 0.f;
    #pragma unroll
    for (int c = 0; c < NCHUNK; c++) {
        float w = expf(g_cls_m[h*NCHUNK + c] - m);
        den += g_cls_s[h*NCHUNK + c] * w;
        num += g_cls_o[(size_t)(h*NCHUNK + c)*HD + d] * w;
    }
    float o = num / den;
    __nv_bfloat16 hv = __float2bfloat16(o);
    g_Chi[h*HD + d] = hv;
    g_Clo[h*HD + d] = __float2bfloat16(o - __bfloat162float(hv));
}

// ====================== stream/event resources (created once, host-side) ======
struct GraphRes {
    cudaStream_t s1, s2;
    cudaEvent_t eF1, eWq, eWo, eF2, eWin, eCls;
    GraphRes() {
        cudaStreamCreateWithFlags(&s1, cudaStreamNonBlocking);
        cudaStreamCreateWithFlags(&s2, cudaStreamNonBlocking);
        cudaEventCreateWithFlags(&eF1,  cudaEventDisableTiming);
        cudaEventCreateWithFlags(&eWq,  cudaEventDisableTiming);
        cudaEventCreateWithFlags(&eWo,  cudaEventDisableTiming);
        cudaEventCreateWithFlags(&eF2,  cudaEventDisableTiming);
        cudaEventCreateWithFlags(&eWin, cudaEventDisableTiming);
        cudaEventCreateWithFlags(&eCls, cudaEventDisableTiming);
    }
};

// ====================== launch =================================================
extern "C" void kernel_launch(void* const* d_in, const int* in_sizes, int n_in,
                              void* d_out, int out_size) {
    (void)in_sizes; (void)n_in; (void)out_size;
    const float* emb   = (const float*)d_in[0];
    const int*   mask  = (const int*)  d_in[1];
    const float* W_qkv = (const float*)d_in[2];
    const float* b_qkv = (const float*)d_in[3];
    const float* W_o   = (const float*)d_in[4];
    const float* b_o   = (const float*)d_in[5];
    float* out = (float*)d_out;

    static GraphRes R;   // one-time host-side stream/event creation

    float* p_qkv;
    cudaGetSymbolAddress((void**)&p_qkv,  g_qkv);
    __nv_bfloat16 *p_Ahi, *p_Alo, *p_Wqhi, *p_Wqlo, *p_Wohi, *p_Wolo, *p_Chi, *p_Clo;
    cudaGetSymbolAddress((void**)&p_Ahi,  g_Ahi);
    cudaGetSymbolAddress((void**)&p_Alo,  g_Alo);
    cudaGetSymbolAddress((void**)&p_Wqhi, g_Wqhi);
    cudaGetSymbolAddress((void**)&p_Wqlo, g_Wqlo);
    cudaGetSymbolAddress((void**)&p_Wohi, g_Wohi);
    cudaGetSymbolAddress((void**)&p_Wolo, g_Wolo);
    cudaGetSymbolAddress((void**)&p_Chi,  g_Chi);
    cudaGetSymbolAddress((void**)&p_Clo,  g_Clo);

    constexpr int GSMEM128 = GNST * (2*128 + 2*128) * SMSTRIDE * 2;  // 81920 B
    constexpr int GSMEM64  = GNST * (2*64  + 2*128) * SMSTRIDE * 2;  // 61440 B
    cudaFuncSetAttribute(gemm_bf16_mma<128>, cudaFuncAttributeMaxDynamicSharedMemorySize, GSMEM128);
    cudaFuncSetAttribute(gemm_bf16_mma<64>,  cudaFuncAttributeMaxDynamicSharedMemorySize, GSMEM64);
    constexpr int SMEM_WIN = (WROWS*WSTRIDE + TQ*HD + TQ*WIN) * 4 + WROWS * 4;
    cudaFuncSetAttribute(window_attn_kernel,
                         cudaFuncAttributeMaxDynamicSharedMemorySize, SMEM_WIN);
    constexpr int SMEM_CLS = (CKEYS*65 + HD + CKEYS + 128) * 4;
    cudaFuncSetAttribute(cls_part_kernel,
                         cudaFuncAttributeMaxDynamicSharedMemorySize, SMEM_CLS);

    // ---- fork 1: emb split (s0) || W_qkv transpose (s1) || W_o transpose (s2)
    cudaEventRecord(R.eF1, 0);
    cudaStreamWaitEvent(R.s1, R.eF1, 0);
    cudaStreamWaitEvent(R.s2, R.eF1, 0);

    split_bf16<<<(L*DM + 255)/256, 256, 0, 0>>>(emb, p_Ahi, p_Alo, L*DM);
    transpose_split<<<dim3((3*DM)/32, DM/32), dim3(32,8), 0, R.s1>>>(W_qkv, p_Wqhi, p_Wqlo, DM, 3*DM);
    transpose_split<<<dim3(DM/32, DM/32),     dim3(32,8), 0, R.s2>>>(W_o,   p_Wohi, p_Wolo, DM, DM);
    cudaEventRecord(R.eWq, R.s1);
    cudaEventRecord(R.eWo, R.s2);

    // ---- gemm1 on s0 after emb split + W_qkv transpose
    cudaStreamWaitEvent(0, R.eWq, 0);
    gemm_bf16_mma<128><<<dim3((3*DM)/128, L/128), 256, GSMEM128, 0>>>(
        p_Ahi, p_Alo, p_Wqhi, p_Wqlo, b_qkv, p_qkv, 3*DM, DM);

    rope_split_kernel<<<L, 384, 0, 0>>>();

    // ---- fork 2: window (s0) || cls_part (s1)
    cudaEventRecord(R.eF2, 0);
    cudaStreamWaitEvent(R.s1, R.eF2, 0);
    cls_part_kernel<<<dim3(NCHUNK, H), 128, SMEM_CLS, R.s1>>>(mask);

    window_attn_kernel<<<H * (L/TQ), 1024, SMEM_WIN, 0>>>(mask);
    cudaEventRecord(R.eWin, 0);

    // cls_combine must follow window's row-0 writes and cls_part
    cudaStreamWaitEvent(R.s1, R.eWin, 0);
    cls_combine_kernel<<<1, 768, 0, R.s1>>>();
    cudaEventRecord(R.eCls, R.s1);

    // ---- join: gemm2 after window (program order), cls chain, W_o transpose
    cudaStreamWaitEvent(0, R.eCls, 0);
    cudaStreamWaitEvent(0, R.eWo, 0);
    gemm_bf16_mma<64><<<dim3(DM/128, L/64), 256, GSMEM64, 0>>>(
        p_Chi, p_Clo, p_Wohi, p_Wolo, b_o, out, DM, DM);
}

// round 11
// speedup vs baseline: 2.0586x; 1.0097x over previous
#include <cuda_runtime.h>
#include <cuda_bf16.h>
#include <math.h>
#include <stdint.h>

#define L    2048
#define DM   768
#define H    12
#define HD   64
#define WIN  128
#define TQ   32
#define WROWS 160
#define NCHUNK 16
#define CKEYS  128
#define WSTRIDE 68

static constexpr float SCALE = 0.03608439182435161f;  // 1/sqrt(768)
static constexpr float ROPE_C = 0.41524101186092029f; // log2(10000)/32

// ====================== scratch ================================================
__device__ float g_q[H * L * HD];
__device__ float g_k[H * L * HD];
__device__ float g_v[H * L * HD];
__device__ float g_cls_m[H * NCHUNK];
__device__ float g_cls_s[H * NCHUNK];
__device__ float g_cls_o[H * NCHUNK * HD];

__device__ __nv_bfloat16 g_Ahi[L * DM],  g_Alo[L * DM];
__device__ __nv_bfloat16 g_Wqhi[3*DM*DM], g_Wqlo[3*DM*DM];
__device__ __nv_bfloat16 g_Wohi[DM*DM],  g_Wolo[DM*DM];
__device__ __nv_bfloat16 g_Chi[L * DM],  g_Clo[L * DM];

// ====================== prep kernels ==========================================
__global__ void __launch_bounds__(256) split_bf16(const float* __restrict__ x,
        __nv_bfloat16* __restrict__ hi, __nv_bfloat16* __restrict__ lo, int n) {
    int i = blockIdx.x * 256 + threadIdx.x;
    if (i < n) {
        float v = x[i];
        __nv_bfloat16 h = __float2bfloat16(v);
        hi[i] = h;
        lo[i] = __float2bfloat16(v - __bfloat162float(h));
    }
}

__global__ void __launch_bounds__(256) transpose_split(const float* __restrict__ W,
        __nv_bfloat16* __restrict__ Thi, __nv_bfloat16* __restrict__ Tlo, int K, int N) {
    __shared__ float t[32][33];
    int n0 = blockIdx.x * 32, k0 = blockIdx.y * 32;
    int tx = threadIdx.x, ty = threadIdx.y;
    #pragma unroll
    for (int i = ty; i < 32; i += 8)
        t[i][tx] = W[(size_t)(k0 + i) * N + n0 + tx];
    __syncthreads();
    #pragma unroll
    for (int i = ty; i < 32; i += 8) {
        float v = t[tx][i];
        __nv_bfloat16 h = __float2bfloat16(v);
        size_t o = (size_t)(n0 + i) * K + k0 + tx;
        Thi[o] = h;
        Tlo[o] = __float2bfloat16(v - __bfloat162float(h));
    }
}

// ====================== mma.sync helpers ======================================
__device__ __forceinline__ uint32_t smem_u32(const void* p) {
    uint32_t a;
    asm("{ .reg .u64 t; cvta.to.shared.u64 t, %1; cvt.u32.u64 %0, t; }" : "=r"(a) : "l"(p));
    return a;
}
__device__ __forceinline__ void ldsm_x4(uint32_t& r0, uint32_t& r1, uint32_t& r2, uint32_t& r3,
                                        uint32_t addr) {
    asm volatile("ldmatrix.sync.aligned.m8n8.x4.shared.b16 {%0,%1,%2,%3}, [%4];"
                 : "=r"(r0), "=r"(r1), "=r"(r2), "=r"(r3) : "r"(addr));
}
__device__ __forceinline__ void mma_bf16(float* d, const uint32_t* a, const uint32_t* b) {
    asm volatile("mma.sync.aligned.m16n8k16.row.col.f32.bf16.bf16.f32 "
                 "{%0,%1,%2,%3}, {%4,%5,%6,%7}, {%8,%9}, {%0,%1,%2,%3};"
                 : "+f"(d[0]), "+f"(d[1]), "+f"(d[2]), "+f"(d[3])
                 : "r"(a[0]), "r"(a[1]), "r"(a[2]), "r"(a[3]), "r"(b[0]), "r"(b[1]));
}
#define CP_ASYNC_16(dst, src) \
    asm volatile("cp.async.cg.shared.global [%0], [%1], 16;" :: "r"(dst), "l"(src))
#define CP_COMMIT() asm volatile("cp.async.commit_group;" ::: "memory")
#define CP_WAIT_1() asm volatile("cp.async.wait_group 1;" ::: "memory")
#define CP_WAIT_0() asm volatile("cp.async.wait_group 0;" ::: "memory")

// ====================== HMMA bf16 merged 3-combo GEMM =========================
// ROPE=true: fused RoPE + head-split epilogue writes g_q/g_k/g_v directly.
#define SMSTRIDE 40
#define GNST 2

template<int BM, bool ROPE>
__global__ void __launch_bounds__(256, 2)
gemm_bf16_mma(const __nv_bfloat16* __restrict__ Ahi, const __nv_bfloat16* __restrict__ Alo,
              const __nv_bfloat16* __restrict__ Bhi, const __nv_bfloat16* __restrict__ Blo,
              const float* __restrict__ bias, float* __restrict__ C,
              int N, int K) {
    constexpr int MI  = BM / 32;
    constexpr int ACH = BM / 64;
    constexpr int A_STAGE = BM * SMSTRIDE;
    constexpr int B_STAGE = 128 * SMSTRIDE;

    extern __shared__ __align__(16) __nv_bfloat16 dsm[];
    __nv_bfloat16* As_hi = dsm;
    __nv_bfloat16* As_lo = dsm + GNST * A_STAGE;
    __nv_bfloat16* Bs_hi = dsm + 2 * GNST * A_STAGE;
    __nv_bfloat16* Bs_lo = dsm + 2 * GNST * A_STAGE + GNST * B_STAGE;

    const int tid  = threadIdx.x;
    const int wid  = tid >> 5;
    const int lane = tid & 31;
    const int bn = blockIdx.x, bm = blockIdx.y;
    const int wm = (wid >> 2) * (BM / 2);
    const int wn = (wid & 3) * 32;

    const int KT = K >> 5;

    float acc[MI][4][4] = {};

    auto load_stage = [&](int kt, int buf) {
        const __nv_bfloat16* Agh = Ahi + (size_t)bm * BM * K + kt * 32;
        const __nv_bfloat16* Agl = Alo + (size_t)bm * BM * K + kt * 32;
        const __nv_bfloat16* Bgh = Bhi + (size_t)bn * 128 * K + kt * 32;
        const __nv_bfloat16* Bgl = Blo + (size_t)bn * 128 * K + kt * 32;
        uint32_t ah = smem_u32(As_hi + buf * A_STAGE);
        uint32_t al = smem_u32(As_lo + buf * A_STAGE);
        uint32_t bh = smem_u32(Bs_hi + buf * B_STAGE);
        uint32_t bl = smem_u32(Bs_lo + buf * B_STAGE);
        #pragma unroll
        for (int i = 0; i < ACH; i++) {
            int ch = tid + i * 256;
            int r = ch >> 2, cc = (ch & 3) * 8;
            uint32_t so = (uint32_t)(r * SMSTRIDE + cc) * 2;
            size_t  go = (size_t)r * K + cc;
            CP_ASYNC_16(ah + so, Agh + go);
            CP_ASYNC_16(al + so, Agl + go);
        }
        #pragma unroll
        for (int i = 0; i < 2; i++) {
            int ch = tid + i * 256;
            int r = ch >> 2, cc = (ch & 3) * 8;
            uint32_t so = (uint32_t)(r * SMSTRIDE + cc) * 2;
            size_t  go = (size_t)r * K + cc;
            CP_ASYNC_16(bh + so, Bgh + go);
            CP_ASYNC_16(bl + so, Bgl + go);
        }
    };

    load_stage(0, 0); CP_COMMIT();
    load_stage(1, 1); CP_COMMIT();

    for (int kt = 0; kt < KT; kt++) {
        const int buf = kt & 1;
        CP_WAIT_1();
        __syncthreads();

        const uint32_t ah = smem_u32(As_hi + buf * A_STAGE);
        const uint32_t al = smem_u32(As_lo + buf * A_STAGE);
        const uint32_t bh = smem_u32(Bs_hi + buf * B_STAGE);
        const uint32_t bl = smem_u32(Bs_lo + buf * B_STAGE);

        #pragma unroll
        for (int ks = 0; ks < 2; ks++) {
            uint32_t af[MI][4], bfh[4][2], bfl[4][2];
            const int acol = ks * 16 + ((lane & 16) ? 8 : 0);
            const int bgrp = lane >> 3;
            #pragma unroll
            for (int mi = 0; mi < MI; mi++) {
                int row = wm + mi * 16 + (lane & 7) + ((lane & 8) ? 8 : 0);
                ldsm_x4(af[mi][0], af[mi][1], af[mi][2], af[mi][3],
                        ah + (uint32_t)(row * SMSTRIDE + acol) * 2);
            }
            #pragma unroll
            for (int njp = 0; njp < 2; njp++) {
                int row = wn + (njp * 2 + (bgrp >> 1)) * 8 + (lane & 7);
                int col = ks * 16 + (bgrp & 1) * 8;
                uint32_t r0, r1, r2, r3;
                ldsm_x4(r0, r1, r2, r3, bh + (uint32_t)(row * SMSTRIDE + col) * 2);
                bfh[njp*2][0] = r0;  bfh[njp*2][1] = r1;
                bfh[njp*2+1][0] = r2; bfh[njp*2+1][1] = r3;
            }
            #pragma unroll
            for (int mi = 0; mi < MI; mi++)
                #pragma unroll
                for (int nj = 0; nj < 4; nj++)
                    mma_bf16(acc[mi][nj], af[mi], bfh[nj]);
            #pragma unroll
            for (int njp = 0; njp < 2; njp++) {
                int row = wn + (njp * 2 + (bgrp >> 1)) * 8 + (lane & 7);
                int col = ks * 16 + (bgrp & 1) * 8;
                uint32_t r0, r1, r2, r3;
                ldsm_x4(r0, r1, r2, r3, bl + (uint32_t)(row * SMSTRIDE + col) * 2);
                bfl[njp*2][0] = r0;  bfl[njp*2][1] = r1;
                bfl[njp*2+1][0] = r2; bfl[njp*2+1][1] = r3;
            }
            #pragma unroll
            for (int mi = 0; mi < MI; mi++)
                #pragma unroll
                for (int nj = 0; nj < 4; nj++)
                    mma_bf16(acc[mi][nj], af[mi], bfl[nj]);
            #pragma unroll
            for (int mi = 0; mi < MI; mi++) {
                int row = wm + mi * 16 + (lane & 7) + ((lane & 8) ? 8 : 0);
                ldsm_x4(af[mi][0], af[mi][1], af[mi][2], af[mi][3],
                        al + (uint32_t)(row * SMSTRIDE + acol) * 2);
            }
            #pragma unroll
            for (int mi = 0; mi < MI; mi++)
                #pragma unroll
                for (int nj = 0; nj < 4; nj++)
                    mma_bf16(acc[mi][nj], af[mi], bfh[nj]);
        }

        __syncthreads();
        int nkt = kt + 2 < KT ? kt + 2 : KT - 1;
        load_stage(nkt, buf);
        CP_COMMIT();
    }

    if (!ROPE) {
        #pragma unroll
        for (int nj = 0; nj < 4; nj++) {
            int gcol = bn * 128 + wn + nj * 8 + (lane & 3) * 2;
            float2 bv = *(const float2*)(bias + gcol);
            #pragma unroll
            for (int mi = 0; mi < MI; mi++) {
                int grow = bm * BM + wm + mi * 16 + (lane >> 2);
                float2 v0 = { acc[mi][nj][0] + bv.x, acc[mi][nj][1] + bv.y };
                float2 v1 = { acc[mi][nj][2] + bv.x, acc[mi][nj][3] + bv.y };
                *(float2*)(C + (size_t)grow * N + gcol)       = v0;
                *(float2*)(C + (size_t)(grow + 8) * N + gcol) = v1;
            }
        }
    } else {
        // ---- fused RoPE + head-split epilogue (BM==128 path) ----
        CP_WAIT_0();                // drain pending tail prefetches before reusing dsm
        __syncthreads();
        float* ep = (float*)dsm;    // [128][132] fp32 = 67584 B

        #pragma unroll
        for (int nj = 0; nj < 4; nj++) {
            int colq = wn + nj * 8 + (lane & 3) * 2;
            float2 bv = *(const float2*)(bias + bn * 128 + colq);
            #pragma unroll
            for (int mi = 0; mi < MI; mi++) {
                int row = wm + mi * 16 + (lane >> 2);
                ep[row * 132 + colq]           = acc[mi][nj][0] + bv.x;
                ep[row * 132 + colq + 1]       = acc[mi][nj][1] + bv.y;
                ep[(row + 8) * 132 + colq]     = acc[mi][nj][2] + bv.x;
                ep[(row + 8) * 132 + colq + 1] = acc[mi][nj][3] + bv.y;
            }
        }
        __syncthreads();

        const int rr  = tid >> 3;          // 0..31 row group base
        const int sub = tid & 7;
        const int hh  = sub >> 2;          // head half of the 128-col tile
        const int qq  = sub & 3;           // 8-wide quarter of 32 pairs
        const int sec = bn / 6;            // 0=q 1=k 2=v
        const int hd  = (bn % 6) * 2 + hh; // head index 0..11
        float* dst = (sec == 0) ? g_q : (sec == 1) ? g_k : g_v;

        float invf[8];
        if (sec < 2) {
            #pragma unroll
            for (int e = 0; e < 8; e++)
                invf[e] = exp2f(-(float)(qq * 8 + e) * ROPE_C);
        }

        #pragma unroll
        for (int rg = 0; rg < 4; rg++) {
            int r = rg * 32 + rr;
            int l = bm * 128 + r;
            const float* er = ep + r * 132 + hh * 64 + qq * 8;
            float x1[8], x2[8];
            *(float4*)&x1[0] = *(const float4*)er;
            *(float4*)&x1[4] = *(const float4*)(er + 4);
            *(float4*)&x2[0] = *(const float4*)(er + 32);
            *(float4*)&x2[4] = *(const float4*)(er + 36);
            float o1[8], o2[8];
            if (sec == 2) {
                #pragma unroll
                for (int e = 0; e < 8; e++) { o1[e] = x1[e]; o2[e] = x2[e]; }
            } else {
                #pragma unroll
                for (int e = 0; e < 8; e++) {
                    float s, c;
                    sincosf((float)l * invf[e], &s, &c);
                    o1[e] = x1[e] * c - x2[e] * s;
                    o2[e] = x1[e] * s + x2[e] * c;
                }
            }
            float* dp = dst + ((size_t)hd * L + l) * HD + qq * 8;
            *(float4*)dp        = *(float4*)&o1[0];
            *(float4*)(dp + 4)  = *(float4*)&o1[4];
            *(float4*)(dp + 32) = *(float4*)&o2[0];
            *(float4*)(dp + 36) = *(float4*)&o2[4];
        }
    }
}

// ====================== sliding-window attention (TQ=32) ======================
__global__ void __launch_bounds__(1024) window_attn_kernel(const int* __restrict__ mask) {
    extern __shared__ float sm[];
    float* ks = sm;                        // WROWS * WSTRIDE
    float* qs = ks + WROWS * WSTRIDE;      // TQ * 64
    float* ws = qs + TQ * HD;              // TQ * 128
    int*   rv = (int*)(ws + TQ * WIN);     // WROWS

    int h  = blockIdx.x / (L / TQ);
    int qt = blockIdx.x % (L / TQ);
    int l0 = qt * TQ;
    int lo = l0 - 64;
    int tid = threadIdx.x;

    for (int idx = tid; idx < WROWS; idx += 1024) {
        int lr = lo + idx;
        rv[idx] = (lr >= 0 && lr < L) ? (mask[lr] != 0) : 0;
    }
    for (int idx = tid; idx < WROWS * HD; idx += 1024) {
        int r = idx >> 6, d = idx & 63;
        int lr = lo + r;
        bool val = (lr >= 0 && lr < L);
        ks[r*WSTRIDE + d] = val ? g_k[(h*L + (val ? lr : 0))*HD + d] : 0.0f;
    }
    for (int idx = tid; idx < TQ * HD; idx += 1024) {
        qs[idx] = g_q[(h*L + l0)*HD + idx];
    }
    __syncthreads();

    int wq   = tid >> 5;
    int lane = tid & 31;
    int l = l0 + wq;

    const float4* qs4 = (const float4*)(qs + wq*HD);
    const float4* kp0 = (const float4*)(ks + (wq + lane      )*WSTRIDE);
    const float4* kp1 = (const float4*)(ks + (wq + lane +  32)*WSTRIDE);
    const float4* kp2 = (const float4*)(ks + (wq + lane +  64)*WSTRIDE);
    const float4* kp3 = (const float4*)(ks + (wq + lane +  96)*WSTRIDE);
    float sc[4] = {0.f, 0.f, 0.f, 0.f};
    #pragma unroll
    for (int d4 = 0; d4 < 16; d4++) {
        float4 qq = qs4[d4];
        float4 k0 = kp0[d4], k1 = kp1[d4], k2 = kp2[d4], k3 = kp3[d4];
        sc[0] += k0.x*qq.x + k0.y*qq.y + k0.z*qq.z + k0.w*qq.w;
        sc[1] += k1.x*qq.x + k1.y*qq.y + k1.z*qq.z + k1.w*qq.w;
        sc[2] += k2.x*qq.x + k2.y*qq.y + k2.z*qq.z + k2.w*qq.w;
        sc[3] += k3.x*qq.x + k3.y*qq.y + k3.z*qq.z + k3.w*qq.w;
    }
    #pragma unroll
    for (int w4 = 0; w4 < 4; w4++)
        sc[w4] = rv[wq + lane + w4*32] ? sc[w4] * SCALE : -1e30f;

    float m = fmaxf(fmaxf(sc[0], sc[1]), fmaxf(sc[2], sc[3]));
    #pragma unroll
    for (int o = 16; o > 0; o >>= 1) m = fmaxf(m, __shfl_xor_sync(0xffffffffu, m, o));
    float e[4], sum = 0.f;
    #pragma unroll
    for (int w4 = 0; w4 < 4; w4++) { e[w4] = expf(sc[w4] - m); sum += e[w4]; }
    #pragma unroll
    for (int o = 16; o > 0; o >>= 1) sum += __shfl_xor_sync(0xffffffffu, sum, o);
    float inv = 1.0f / sum;
    #pragma unroll
    for (int w4 = 0; w4 < 4; w4++) ws[wq*WIN + lane + w4*32] = e[w4] * inv;
    __syncwarp();

    const int wpair = lane >> 4;
    const int chunk = lane & 15;
    float4 a4 = {0.f, 0.f, 0.f, 0.f};
    const float* vbase = g_v + (size_t)h*L*HD + chunk*4;
    #pragma unroll 4
    for (int w = 0; w < WIN; w += 2) {
        float wt = ws[wq*WIN + w + wpair];
        int lr = lo + wq + w + wpair;
        lr = lr < 0 ? 0 : (lr > L-1 ? L-1 : lr);
        float4 v = *(const float4*)(vbase + (size_t)lr*HD);
        a4.x += wt * v.x;
        a4.y += wt * v.y;
        a4.z += wt * v.z;
        a4.w += wt * v.w;
    }
    a4.x += __shfl_xor_sync(0xffffffffu, a4.x, 16);
    a4.y += __shfl_xor_sync(0xffffffffu, a4.y, 16);
    a4.z += __shfl_xor_sync(0xffffffffu, a4.z, 16);
    a4.w += __shfl_xor_sync(0xffffffffu, a4.w, 16);

    if (wpair == 0) {
        __nv_bfloat16 h0 = __float2bfloat16(a4.x);
        __nv_bfloat16 h1 = __float2bfloat16(a4.y);
        __nv_bfloat16 h2 = __float2bfloat16(a4.z);
        __nv_bfloat16 h3 = __float2bfloat16(a4.w);
        __nv_bfloat162 hiA; hiA.x = h0; hiA.y = h1;
        __nv_bfloat162 hiB; hiB.x = h2; hiB.y = h3;
        __nv_bfloat162 loA, loB;
        loA.x = __float2bfloat16(a4.x - __bfloat162float(h0));
        loA.y = __float2bfloat16(a4.y - __bfloat162float(h1));
        loB.x = __float2bfloat16(a4.z - __bfloat162float(h2));
        loB.y = __float2bfloat16(a4.w - __bfloat162float(h3));
        size_t o = (size_t)l*DM + h*HD + chunk*4;
        *(__nv_bfloat162*)(g_Chi + o)     = hiA;
        *(__nv_bfloat162*)(g_Chi + o + 2) = hiB;
        *(__nv_bfloat162*)(g_Clo + o)     = loA;
        *(__nv_bfloat162*)(g_Clo + o + 2) = loB;
    }
}

// ====================== CLS split-softmax ======================================
__global__ void __launch_bounds__(128) cls_part_kernel(const int* __restrict__ mask) {
    extern __shared__ float smc[];
    float* ksm = smc;
    float* q0  = ksm + CKEYS*65;
    float* ew  = q0 + HD;
    float* red = ew + CKEYS;

    int c = blockIdx.x, h = blockIdx.y;
    int tid = threadIdx.x;
    int base = c * CKEYS;

    if (tid < HD) q0[tid] = g_q[(size_t)(h*L)*HD + tid];
    for (int idx = tid; idx < CKEYS*HD; idx += 128) {
        int key = idx >> 6, d = idx & 63;
        ksm[key*65 + d] = g_k[(size_t)(h*L + base + key)*HD + d];
    }
    __syncthreads();

    float s = 0.f;
    #pragma unroll
    for (int d = 0; d < HD; d++) s += ksm[tid*65 + d] * q0[d];
    s = (mask[base + tid] != 0) ? s * SCALE : -1e30f;

    red[tid] = s; __syncthreads();
    for (int o = 64; o > 0; o >>= 1) {
        if (tid < o) red[tid] = fmaxf(red[tid], red[tid + o]);
        __syncthreads();
    }
    float m_c = red[0];
    __syncthreads();

    float e = expf(s - m_c);
    ew[tid] = e;
    red[tid] = e; __syncthreads();
    for (int o = 64; o > 0; o >>= 1) {
        if (tid < o) red[tid] += red[tid + o];
        __syncthreads();
    }
    float s_c = red[0];
    __syncthreads();

    int d = tid & 63, half = tid >> 6;
    const float* vb = g_v + (size_t)(h*L + base + half*64)*HD + d;
    float acc = 0.f;
    #pragma unroll 8
    for (int kk = 0; kk < 64; kk++)
        acc += ew[half*64 + kk] * vb[(size_t)kk*HD];
    red[tid] = acc; __syncthreads();
    if (tid < HD) {
        g_cls_o[(size_t)(h*NCHUNK + c)*HD + tid] = red[tid] + red[HD + tid];
        if (tid == 0) { g_cls_m[h*NCHUNK + c] = m_c; g_cls_s[h*NCHUNK + c] = s_c; }
    }
}

__global__ void __launch_bounds__(768) cls_combine_kernel() {
    int tid = threadIdx.x;
    int h = tid >> 6, d = tid & 63;
    float m = -1e30f;
    #pragma unroll
    for (int c = 0; c < NCHUNK; c++) m = fmaxf(m, g_cls_m[h*NCHUNK + c]);
    float den = 0.f, num = 0.f;
    #pragma unroll
    for (int c = 0; c < NCHUNK; c++) {
        float w = expf(g_cls_m[h*NCHUNK + c] - m);
        den += g_cls_s[h*NCHUNK + c] * w;
        num += g_cls_o[(size_t)(h*NCHUNK + c)*HD + d] * w;
    }
    float o = num / den;
    __nv_bfloat16 hv = __float2bfloat16(o);
    g_Chi[h*HD + d] = hv;
    g_Clo[h*HD + d] = __float2bfloat16(o - __bfloat162float(hv));
}

// ====================== stream/event resources =================================
struct GraphRes {
    cudaStream_t s1, s2;
    cudaEvent_t eF1, eWq, eWo, eF2, eWin, eCls;
    GraphRes() {
        cudaStreamCreateWithFlags(&s1, cudaStreamNonBlocking);
        cudaStreamCreateWithFlags(&s2, cudaStreamNonBlocking);
        cudaEventCreateWithFlags(&eF1,  cudaEventDisableTiming);
        cudaEventCreateWithFlags(&eWq,  cudaEventDisableTiming);
        cudaEventCreateWithFlags(&eWo,  cudaEventDisableTiming);
        cudaEventCreateWithFlags(&eF2,  cudaEventDisableTiming);
        cudaEventCreateWithFlags(&eWin, cudaEventDisableTiming);
        cudaEventCreateWithFlags(&eCls, cudaEventDisableTiming);
    }
};

// ====================== launch =================================================
extern "C" void kernel_launch(void* const* d_in, const int* in_sizes, int n_in,
                              void* d_out, int out_size) {
    (void)in_sizes; (void)n_in; (void)out_size;
    const float* emb   = (const float*)d_in[0];
    const int*   mask  = (const int*)  d_in[1];
    const float* W_qkv = (const float*)d_in[2];
    const float* b_qkv = (const float*)d_in[3];
    const float* W_o   = (const float*)d_in[4];
    const float* b_o   = (const float*)d_in[5];
    float* out = (float*)d_out;

    static GraphRes R;

    __nv_bfloat16 *p_Ahi, *p_Alo, *p_Wqhi, *p_Wqlo, *p_Wohi, *p_Wolo, *p_Chi, *p_Clo;
    cudaGetSymbolAddress((void**)&p_Ahi,  g_Ahi);
    cudaGetSymbolAddress((void**)&p_Alo,  g_Alo);
    cudaGetSymbolAddress((void**)&p_Wqhi, g_Wqhi);
    cudaGetSymbolAddress((void**)&p_Wqlo, g_Wqlo);
    cudaGetSymbolAddress((void**)&p_Wohi, g_Wohi);
    cudaGetSymbolAddress((void**)&p_Wolo, g_Wolo);
    cudaGetSymbolAddress((void**)&p_Chi,  g_Chi);
    cudaGetSymbolAddress((void**)&p_Clo,  g_Clo);

    constexpr int GSMEM128 = GNST * (2*128 + 2*128) * SMSTRIDE * 2;  // 81920 B
    constexpr int GSMEM64  = GNST * (2*64  + 2*128) * SMSTRIDE * 2;  // 61440 B
    cudaFuncSetAttribute((const void*)gemm_bf16_mma<128,true>,
                         cudaFuncAttributeMaxDynamicSharedMemorySize, GSMEM128);
    cudaFuncSetAttribute((const void*)gemm_bf16_mma<64,false>,
                         cudaFuncAttributeMaxDynamicSharedMemorySize, GSMEM64);
    constexpr int SMEM_WIN = (WROWS*WSTRIDE + TQ*HD + TQ*WIN) * 4 + WROWS * 4;
    cudaFuncSetAttribute(window_attn_kernel,
                         cudaFuncAttributeMaxDynamicSharedMemorySize, SMEM_WIN);
    constexpr int SMEM_CLS = (CKEYS*65 + HD + CKEYS + 128) * 4;
    cudaFuncSetAttribute(cls_part_kernel,
                         cudaFuncAttributeMaxDynamicSharedMemorySize, SMEM_CLS);

    // ---- fork 1: emb split (s0) || W_qkv transpose (s1) || W_o transpose (s2)
    cudaEventRecord(R.eF1, 0);
    cudaStreamWaitEvent(R.s1, R.eF1, 0);
    cudaStreamWaitEvent(R.s2, R.eF1, 0);

    split_bf16<<<(L*DM + 255)/256, 256, 0, 0>>>(emb, p_Ahi, p_Alo, L*DM);
    transpose_split<<<dim3((3*DM)/32, DM/32), dim3(32,8), 0, R.s1>>>(W_qkv, p_Wqhi, p_Wqlo, DM, 3*DM);
    transpose_split<<<dim3(DM/32, DM/32),     dim3(32,8), 0, R.s2>>>(W_o,   p_Wohi, p_Wolo, DM, DM);
    cudaEventRecord(R.eWq, R.s1);
    cudaEventRecord(R.eWo, R.s2);

    // ---- gemm1 with fused RoPE+split epilogue -> g_q/g_k/g_v
    cudaStreamWaitEvent(0, R.eWq, 0);
    gemm_bf16_mma<128,true><<<dim3((3*DM)/128, L/128), 256, GSMEM128, 0>>>(
        p_Ahi, p_Alo, p_Wqhi, p_Wqlo, b_qkv, nullptr, 3*DM, DM);

    // ---- fork 2: window (s0) || cls_part (s1)
    cudaEventRecord(R.eF2, 0);
    cudaStreamWaitEvent(R.s1, R.eF2, 0);
    cls_part_kernel<<<dim3(NCHUNK, H), 128, SMEM_CLS, R.s1>>>(mask);

    window_attn_kernel<<<H * (L/TQ), 1024, SMEM_WIN, 0>>>(mask);
    cudaEventRecord(R.eWin, 0);

    cudaStreamWaitEvent(R.s1, R.eWin, 0);
    cls_combine_kernel<<<1, 768, 0, R.s1>>>();
    cudaEventRecord(R.eCls, R.s1);

    // ---- join: gemm2
    cudaStreamWaitEvent(0, R.eCls, 0);
    cudaStreamWaitEvent(0, R.eWo, 0);
    gemm_bf16_mma<64,false><<<dim3(DM/128, L/64), 256, GSMEM64, 0>>>(
        p_Chi, p_Clo, p_Wohi, p_Wolo, b_o, out, DM, DM);
}

// round 12
// speedup vs baseline: 2.7712x; 1.3462x over previous
#include <cuda_runtime.h>
#include <cuda_fp16.h>
#include <math.h>
#include <stdint.h>

#define L    2048
#define DM   768
#define H    12
#define HD   64
#define WIN  128
#define TQ   32
#define WROWS 160
#define NCHUNK 16
#define CKEYS  128
#define WSTRIDE 68

static constexpr float SCALE = 0.03608439182435161f;  // 1/sqrt(768)
static constexpr float ROPE_C = 0.41524101186092029f; // log2(10000)/32

// ====================== scratch ================================================
__device__ float g_q[H * L * HD];
__device__ float g_k[H * L * HD];
__device__ float g_v[H * L * HD];
__device__ float g_cls_m[H * NCHUNK];
__device__ float g_cls_s[H * NCHUNK];
__device__ float g_cls_o[H * NCHUNK * HD];

__device__ __half g_Af[L * DM];          // emb fp16
__device__ __half g_Wqf[3*DM*DM];        // W_qkv^T fp16 [2304][768]
__device__ __half g_Wof[DM*DM];          // W_o^T fp16 [768][768]
__device__ __half g_Cf[L * DM];          // attn-out fp16

// ====================== prep kernels ==========================================
__global__ void __launch_bounds__(256) to_f16(const float* __restrict__ x,
        __half* __restrict__ y, int n) {
    int i = blockIdx.x * 256 + threadIdx.x;
    if (i < n) y[i] = __float2half_rn(x[i]);
}

// W [K,N] fp32 row-major -> T [N,K] fp16 row-major
__global__ void __launch_bounds__(256) transpose_f16(const float* __restrict__ W,
        __half* __restrict__ T, int K, int N) {
    __shared__ float t[32][33];
    int n0 = blockIdx.x * 32, k0 = blockIdx.y * 32;
    int tx = threadIdx.x, ty = threadIdx.y;
    #pragma unroll
    for (int i = ty; i < 32; i += 8)
        t[i][tx] = W[(size_t)(k0 + i) * N + n0 + tx];
    __syncthreads();
    #pragma unroll
    for (int i = ty; i < 32; i += 8)
        T[(size_t)(n0 + i) * K + k0 + tx] = __float2half_rn(t[tx][i]);
}

// ====================== mma.sync helpers ======================================
__device__ __forceinline__ uint32_t smem_u32(const void* p) {
    uint32_t a;
    asm("{ .reg .u64 t; cvta.to.shared.u64 t, %1; cvt.u32.u64 %0, t; }" : "=r"(a) : "l"(p));
    return a;
}
__device__ __forceinline__ void ldsm_x4(uint32_t& r0, uint32_t& r1, uint32_t& r2, uint32_t& r3,
                                        uint32_t addr) {
    asm volatile("ldmatrix.sync.aligned.m8n8.x4.shared.b16 {%0,%1,%2,%3}, [%4];"
                 : "=r"(r0), "=r"(r1), "=r"(r2), "=r"(r3) : "r"(addr));
}
__device__ __forceinline__ void mma_f16(float* d, const uint32_t* a, const uint32_t* b) {
    asm volatile("mma.sync.aligned.m16n8k16.row.col.f32.f16.f16.f32 "
                 "{%0,%1,%2,%3}, {%4,%5,%6,%7}, {%8,%9}, {%0,%1,%2,%3};"
                 : "+f"(d[0]), "+f"(d[1]), "+f"(d[2]), "+f"(d[3])
                 : "r"(a[0]), "r"(a[1]), "r"(a[2]), "r"(a[3]), "r"(b[0]), "r"(b[1]));
}
#define CP_ASYNC_16(dst, src) \
    asm volatile("cp.async.cg.shared.global [%0], [%1], 16;" :: "r"(dst), "l"(src))
#define CP_COMMIT() asm volatile("cp.async.commit_group;" ::: "memory")
#define CP_WAIT_2() asm volatile("cp.async.wait_group 2;" ::: "memory")
#define CP_WAIT_0() asm volatile("cp.async.wait_group 0;" ::: "memory")

// ====================== HMMA fp16 single-pass GEMM ============================
// C[M,N] = A[M,K] @ B[N,K]^T + bias.  4-stage cp.async pipeline.
// ROPE=true: fused RoPE + head-split epilogue writes g_q/g_k/g_v directly.
#define SMSTRIDE 40
#define FNST 4

template<int BM, bool ROPE>
__global__ void __launch_bounds__(256, 2)
gemm_f16(const __half* __restrict__ A, const __half* __restrict__ B,
         const float* __restrict__ bias, float* __restrict__ C,
         int N, int K) {
    constexpr int MI  = BM / 32;
    constexpr int ACH = BM / 64;          // 16B chunks per thread for A stage
    constexpr int A_STAGE = BM * SMSTRIDE;
    constexpr int B_STAGE = 128 * SMSTRIDE;

    extern __shared__ __align__(16) __half dsm[];
    __half* As = dsm;
    __half* Bs = dsm + FNST * A_STAGE;

    const int tid  = threadIdx.x;
    const int wid  = tid >> 5;
    const int lane = tid & 31;
    const int bn = blockIdx.x, bm = blockIdx.y;
    const int wm = (wid >> 2) * (BM / 2);
    const int wn = (wid & 3) * 32;

    const int KT = K >> 5;    // 24

    float acc[MI][4][4] = {};

    auto load_stage = [&](int kt, int buf) {
        const __half* Ag = A + (size_t)bm * BM * K + kt * 32;
        const __half* Bg = B + (size_t)bn * 128 * K + kt * 32;
        uint32_t a_s = smem_u32(As + buf * A_STAGE);
        uint32_t b_s = smem_u32(Bs + buf * B_STAGE);
        #pragma unroll
        for (int i = 0; i < ACH; i++) {
            int ch = tid + i * 256;
            int r = ch >> 2, cc = (ch & 3) * 8;
            CP_ASYNC_16(a_s + (uint32_t)(r * SMSTRIDE + cc) * 2, Ag + (size_t)r * K + cc);
        }
        #pragma unroll
        for (int i = 0; i < 2; i++) {
            int ch = tid + i * 256;
            int r = ch >> 2, cc = (ch & 3) * 8;
            CP_ASYNC_16(b_s + (uint32_t)(r * SMSTRIDE + cc) * 2, Bg + (size_t)r * K + cc);
        }
    };

    #pragma unroll
    for (int s = 0; s < 3; s++) { load_stage(s, s); CP_COMMIT(); }

    for (int kt = 0; kt < KT; kt++) {
        const int buf = kt & 3;
        CP_WAIT_2();
        __syncthreads();

        const uint32_t a_base = smem_u32(As + buf * A_STAGE);
        const uint32_t b_base = smem_u32(Bs + buf * B_STAGE);

        #pragma unroll
        for (int ks = 0; ks < 2; ks++) {
            uint32_t af[MI][4], bf[4][2];
            const int acol = ks * 16 + ((lane & 16) ? 8 : 0);
            const int bgrp = lane >> 3;
            #pragma unroll
            for (int mi = 0; mi < MI; mi++) {
                int row = wm + mi * 16 + (lane & 7) + ((lane & 8) ? 8 : 0);
                ldsm_x4(af[mi][0], af[mi][1], af[mi][2], af[mi][3],
                        a_base + (uint32_t)(row * SMSTRIDE + acol) * 2);
            }
            #pragma unroll
            for (int njp = 0; njp < 2; njp++) {
                int row = wn + (njp * 2 + (bgrp >> 1)) * 8 + (lane & 7);
                int col = ks * 16 + (bgrp & 1) * 8;
                uint32_t r0, r1, r2, r3;
                ldsm_x4(r0, r1, r2, r3, b_base + (uint32_t)(row * SMSTRIDE + col) * 2);
                bf[njp*2][0] = r0;  bf[njp*2][1] = r1;
                bf[njp*2+1][0] = r2; bf[njp*2+1][1] = r3;
            }
            #pragma unroll
            for (int mi = 0; mi < MI; mi++)
                #pragma unroll
                for (int nj = 0; nj < 4; nj++)
                    mma_f16(acc[mi][nj], af[mi], bf[nj]);
        }

        __syncthreads();
        int nkt = kt + 3 < KT ? kt + 3 : KT - 1;
        load_stage(nkt, (kt + 3) & 3);
        CP_COMMIT();
    }

    if (!ROPE) {
        #pragma unroll
        for (int nj = 0; nj < 4; nj++) {
            int gcol = bn * 128 + wn + nj * 8 + (lane & 3) * 2;
            float2 bv = *(const float2*)(bias + gcol);
            #pragma unroll
            for (int mi = 0; mi < MI; mi++) {
                int grow = bm * BM + wm + mi * 16 + (lane >> 2);
                float2 v0 = { acc[mi][nj][0] + bv.x, acc[mi][nj][1] + bv.y };
                float2 v1 = { acc[mi][nj][2] + bv.x, acc[mi][nj][3] + bv.y };
                *(float2*)(C + (size_t)grow * N + gcol)       = v0;
                *(float2*)(C + (size_t)(grow + 8) * N + gcol) = v1;
            }
        }
    } else {
        // ---- fused RoPE + head-split epilogue (BM==128) ----
        CP_WAIT_0();
        __syncthreads();
        float* ep = (float*)dsm;   // [128][132] fp32 = 67584 B (fits in 81920)

        #pragma unroll
        for (int nj = 0; nj < 4; nj++) {
            int colq = wn + nj * 8 + (lane & 3) * 2;
            float2 bv = *(const float2*)(bias + bn * 128 + colq);
            #pragma unroll
            for (int mi = 0; mi < MI; mi++) {
                int row = wm + mi * 16 + (lane >> 2);
                ep[row * 132 + colq]           = acc[mi][nj][0] + bv.x;
                ep[row * 132 + colq + 1]       = acc[mi][nj][1] + bv.y;
                ep[(row + 8) * 132 + colq]     = acc[mi][nj][2] + bv.x;
                ep[(row + 8) * 132 + colq + 1] = acc[mi][nj][3] + bv.y;
            }
        }
        __syncthreads();

        const int rr  = tid >> 3;
        const int sub = tid & 7;
        const int hh  = sub >> 2;
        const int qq  = sub & 3;
        const int sec = bn / 6;            // 0=q 1=k 2=v
        const int hd  = (bn % 6) * 2 + hh;
        float* dst = (sec == 0) ? g_q : (sec == 1) ? g_k : g_v;

        float invf[8];
        if (sec < 2) {
            #pragma unroll
            for (int e = 0; e < 8; e++)
                invf[e] = exp2f(-(float)(qq * 8 + e) * ROPE_C);
        }

        #pragma unroll
        for (int rg = 0; rg < 4; rg++) {
            int r = rg * 32 + rr;
            int l = bm * 128 + r;
            const float* er = ep + r * 132 + hh * 64 + qq * 8;
            float x1[8], x2[8];
            *(float4*)&x1[0] = *(const float4*)er;
            *(float4*)&x1[4] = *(const float4*)(er + 4);
            *(float4*)&x2[0] = *(const float4*)(er + 32);
            *(float4*)&x2[4] = *(const float4*)(er + 36);
            float o1[8], o2[8];
            if (sec == 2) {
                #pragma unroll
                for (int e = 0; e < 8; e++) { o1[e] = x1[e]; o2[e] = x2[e]; }
            } else {
                #pragma unroll
                for (int e = 0; e < 8; e++) {
                    float s, c;
                    sincosf((float)l * invf[e], &s, &c);
                    o1[e] = x1[e] * c - x2[e] * s;
                    o2[e] = x1[e] * s + x2[e] * c;
                }
            }
            float* dp = dst + ((size_t)hd * L + l) * HD + qq * 8;
            *(float4*)dp        = *(float4*)&o1[0];
            *(float4*)(dp + 4)  = *(float4*)&o1[4];
            *(float4*)(dp + 32) = *(float4*)&o2[0];
            *(float4*)(dp + 36) = *(float4*)&o2[4];
        }
    }
}

// ====================== sliding-window attention (TQ=32) ======================
__global__ void __launch_bounds__(1024) window_attn_kernel(const int* __restrict__ mask) {
    extern __shared__ float sm[];
    float* ks = sm;                        // WROWS * WSTRIDE
    float* qs = ks + WROWS * WSTRIDE;      // TQ * 64
    float* ws = qs + TQ * HD;              // TQ * 128
    int*   rv = (int*)(ws + TQ * WIN);     // WROWS

    int h  = blockIdx.x / (L / TQ);
    int qt = blockIdx.x % (L / TQ);
    int l0 = qt * TQ;
    int lo = l0 - 64;
    int tid = threadIdx.x;

    for (int idx = tid; idx < WROWS; idx += 1024) {
        int lr = lo + idx;
        rv[idx] = (lr >= 0 && lr < L) ? (mask[lr] != 0) : 0;
    }
    for (int idx = tid; idx < WROWS * HD; idx += 1024) {
        int r = idx >> 6, d = idx & 63;
        int lr = lo + r;
        bool val = (lr >= 0 && lr < L);
        ks[r*WSTRIDE + d] = val ? g_k[(h*L + (val ? lr : 0))*HD + d] : 0.0f;
    }
    for (int idx = tid; idx < TQ * HD; idx += 1024) {
        qs[idx] = g_q[(h*L + l0)*HD + idx];
    }
    __syncthreads();

    int wq   = tid >> 5;
    int lane = tid & 31;
    int l = l0 + wq;

    const float4* qs4 = (const float4*)(qs + wq*HD);
    const float4* kp0 = (const float4*)(ks + (wq + lane      )*WSTRIDE);
    const float4* kp1 = (const float4*)(ks + (wq + lane +  32)*WSTRIDE);
    const float4* kp2 = (const float4*)(ks + (wq + lane +  64)*WSTRIDE);
    const float4* kp3 = (const float4*)(ks + (wq + lane +  96)*WSTRIDE);
    float sc[4] = {0.f, 0.f, 0.f, 0.f};
    #pragma unroll
    for (int d4 = 0; d4 < 16; d4++) {
        float4 qq = qs4[d4];
        float4 k0 = kp0[d4], k1 = kp1[d4], k2 = kp2[d4], k3 = kp3[d4];
        sc[0] += k0.x*qq.x + k0.y*qq.y + k0.z*qq.z + k0.w*qq.w;
        sc[1] += k1.x*qq.x + k1.y*qq.y + k1.z*qq.z + k1.w*qq.w;
        sc[2] += k2.x*qq.x + k2.y*qq.y + k2.z*qq.z + k2.w*qq.w;
        sc[3] += k3.x*qq.x + k3.y*qq.y + k3.z*qq.z + k3.w*qq.w;
    }
    #pragma unroll
    for (int w4 = 0; w4 < 4; w4++)
        sc[w4] = rv[wq + lane + w4*32] ? sc[w4] * SCALE : -1e30f;

    float m = fmaxf(fmaxf(sc[0], sc[1]), fmaxf(sc[2], sc[3]));
    #pragma unroll
    for (int o = 16; o > 0; o >>= 1) m = fmaxf(m, __shfl_xor_sync(0xffffffffu, m, o));
    float e[4], sum = 0.f;
    #pragma unroll
    for (int w4 = 0; w4 < 4; w4++) { e[w4] = expf(sc[w4] - m); sum += e[w4]; }
    #pragma unroll
    for (int o = 16; o > 0; o >>= 1) sum += __shfl_xor_sync(0xffffffffu, sum, o);
    float inv = 1.0f / sum;
    #pragma unroll
    for (int w4 = 0; w4 < 4; w4++) ws[wq*WIN + lane + w4*32] = e[w4] * inv;
    __syncwarp();

    const int wpair = lane >> 4;
    const int chunk = lane & 15;
    float4 a4 = {0.f, 0.f, 0.f, 0.f};
    const float* vbase = g_v + (size_t)h*L*HD + chunk*4;
    #pragma unroll 4
    for (int w = 0; w < WIN; w += 2) {
        float wt = ws[wq*WIN + w + wpair];
        int lr = lo + wq + w + wpair;
        lr = lr < 0 ? 0 : (lr > L-1 ? L-1 : lr);
        float4 v = *(const float4*)(vbase + (size_t)lr*HD);
        a4.x += wt * v.x;
        a4.y += wt * v.y;
        a4.z += wt * v.z;
        a4.w += wt * v.w;
    }
    a4.x += __shfl_xor_sync(0xffffffffu, a4.x, 16);
    a4.y += __shfl_xor_sync(0xffffffffu, a4.y, 16);
    a4.z += __shfl_xor_sync(0xffffffffu, a4.z, 16);
    a4.w += __shfl_xor_sync(0xffffffffu, a4.w, 16);

    if (wpair == 0) {
        __half2 hA, hB;
        hA.x = __float2half_rn(a4.x); hA.y = __float2half_rn(a4.y);
        hB.x = __float2half_rn(a4.z); hB.y = __float2half_rn(a4.w);
        size_t o = (size_t)l*DM + h*HD + chunk*4;
        *(__half2*)(g_Cf + o)     = hA;
        *(__half2*)(g_Cf + o + 2) = hB;
    }
}

// ====================== CLS split-softmax ======================================
__global__ void __launch_bounds__(128) cls_part_kernel(const int* __restrict__ mask) {
    extern __shared__ float smc[];
    float* ksm = smc;
    float* q0  = ksm + CKEYS*65;
    float* ew  = q0 + HD;
    float* red = ew + CKEYS;

    int c = blockIdx.x, h = blockIdx.y;
    int tid = threadIdx.x;
    int base = c * CKEYS;

    if (tid < HD) q0[tid] = g_q[(size_t)(h*L)*HD + tid];
    for (int idx = tid; idx < CKEYS*HD; idx += 128) {
        int key = idx >> 6, d = idx & 63;
        ksm[key*65 + d] = g_k[(size_t)(h*L + base + key)*HD + d];
    }
    __syncthreads();

    float s = 0.f;
    #pragma unroll
    for (int d = 0; d < HD; d++) s += ksm[tid*65 + d] * q0[d];
    s = (mask[base + tid] != 0) ? s * SCALE : -1e30f;

    red[tid] = s; __syncthreads();
    for (int o = 64; o > 0; o >>= 1) {
        if (tid < o) red[tid] = fmaxf(red[tid], red[tid + o]);
        __syncthreads();
    }
    float m_c = red[0];
    __syncthreads();

    float e = expf(s - m_c);
    ew[tid] = e;
    red[tid] = e; __syncthreads();
    for (int o = 64; o > 0; o >>= 1) {
        if (tid < o) red[tid] += red[tid + o];
        __syncthreads();
    }
    float s_c = red[0];
    __syncthreads();

    int d = tid & 63, half = tid >> 6;
    const float* vb = g_v + (size_t)(h*L + base + half*64)*HD + d;
    float acc = 0.f;
    #pragma unroll 8
    for (int kk = 0; kk < 64; kk++)
        acc += ew[half*64 + kk] * vb[(size_t)kk*HD];
    red[tid] = acc; __syncthreads();
    if (tid < HD) {
        g_cls_o[(size_t)(h*NCHUNK + c)*HD + tid] = red[tid] + red[HD + tid];
        if (tid == 0) { g_cls_m[h*NCHUNK + c] = m_c; g_cls_s[h*NCHUNK + c] = s_c; }
    }
}

__global__ void __launch_bounds__(768) cls_combine_kernel() {
    int tid = threadIdx.x;
    int h = tid >> 6, d = tid & 63;
    float m = -1e30f;
    #pragma unroll
    for (int c = 0; c < NCHUNK; c++) m = fmaxf(m, g_cls_m[h*NCHUNK + c]);
    float den = 0.f, num = 0.f;
    #pragma unroll
    for (int c = 0; c < NCHUNK; c++) {
        float w = expf(g_cls_m[h*NCHUNK + c] - m);
        den += g_cls_s[h*NCHUNK + c] * w;
        num += g_cls_o[(size_t)(h*NCHUNK + c)*HD + d] * w;
    }
    g_Cf[h*HD + d] = __float2half_rn(num / den);
}

// ====================== stream/event resources =================================
struct GraphRes {
    cudaStream_t s1, s2;
    cudaEvent_t eF1, eWq, eWo, eF2, eWin, eCls;
    GraphRes() {
        cudaStreamCreateWithFlags(&s1, cudaStreamNonBlocking);
        cudaStreamCreateWithFlags(&s2, cudaStreamNonBlocking);
        cudaEventCreateWithFlags(&eF1,  cudaEventDisableTiming);
        cudaEventCreateWithFlags(&eWq,  cudaEventDisableTiming);
        cudaEventCreateWithFlags(&eWo,  cudaEventDisableTiming);
        cudaEventCreateWithFlags(&eF2,  cudaEventDisableTiming);
        cudaEventCreateWithFlags(&eWin, cudaEventDisableTiming);
        cudaEventCreateWithFlags(&eCls, cudaEventDisableTiming);
    }
};

// ====================== launch =================================================
extern "C" void kernel_launch(void* const* d_in, const int* in_sizes, int n_in,
                              void* d_out, int out_size) {
    (void)in_sizes; (void)n_in; (void)out_size;
    const float* emb   = (const float*)d_in[0];
    const int*   mask  = (const int*)  d_in[1];
    const float* W_qkv = (const float*)d_in[2];
    const float* b_qkv = (const float*)d_in[3];
    const float* W_o   = (const float*)d_in[4];
    const float* b_o   = (const float*)d_in[5];
    float* out = (float*)d_out;

    static GraphRes R;

    __half *p_Af, *p_Wqf, *p_Wof, *p_Cf;
    cudaGetSymbolAddress((void**)&p_Af,  g_Af);
    cudaGetSymbolAddress((void**)&p_Wqf, g_Wqf);
    cudaGetSymbolAddress((void**)&p_Wof, g_Wof);
    cudaGetSymbolAddress((void**)&p_Cf,  g_Cf);

    constexpr int GSMEM128 = FNST * (128 + 128) * SMSTRIDE * 2;  // 81920 B
    constexpr int GSMEM64  = FNST * (64  + 128) * SMSTRIDE * 2;  // 61440 B
    cudaFuncSetAttribute((const void*)gemm_f16<128,true>,
                         cudaFuncAttributeMaxDynamicSharedMemorySize, GSMEM128);
    cudaFuncSetAttribute((const void*)gemm_f16<64,false>,
                         cudaFuncAttributeMaxDynamicSharedMemorySize, GSMEM64);
    constexpr int SMEM_WIN = (WROWS*WSTRIDE + TQ*HD + TQ*WIN) * 4 + WROWS * 4;
    cudaFuncSetAttribute(window_attn_kernel,
                         cudaFuncAttributeMaxDynamicSharedMemorySize, SMEM_WIN);
    constexpr int SMEM_CLS = (CKEYS*65 + HD + CKEYS + 128) * 4;
    cudaFuncSetAttribute(cls_part_kernel,
                         cudaFuncAttributeMaxDynamicSharedMemorySize, SMEM_CLS);

    // ---- fork 1: emb f16 (s0) || W_qkv transpose (s1) || W_o transpose (s2)
    cudaEventRecord(R.eF1, 0);
    cudaStreamWaitEvent(R.s1, R.eF1, 0);
    cudaStreamWaitEvent(R.s2, R.eF1, 0);

    to_f16<<<(L*DM + 255)/256, 256, 0, 0>>>(emb, p_Af, L*DM);
    transpose_f16<<<dim3((3*DM)/32, DM/32), dim3(32,8), 0, R.s1>>>(W_qkv, p_Wqf, DM, 3*DM);
    transpose_f16<<<dim3(DM/32, DM/32),     dim3(32,8), 0, R.s2>>>(W_o,   p_Wof, DM, DM);
    cudaEventRecord(R.eWq, R.s1);
    cudaEventRecord(R.eWo, R.s2);

    // ---- gemm1 (fp16, fused RoPE+split) -> g_q/g_k/g_v
    cudaStreamWaitEvent(0, R.eWq, 0);
    gemm_f16<128,true><<<dim3((3*DM)/128, L/128), 256, GSMEM128, 0>>>(
        p_Af, p_Wqf, b_qkv, nullptr, 3*DM, DM);

    // ---- fork 2: window (s0) || cls_part (s1)
    cudaEventRecord(R.eF2, 0);
    cudaStreamWaitEvent(R.s1, R.eF2, 0);
    cls_part_kernel<<<dim3(NCHUNK, H), 128, SMEM_CLS, R.s1>>>(mask);

    window_attn_kernel<<<H * (L/TQ), 1024, SMEM_WIN, 0>>>(mask);
    cudaEventRecord(R.eWin, 0);

    cudaStreamWaitEvent(R.s1, R.eWin, 0);
    cls_combine_kernel<<<1, 768, 0, R.s1>>>();
    cudaEventRecord(R.eCls, R.s1);

    // ---- join: gemm2 (fp16)
    cudaStreamWaitEvent(0, R.eCls, 0);
    cudaStreamWaitEvent(0, R.eWo, 0);
    gemm_f16<64,false><<<dim3(DM/128, L/64), 256, GSMEM64, 0>>>(
        p_Cf, p_Wof, b_o, out, DM, DM);
}

// round 13
// speedup vs baseline: 2.8477x; 1.0276x over previous
#include <cuda_runtime.h>
#include <cuda_fp16.h>
#include <math.h>
#include <stdint.h>

#define L    2048
#define DM   768
#define H    12
#define HD   64
#define WIN  128
#define TQ   32
#define WROWS 160
#define NCHUNK 16
#define CKEYS  128
#define WSTRIDE 68

static constexpr float SCALE = 0.03608439182435161f;  // 1/sqrt(768)
static constexpr float ROPE_C = 0.41524101186092029f; // log2(10000)/32

// ====================== scratch ================================================
__device__ float g_q[H * L * HD];
__device__ float g_k[H * L * HD];
__device__ float g_v[H * L * HD];
__device__ float g_cls_m[H * NCHUNK];
__device__ float g_cls_s[H * NCHUNK];
__device__ float g_cls_o[H * NCHUNK * HD];

__device__ __half g_Af[L * DM];          // emb fp16
__device__ __half g_Wqf[3*DM*DM];        // W_qkv^T fp16 [2304][768]
__device__ __half g_Wof[DM*DM];          // W_o^T fp16 [768][768]
__device__ __half g_Cf[L * DM];          // attn-out fp16

// ====================== prep kernels ==========================================
__global__ void __launch_bounds__(256) to_f16(const float* __restrict__ x,
        __half* __restrict__ y, int n) {
    int i = blockIdx.x * 256 + threadIdx.x;
    if (i < n) y[i] = __float2half_rn(x[i]);
}

// W [K,N] fp32 row-major -> T [N,K] fp16 row-major
__global__ void __launch_bounds__(256) transpose_f16(const float* __restrict__ W,
        __half* __restrict__ T, int K, int N) {
    __shared__ float t[32][33];
    int n0 = blockIdx.x * 32, k0 = blockIdx.y * 32;
    int tx = threadIdx.x, ty = threadIdx.y;
    #pragma unroll
    for (int i = ty; i < 32; i += 8)
        t[i][tx] = W[(size_t)(k0 + i) * N + n0 + tx];
    __syncthreads();
    #pragma unroll
    for (int i = ty; i < 32; i += 8)
        T[(size_t)(n0 + i) * K + k0 + tx] = __float2half_rn(t[tx][i]);
}

// ====================== mma.sync helpers ======================================
__device__ __forceinline__ uint32_t smem_u32(const void* p) {
    uint32_t a;
    asm("{ .reg .u64 t; cvta.to.shared.u64 t, %1; cvt.u32.u64 %0, t; }" : "=r"(a) : "l"(p));
    return a;
}
__device__ __forceinline__ void ldsm_x4(uint32_t& r0, uint32_t& r1, uint32_t& r2, uint32_t& r3,
                                        uint32_t addr) {
    asm volatile("ldmatrix.sync.aligned.m8n8.x4.shared.b16 {%0,%1,%2,%3}, [%4];"
                 : "=r"(r0), "=r"(r1), "=r"(r2), "=r"(r3) : "r"(addr));
}
__device__ __forceinline__ void mma_f16(float* d, const uint32_t* a, const uint32_t* b) {
    asm volatile("mma.sync.aligned.m16n8k16.row.col.f32.f16.f16.f32 "
                 "{%0,%1,%2,%3}, {%4,%5,%6,%7}, {%8,%9}, {%0,%1,%2,%3};"
                 : "+f"(d[0]), "+f"(d[1]), "+f"(d[2]), "+f"(d[3])
                 : "r"(a[0]), "r"(a[1]), "r"(a[2]), "r"(a[3]), "r"(b[0]), "r"(b[1]));
}
#define CP_ASYNC_16(dst, src) \
    asm volatile("cp.async.cg.shared.global [%0], [%1], 16;" :: "r"(dst), "l"(src))
#define CP_COMMIT() asm volatile("cp.async.commit_group;" ::: "memory")
#define CP_WAIT_1() asm volatile("cp.async.wait_group 1;" ::: "memory")
#define CP_WAIT_0() asm volatile("cp.async.wait_group 0;" ::: "memory")

// ====================== HMMA fp16 single-pass GEMM (BK=64 stages) =============
// C[M,N] = A[M,K] @ B[N,K]^T + bias. 2-stage double buffer, 64-K per stage.
// ROPE=true: fused RoPE + head-split epilogue writes g_q/g_k/g_v directly.
#define SMSTRIDE 72     // halves per row: 64 data + 8 pad (rows 144B apart -> conflict-free ldsm)
#define FNST 2

template<int BM, bool ROPE>
__global__ void __launch_bounds__(256, 2)
gemm_f16(const __half* __restrict__ A, const __half* __restrict__ B,
         const float* __restrict__ bias, float* __restrict__ C,
         int N, int K) {
    constexpr int MI  = BM / 32;
    constexpr int ACH = BM / 32;          // 16B chunks per thread for A stage (BM*8/256)
    constexpr int A_STAGE = BM * SMSTRIDE;
    constexpr int B_STAGE = 128 * SMSTRIDE;

    extern __shared__ __align__(16) __half dsm[];
    __half* As = dsm;
    __half* Bs = dsm + FNST * A_STAGE;

    const int tid  = threadIdx.x;
    const int wid  = tid >> 5;
    const int lane = tid & 31;
    const int bn = blockIdx.x, bm = blockIdx.y;
    const int wm = (wid >> 2) * (BM / 2);
    const int wn = (wid & 3) * 32;

    const int KT = K >> 6;    // 64-K stages (12 for K=768)

    float acc[MI][4][4] = {};

    auto load_stage = [&](int kt, int buf) {
        const __half* Ag = A + (size_t)bm * BM * K + kt * 64;
        const __half* Bg = B + (size_t)bn * 128 * K + kt * 64;
        uint32_t a_s = smem_u32(As + buf * A_STAGE);
        uint32_t b_s = smem_u32(Bs + buf * B_STAGE);
        #pragma unroll
        for (int i = 0; i < ACH; i++) {
            int ch = tid + i * 256;          // BM*8 chunks; 8 chunks per 64-half row
            int r = ch >> 3, cc = (ch & 7) * 8;
            CP_ASYNC_16(a_s + (uint32_t)(r * SMSTRIDE + cc) * 2, Ag + (size_t)r * K + cc);
        }
        #pragma unroll
        for (int i = 0; i < 4; i++) {
            int ch = tid + i * 256;          // 1024 chunks
            int r = ch >> 3, cc = (ch & 7) * 8;
            CP_ASYNC_16(b_s + (uint32_t)(r * SMSTRIDE + cc) * 2, Bg + (size_t)r * K + cc);
        }
    };

    load_stage(0, 0); CP_COMMIT();
    load_stage(1, 1); CP_COMMIT();

    for (int kt = 0; kt < KT; kt++) {
        const int buf = kt & 1;
        CP_WAIT_1();
        __syncthreads();

        const uint32_t a_base = smem_u32(As + buf * A_STAGE);
        const uint32_t b_base = smem_u32(Bs + buf * B_STAGE);

        #pragma unroll
        for (int ks = 0; ks < 4; ks++) {
            uint32_t af[MI][4], bf[4][2];
            const int acol = ks * 16 + ((lane & 16) ? 8 : 0);
            const int bgrp = lane >> 3;
            #pragma unroll
            for (int mi = 0; mi < MI; mi++) {
                int row = wm + mi * 16 + (lane & 7) + ((lane & 8) ? 8 : 0);
                ldsm_x4(af[mi][0], af[mi][1], af[mi][2], af[mi][3],
                        a_base + (uint32_t)(row * SMSTRIDE + acol) * 2);
            }
            #pragma unroll
            for (int njp = 0; njp < 2; njp++) {
                int row = wn + (njp * 2 + (bgrp >> 1)) * 8 + (lane & 7);
                int col = ks * 16 + (bgrp & 1) * 8;
                uint32_t r0, r1, r2, r3;
                ldsm_x4(r0, r1, r2, r3, b_base + (uint32_t)(row * SMSTRIDE + col) * 2);
                bf[njp*2][0] = r0;  bf[njp*2][1] = r1;
                bf[njp*2+1][0] = r2; bf[njp*2+1][1] = r3;
            }
            #pragma unroll
            for (int mi = 0; mi < MI; mi++)
                #pragma unroll
                for (int nj = 0; nj < 4; nj++)
                    mma_f16(acc[mi][nj], af[mi], bf[nj]);
        }

        __syncthreads();
        int nkt = kt + 2 < KT ? kt + 2 : KT - 1;   // clamp keeps one real commit per iter
        load_stage(nkt, buf);
        CP_COMMIT();
    }

    if (!ROPE) {
        #pragma unroll
        for (int nj = 0; nj < 4; nj++) {
            int gcol = bn * 128 + wn + nj * 8 + (lane & 3) * 2;
            float2 bv = *(const float2*)(bias + gcol);
            #pragma unroll
            for (int mi = 0; mi < MI; mi++) {
                int grow = bm * BM + wm + mi * 16 + (lane >> 2);
                float2 v0 = { acc[mi][nj][0] + bv.x, acc[mi][nj][1] + bv.y };
                float2 v1 = { acc[mi][nj][2] + bv.x, acc[mi][nj][3] + bv.y };
                *(float2*)(C + (size_t)grow * N + gcol)       = v0;
                *(float2*)(C + (size_t)(grow + 8) * N + gcol) = v1;
            }
        }
    } else {
        // ---- fused RoPE + head-split epilogue (BM==128) ----
        CP_WAIT_0();
        __syncthreads();
        float* ep = (float*)dsm;   // [128][132] fp32 = 67584 B (fits in 73728)

        #pragma unroll
        for (int nj = 0; nj < 4; nj++) {
            int colq = wn + nj * 8 + (lane & 3) * 2;
            float2 bv = *(const float2*)(bias + bn * 128 + colq);
            #pragma unroll
            for (int mi = 0; mi < MI; mi++) {
                int row = wm + mi * 16 + (lane >> 2);
                ep[row * 132 + colq]           = acc[mi][nj][0] + bv.x;
                ep[row * 132 + colq + 1]       = acc[mi][nj][1] + bv.y;
                ep[(row + 8) * 132 + colq]     = acc[mi][nj][2] + bv.x;
                ep[(row + 8) * 132 + colq + 1] = acc[mi][nj][3] + bv.y;
            }
        }
        __syncthreads();

        const int rr  = tid >> 3;
        const int sub = tid & 7;
        const int hh  = sub >> 2;
        const int qq  = sub & 3;
        const int sec = bn / 6;            // 0=q 1=k 2=v
        const int hd  = (bn % 6) * 2 + hh;
        float* dst = (sec == 0) ? g_q : (sec == 1) ? g_k : g_v;

        float invf[8];
        if (sec < 2) {
            #pragma unroll
            for (int e = 0; e < 8; e++)
                invf[e] = exp2f(-(float)(qq * 8 + e) * ROPE_C);
        }

        #pragma unroll
        for (int rg = 0; rg < 4; rg++) {
            int r = rg * 32 + rr;
            int l = bm * 128 + r;
            const float* er = ep + r * 132 + hh * 64 + qq * 8;
            float x1[8], x2[8];
            *(float4*)&x1[0] = *(const float4*)er;
            *(float4*)&x1[4] = *(const float4*)(er + 4);
            *(float4*)&x2[0] = *(const float4*)(er + 32);
            *(float4*)&x2[4] = *(const float4*)(er + 36);
            float o1[8], o2[8];
            if (sec == 2) {
                #pragma unroll
                for (int e = 0; e < 8; e++) { o1[e] = x1[e]; o2[e] = x2[e]; }
            } else {
                #pragma unroll
                for (int e = 0; e < 8; e++) {
                    float s, c;
                    sincosf((float)l * invf[e], &s, &c);
                    o1[e] = x1[e] * c - x2[e] * s;
                    o2[e] = x1[e] * s + x2[e] * c;
                }
            }
            float* dp = dst + ((size_t)hd * L + l) * HD + qq * 8;
            *(float4*)dp        = *(float4*)&o1[0];
            *(float4*)(dp + 4)  = *(float4*)&o1[4];
            *(float4*)(dp + 32) = *(float4*)&o2[0];
            *(float4*)(dp + 36) = *(float4*)&o2[4];
        }
    }
}

// ====================== sliding-window attention (TQ=32) ======================
__global__ void __launch_bounds__(1024) window_attn_kernel(const int* __restrict__ mask) {
    extern __shared__ float sm[];
    float* ks = sm;                        // WROWS * WSTRIDE
    float* qs = ks + WROWS * WSTRIDE;      // TQ * 64
    float* ws = qs + TQ * HD;              // TQ * 128
    int*   rv = (int*)(ws + TQ * WIN);     // WROWS

    int h  = blockIdx.x / (L / TQ);
    int qt = blockIdx.x % (L / TQ);
    int l0 = qt * TQ;
    int lo = l0 - 64;
    int tid = threadIdx.x;

    for (int idx = tid; idx < WROWS; idx += 1024) {
        int lr = lo + idx;
        rv[idx] = (lr >= 0 && lr < L) ? (mask[lr] != 0) : 0;
    }
    for (int idx = tid; idx < WROWS * HD; idx += 1024) {
        int r = idx >> 6, d = idx & 63;
        int lr = lo + r;
        bool val = (lr >= 0 && lr < L);
        ks[r*WSTRIDE + d] = val ? g_k[(h*L + (val ? lr : 0))*HD + d] : 0.0f;
    }
    for (int idx = tid; idx < TQ * HD; idx += 1024) {
        qs[idx] = g_q[(h*L + l0)*HD + idx];
    }
    __syncthreads();

    int wq   = tid >> 5;
    int lane = tid & 31;
    int l = l0 + wq;

    const float4* qs4 = (const float4*)(qs + wq*HD);
    const float4* kp0 = (const float4*)(ks + (wq + lane      )*WSTRIDE);
    const float4* kp1 = (const float4*)(ks + (wq + lane +  32)*WSTRIDE);
    const float4* kp2 = (const float4*)(ks + (wq + lane +  64)*WSTRIDE);
    const float4* kp3 = (const float4*)(ks + (wq + lane +  96)*WSTRIDE);
    float sc[4] = {0.f, 0.f, 0.f, 0.f};
    #pragma unroll
    for (int d4 = 0; d4 < 16; d4++) {
        float4 qq = qs4[d4];
        float4 k0 = kp0[d4], k1 = kp1[d4], k2 = kp2[d4], k3 = kp3[d4];
        sc[0] += k0.x*qq.x + k0.y*qq.y + k0.z*qq.z + k0.w*qq.w;
        sc[1] += k1.x*qq.x + k1.y*qq.y + k1.z*qq.z + k1.w*qq.w;
        sc[2] += k2.x*qq.x + k2.y*qq.y + k2.z*qq.z + k2.w*qq.w;
        sc[3] += k3.x*qq.x + k3.y*qq.y + k3.z*qq.z + k3.w*qq.w;
    }
    #pragma unroll
    for (int w4 = 0; w4 < 4; w4++)
        sc[w4] = rv[wq + lane + w4*32] ? sc[w4] * SCALE : -1e30f;

    float m = fmaxf(fmaxf(sc[0], sc[1]), fmaxf(sc[2], sc[3]));
    #pragma unroll
    for (int o = 16; o > 0; o >>= 1) m = fmaxf(m, __shfl_xor_sync(0xffffffffu, m, o));
    float e[4], sum = 0.f;
    #pragma unroll
    for (int w4 = 0; w4 < 4; w4++) { e[w4] = expf(sc[w4] - m); sum += e[w4]; }
    #pragma unroll
    for (int o = 16; o > 0; o >>= 1) sum += __shfl_xor_sync(0xffffffffu, sum, o);
    float inv = 1.0f / sum;
    #pragma unroll
    for (int w4 = 0; w4 < 4; w4++) ws[wq*WIN + lane + w4*32] = e[w4] * inv;
    __syncwarp();

    const int wpair = lane >> 4;
    const int chunk = lane & 15;
    float4 a4 = {0.f, 0.f, 0.f, 0.f};
    const float* vbase = g_v + (size_t)h*L*HD + chunk*4;
    #pragma unroll 4
    for (int w = 0; w < WIN; w += 2) {
        float wt = ws[wq*WIN + w + wpair];
        int lr = lo + wq + w + wpair;
        lr = lr < 0 ? 0 : (lr > L-1 ? L-1 : lr);
        float4 v = *(const float4*)(vbase + (size_t)lr*HD);
        a4.x += wt * v.x;
        a4.y += wt * v.y;
        a4.z += wt * v.z;
        a4.w += wt * v.w;
    }
    a4.x += __shfl_xor_sync(0xffffffffu, a4.x, 16);
    a4.y += __shfl_xor_sync(0xffffffffu, a4.y, 16);
    a4.z += __shfl_xor_sync(0xffffffffu, a4.z, 16);
    a4.w += __shfl_xor_sync(0xffffffffu, a4.w, 16);

    if (wpair == 0) {
        __half2 hA, hB;
        hA.x = __float2half_rn(a4.x); hA.y = __float2half_rn(a4.y);
        hB.x = __float2half_rn(a4.z); hB.y = __float2half_rn(a4.w);
        size_t o = (size_t)l*DM + h*HD + chunk*4;
        *(__half2*)(g_Cf + o)     = hA;
        *(__half2*)(g_Cf + o + 2) = hB;
    }
}

// ====================== CLS split-softmax ======================================
__global__ void __launch_bounds__(128) cls_part_kernel(const int* __restrict__ mask) {
    extern __shared__ float smc[];
    float* ksm = smc;
    float* q0  = ksm + CKEYS*65;
    float* ew  = q0 + HD;
    float* red = ew + CKEYS;

    int c = blockIdx.x, h = blockIdx.y;
    int tid = threadIdx.x;
    int base = c * CKEYS;

    if (tid < HD) q0[tid] = g_q[(size_t)(h*L)*HD + tid];
    for (int idx = tid; idx < CKEYS*HD; idx += 128) {
        int key = idx >> 6, d = idx & 63;
        ksm[key*65 + d] = g_k[(size_t)(h*L + base + key)*HD + d];
    }
    __syncthreads();

    float s = 0.f;
    #pragma unroll
    for (int d = 0; d < HD; d++) s += ksm[tid*65 + d] * q0[d];
    s = (mask[base + tid] != 0) ? s * SCALE : -1e30f;

    red[tid] = s; __syncthreads();
    for (int o = 64; o > 0; o >>= 1) {
        if (tid < o) red[tid] = fmaxf(red[tid], red[tid + o]);
        __syncthreads();
    }
    float m_c = red[0];
    __syncthreads();

    float e = expf(s - m_c);
    ew[tid] = e;
    red[tid] = e; __syncthreads();
    for (int o = 64; o > 0; o >>= 1) {
        if (tid < o) red[tid] += red[tid + o];
        __syncthreads();
    }
    float s_c = red[0];
    __syncthreads();

    int d = tid & 63, half = tid >> 6;
    const float* vb = g_v + (size_t)(h*L + base + half*64)*HD + d;
    float acc = 0.f;
    #pragma unroll 8
    for (int kk = 0; kk < 64; kk++)
        acc += ew[half*64 + kk] * vb[(size_t)kk*HD];
    red[tid] = acc; __syncthreads();
    if (tid < HD) {
        g_cls_o[(size_t)(h*NCHUNK + c)*HD + tid] = red[tid] + red[HD + tid];
        if (tid == 0) { g_cls_m[h*NCHUNK + c] = m_c; g_cls_s[h*NCHUNK + c] = s_c; }
    }
}

__global__ void __launch_bounds__(768) cls_combine_kernel() {
    int tid = threadIdx.x;
    int h = tid >> 6, d = tid & 63;
    float m = -1e30f;
    #pragma unroll
    for (int c = 0; c < NCHUNK; c++) m = fmaxf(m, g_cls_m[h*NCHUNK + c]);
    float den = 0.f, num = 0.f;
    #pragma unroll
    for (int c = 0; c < NCHUNK; c++) {
        float w = expf(g_cls_m[h*NCHUNK + c] - m);
        den += g_cls_s[h*NCHUNK + c] * w;
        num += g_cls_o[(size_t)(h*NCHUNK + c)*HD + d] * w;
    }
    g_Cf[h*HD + d] = __float2half_rn(num / den);
}

// ====================== stream/event resources =================================
struct GraphRes {
    cudaStream_t s1, s2;
    cudaEvent_t eF1, eWq, eWo, eF2, eWin, eCls;
    GraphRes() {
        cudaStreamCreateWithFlags(&s1, cudaStreamNonBlocking);
        cudaStreamCreateWithFlags(&s2, cudaStreamNonBlocking);
        cudaEventCreateWithFlags(&eF1,  cudaEventDisableTiming);
        cudaEventCreateWithFlags(&eWq,  cudaEventDisableTiming);
        cudaEventCreateWithFlags(&eWo,  cudaEventDisableTiming);
        cudaEventCreateWithFlags(&eF2,  cudaEventDisableTiming);
        cudaEventCreateWithFlags(&eWin, cudaEventDisableTiming);
        cudaEventCreateWithFlags(&eCls, cudaEventDisableTiming);
    }
};

// ====================== launch =================================================
extern "C" void kernel_launch(void* const* d_in, const int* in_sizes, int n_in,
                              void* d_out, int out_size) {
    (void)in_sizes; (void)n_in; (void)out_size;
    const float* emb   = (const float*)d_in[0];
    const int*   mask  = (const int*)  d_in[1];
    const float* W_qkv = (const float*)d_in[2];
    const float* b_qkv = (const float*)d_in[3];
    const float* W_o   = (const float*)d_in[4];
    const float* b_o   = (const float*)d_in[5];
    float* out = (float*)d_out;

    static GraphRes R;

    __half *p_Af, *p_Wqf, *p_Wof, *p_Cf;
    cudaGetSymbolAddress((void**)&p_Af,  g_Af);
    cudaGetSymbolAddress((void**)&p_Wqf, g_Wqf);
    cudaGetSymbolAddress((void**)&p_Wof, g_Wof);
    cudaGetSymbolAddress((void**)&p_Cf,  g_Cf);

    constexpr int GSMEM128 = FNST * (128 + 128) * SMSTRIDE * 2;  // 73728 B
    constexpr int GSMEM64  = FNST * (64  + 128) * SMSTRIDE * 2;  // 55296 B
    cudaFuncSetAttribute((const void*)gemm_f16<128,true>,
                         cudaFuncAttributeMaxDynamicSharedMemorySize, GSMEM128);
    cudaFuncSetAttribute((const void*)gemm_f16<64,false>,
                         cudaFuncAttributeMaxDynamicSharedMemorySize, GSMEM64);
    constexpr int SMEM_WIN = (WROWS*WSTRIDE + TQ*HD + TQ*WIN) * 4 + WROWS * 4;
    cudaFuncSetAttribute(window_attn_kernel,
                         cudaFuncAttributeMaxDynamicSharedMemorySize, SMEM_WIN);
    constexpr int SMEM_CLS = (CKEYS*65 + HD + CKEYS + 128) * 4;
    cudaFuncSetAttribute(cls_part_kernel,
                         cudaFuncAttributeMaxDynamicSharedMemorySize, SMEM_CLS);

    // ---- fork 1: emb f16 (s0) || W_qkv transpose (s1) || W_o transpose (s2)
    cudaEventRecord(R.eF1, 0);
    cudaStreamWaitEvent(R.s1, R.eF1, 0);
    cudaStreamWaitEvent(R.s2, R.eF1, 0);

    to_f16<<<(L*DM + 255)/256, 256, 0, 0>>>(emb, p_Af, L*DM);
    transpose_f16<<<dim3((3*DM)/32, DM/32), dim3(32,8), 0, R.s1>>>(W_qkv, p_Wqf, DM, 3*DM);
    transpose_f16<<<dim3(DM/32, DM/32),     dim3(32,8), 0, R.s2>>>(W_o,   p_Wof, DM, DM);
    cudaEventRecord(R.eWq, R.s1);
    cudaEventRecord(R.eWo, R.s2);

    // ---- gemm1 (fp16, fused RoPE+split) -> g_q/g_k/g_v
    cudaStreamWaitEvent(0, R.eWq, 0);
    gemm_f16<128,true><<<dim3((3*DM)/128, L/128), 256, GSMEM128, 0>>>(
        p_Af, p_Wqf, b_qkv, nullptr, 3*DM, DM);

    // ---- fork 2: window (s0) || cls_part (s1)
    cudaEventRecord(R.eF2, 0);
    cudaStreamWaitEvent(R.s1, R.eF2, 0);
    cls_part_kernel<<<dim3(NCHUNK, H), 128, SMEM_CLS, R.s1>>>(mask);

    window_attn_kernel<<<H * (L/TQ), 1024, SMEM_WIN, 0>>>(mask);
    cudaEventRecord(R.eWin, 0);

    cudaStreamWaitEvent(R.s1, R.eWin, 0);
    cls_combine_kernel<<<1, 768, 0, R.s1>>>();
    cudaEventRecord(R.eCls, R.s1);

    // ---- join: gemm2 (fp16)
    cudaStreamWaitEvent(0, R.eCls, 0);
    cudaStreamWaitEvent(0, R.eWo, 0);
    gemm_f16<64,false><<<dim3(DM/128, L/64), 256, GSMEM64, 0>>>(
        p_Cf, p_Wof, b_o, out, DM, DM);
}

// round 14
// speedup vs baseline: 2.9776x; 1.0456x over previous
#include <cuda_runtime.h>
#include <cuda_fp16.h>
#include <math.h>
#include <stdint.h>

#define L    2048
#define DM   768
#define H    12
#define HD   64
#define WIN  128
#define TQ   32
#define WROWS 160
#define NCHUNK 16
#define CKEYS  128
#define WSTRIDE 68

static constexpr float SCALE = 0.03608439182435161f;  // 1/sqrt(768)
static constexpr float ROPE_C = 0.41524101186092029f; // log2(10000)/32

// ====================== scratch ================================================
__device__ float g_q[H * L * HD];
__device__ float g_k[H * L * HD];
__device__ float g_v[H * L * HD];
__device__ float g_cls_m[H * NCHUNK];
__device__ float g_cls_s[H * NCHUNK];
__device__ float g_cls_o[H * NCHUNK * HD];

__device__ __half g_Af[L * DM];          // emb fp16
__device__ __half g_Wqf[3*DM*DM];        // W_qkv^T fp16 [2304][768]
__device__ __half g_Wof[DM*DM];          // W_o^T fp16 [768][768]
__device__ __half g_Cf[L * DM];          // attn-out fp16

// ====================== fused prep kernel ======================================
// sections: [0, NB_A): emb->f16 ; [NB_A, NB_A+NB_WQ): W_qkv transpose ;
//           [NB_A+NB_WQ, +NB_WO): W_o transpose.  256 threads.
#define NB_A  ((L*DM)/256)            // 6144
#define NB_WQ ((3*DM/32)*(DM/32))     // 72*24 = 1728
#define NB_WO ((DM/32)*(DM/32))       // 576

__global__ void __launch_bounds__(256) prep_kernel(
        const float* __restrict__ emb, const float* __restrict__ W_qkv,
        const float* __restrict__ W_o) {
    __shared__ float t[32][33];
    int b = blockIdx.x;
    int tid = threadIdx.x;

    if (b < NB_A) {
        int i = b * 256 + tid;
        g_Af[i] = __float2half_rn(emb[i]);
        return;
    }
    const float* W;
    __half* T;
    int K = DM, N, b2;
    if (b < NB_A + NB_WQ) {
        b2 = b - NB_A;  W = W_qkv;  T = g_Wqf;  N = 3*DM;
    } else {
        b2 = b - NB_A - NB_WQ;  W = W_o;  T = g_Wof;  N = DM;
    }
    int nblk = N / 32;
    int n0 = (b2 % nblk) * 32, k0 = (b2 / nblk) * 32;
    int tx = tid & 31, ty = tid >> 5;
    #pragma unroll
    for (int i = ty; i < 32; i += 8)
        t[i][tx] = W[(size_t)(k0 + i) * N + n0 + tx];
    __syncthreads();
    #pragma unroll
    for (int i = ty; i < 32; i += 8)
        T[(size_t)(n0 + i) * K + k0 + tx] = __float2half_rn(t[tx][i]);
}

// ====================== mma.sync helpers ======================================
__device__ __forceinline__ uint32_t smem_u32(const void* p) {
    uint32_t a;
    asm("{ .reg .u64 t; cvta.to.shared.u64 t, %1; cvt.u32.u64 %0, t; }" : "=r"(a) : "l"(p));
    return a;
}
__device__ __forceinline__ void ldsm_x4(uint32_t& r0, uint32_t& r1, uint32_t& r2, uint32_t& r3,
                                        uint32_t addr) {
    asm volatile("ldmatrix.sync.aligned.m8n8.x4.shared.b16 {%0,%1,%2,%3}, [%4];"
                 : "=r"(r0), "=r"(r1), "=r"(r2), "=r"(r3) : "r"(addr));
}
__device__ __forceinline__ void mma_f16(float* d, const uint32_t* a, const uint32_t* b) {
    asm volatile("mma.sync.aligned.m16n8k16.row.col.f32.f16.f16.f32 "
                 "{%0,%1,%2,%3}, {%4,%5,%6,%7}, {%8,%9}, {%0,%1,%2,%3};"
                 : "+f"(d[0]), "+f"(d[1]), "+f"(d[2]), "+f"(d[3])
                 : "r"(a[0]), "r"(a[1]), "r"(a[2]), "r"(a[3]), "r"(b[0]), "r"(b[1]));
}
#define CP_ASYNC_16(dst, src) \
    asm volatile("cp.async.cg.shared.global [%0], [%1], 16;" :: "r"(dst), "l"(src))
#define CP_COMMIT() asm volatile("cp.async.commit_group;" ::: "memory")
#define CP_WAIT_1() asm volatile("cp.async.wait_group 1;" ::: "memory")
#define CP_WAIT_0() asm volatile("cp.async.wait_group 0;" ::: "memory")

// ====================== HMMA fp16 GEMM (BK=64 stages) =========================
// ROPE: fused RoPE+head-split epilogue. COMB: bm==0 blocks patch A row 0 with
// the CLS-combine output (computed in-block from g_cls_*).
#define SMSTRIDE 72
#define FNST 2

template<int BM, bool ROPE, bool COMB>
__global__ void __launch_bounds__(256, 2)
gemm_f16(const __half* __restrict__ A, const __half* __restrict__ B,
         const float* __restrict__ bias, float* __restrict__ C,
         int N, int K) {
    constexpr int MI  = BM / 32;
    constexpr int ACH = BM / 32;
    constexpr int A_STAGE = BM * SMSTRIDE;
    constexpr int B_STAGE = 128 * SMSTRIDE;

    extern __shared__ __align__(16) __half dsm[];
    __half* As = dsm;
    __half* Bs = dsm + FNST * A_STAGE;
    __half* combo = dsm + FNST * (A_STAGE + B_STAGE);   // 768 halves (COMB only)

    const int tid  = threadIdx.x;
    const int wid  = tid >> 5;
    const int lane = tid & 31;
    const int bn = blockIdx.x, bm = blockIdx.y;
    const int wm = (wid >> 2) * (BM / 2);
    const int wn = (wid & 3) * 32;

    const int KT = K >> 6;
    const bool patch = COMB && (bm == 0);

    if (patch) {
        for (int idx = tid; idx < DM; idx += 256) {
            int h = idx >> 6, d = idx & 63;
            float m = -1e30f;
            #pragma unroll
            for (int c = 0; c < NCHUNK; c++) m = fmaxf(m, g_cls_m[h*NCHUNK + c]);
            float den = 0.f, num = 0.f;
            #pragma unroll
            for (int c = 0; c < NCHUNK; c++) {
                float w = expf(g_cls_m[h*NCHUNK + c] - m);
                den += g_cls_s[h*NCHUNK + c] * w;
                num += g_cls_o[(size_t)(h*NCHUNK + c)*HD + d] * w;
            }
            combo[idx] = __float2half_rn(num / den);
        }
    }

    float acc[MI][4][4] = {};

    auto load_stage = [&](int kt, int buf) {
        const __half* Ag = A + (size_t)bm * BM * K + kt * 64;
        const __half* Bg = B + (size_t)bn * 128 * K + kt * 64;
        uint32_t a_s = smem_u32(As + buf * A_STAGE);
        uint32_t b_s = smem_u32(Bs + buf * B_STAGE);
        #pragma unroll
        for (int i = 0; i < ACH; i++) {
            int ch = tid + i * 256;
            int r = ch >> 3, cc = (ch & 7) * 8;
            CP_ASYNC_16(a_s + (uint32_t)(r * SMSTRIDE + cc) * 2, Ag + (size_t)r * K + cc);
        }
        #pragma unroll
        for (int i = 0; i < 4; i++) {
            int ch = tid + i * 256;
            int r = ch >> 3, cc = (ch & 7) * 8;
            CP_ASYNC_16(b_s + (uint32_t)(r * SMSTRIDE + cc) * 2, Bg + (size_t)r * K + cc);
        }
    };

    load_stage(0, 0); CP_COMMIT();
    load_stage(1, 1); CP_COMMIT();

    for (int kt = 0; kt < KT; kt++) {
        const int buf = kt & 1;
        CP_WAIT_1();
        __syncthreads();

        if (patch) {
            // replace A row 0 (l=0) columns kt*64.. with CLS combine output
            if (tid < 8) {
                int cc = tid * 8;
                *(uint4*)(As + buf * A_STAGE + cc) = *(const uint4*)(combo + kt * 64 + cc);
            }
            __syncthreads();
        }

        const uint32_t a_base = smem_u32(As + buf * A_STAGE);
        const uint32_t b_base = smem_u32(Bs + buf * B_STAGE);

        #pragma unroll
        for (int ks = 0; ks < 4; ks++) {
            uint32_t af[MI][4], bf[4][2];
            const int acol = ks * 16 + ((lane & 16) ? 8 : 0);
            const int bgrp = lane >> 3;
            #pragma unroll
            for (int mi = 0; mi < MI; mi++) {
                int row = wm + mi * 16 + (lane & 7) + ((lane & 8) ? 8 : 0);
                ldsm_x4(af[mi][0], af[mi][1], af[mi][2], af[mi][3],
                        a_base + (uint32_t)(row * SMSTRIDE + acol) * 2);
            }
            #pragma unroll
            for (int njp = 0; njp < 2; njp++) {
                int row = wn + (njp * 2 + (bgrp >> 1)) * 8 + (lane & 7);
                int col = ks * 16 + (bgrp & 1) * 8;
                uint32_t r0, r1, r2, r3;
                ldsm_x4(r0, r1, r2, r3, b_base + (uint32_t)(row * SMSTRIDE + col) * 2);
                bf[njp*2][0] = r0;  bf[njp*2][1] = r1;
                bf[njp*2+1][0] = r2; bf[njp*2+1][1] = r3;
            }
            #pragma unroll
            for (int mi = 0; mi < MI; mi++)
                #pragma unroll
                for (int nj = 0; nj < 4; nj++)
                    mma_f16(acc[mi][nj], af[mi], bf[nj]);
        }

        __syncthreads();
        int nkt = kt + 2 < KT ? kt + 2 : KT - 1;
        load_stage(nkt, buf);
        CP_COMMIT();
    }

    if (!ROPE) {
        #pragma unroll
        for (int nj = 0; nj < 4; nj++) {
            int gcol = bn * 128 + wn + nj * 8 + (lane & 3) * 2;
            float2 bv = *(const float2*)(bias + gcol);
            #pragma unroll
            for (int mi = 0; mi < MI; mi++) {
                int grow = bm * BM + wm + mi * 16 + (lane >> 2);
                float2 v0 = { acc[mi][nj][0] + bv.x, acc[mi][nj][1] + bv.y };
                float2 v1 = { acc[mi][nj][2] + bv.x, acc[mi][nj][3] + bv.y };
                *(float2*)(C + (size_t)grow * N + gcol)       = v0;
                *(float2*)(C + (size_t)(grow + 8) * N + gcol) = v1;
            }
        }
    } else {
        CP_WAIT_0();
        __syncthreads();
        float* ep = (float*)dsm;   // [128][132] fp32

        #pragma unroll
        for (int nj = 0; nj < 4; nj++) {
            int colq = wn + nj * 8 + (lane & 3) * 2;
            float2 bv = *(const float2*)(bias + bn * 128 + colq);
            #pragma unroll
            for (int mi = 0; mi < MI; mi++) {
                int row = wm + mi * 16 + (lane >> 2);
                ep[row * 132 + colq]           = acc[mi][nj][0] + bv.x;
                ep[row * 132 + colq + 1]       = acc[mi][nj][1] + bv.y;
                ep[(row + 8) * 132 + colq]     = acc[mi][nj][2] + bv.x;
                ep[(row + 8) * 132 + colq + 1] = acc[mi][nj][3] + bv.y;
            }
        }
        __syncthreads();

        const int rr  = tid >> 3;
        const int sub = tid & 7;
        const int hh  = sub >> 2;
        const int qq  = sub & 3;
        const int sec = bn / 6;
        const int hd  = (bn % 6) * 2 + hh;
        float* dst = (sec == 0) ? g_q : (sec == 1) ? g_k : g_v;

        float invf[8];
        if (sec < 2) {
            #pragma unroll
            for (int e = 0; e < 8; e++)
                invf[e] = exp2f(-(float)(qq * 8 + e) * ROPE_C);
        }

        #pragma unroll
        for (int rg = 0; rg < 4; rg++) {
            int r = rg * 32 + rr;
            int l = bm * 128 + r;
            const float* er = ep + r * 132 + hh * 64 + qq * 8;
            float x1[8], x2[8];
            *(float4*)&x1[0] = *(const float4*)er;
            *(float4*)&x1[4] = *(const float4*)(er + 4);
            *(float4*)&x2[0] = *(const float4*)(er + 32);
            *(float4*)&x2[4] = *(const float4*)(er + 36);
            float o1[8], o2[8];
            if (sec == 2) {
                #pragma unroll
                for (int e = 0; e < 8; e++) { o1[e] = x1[e]; o2[e] = x2[e]; }
            } else {
                #pragma unroll
                for (int e = 0; e < 8; e++) {
                    float s, c;
                    sincosf((float)l * invf[e], &s, &c);
                    o1[e] = x1[e] * c - x2[e] * s;
                    o2[e] = x1[e] * s + x2[e] * c;
                }
            }
            float* dp = dst + ((size_t)hd * L + l) * HD + qq * 8;
            *(float4*)dp        = *(float4*)&o1[0];
            *(float4*)(dp + 4)  = *(float4*)&o1[4];
            *(float4*)(dp + 32) = *(float4*)&o2[0];
            *(float4*)(dp + 36) = *(float4*)&o2[4];
        }
    }
}

// ====================== window attention + CLS chunks (one launch) ============
// blocks [0, 768): sliding-window tiles. blocks [768, 960): CLS split-softmax
// chunks (h = b2/16, chunk c = b2%16), writing g_cls_m/s/o.
__global__ void __launch_bounds__(1024) window_attn_kernel(const int* __restrict__ mask) {
    extern __shared__ float sm[];
    int tid = threadIdx.x;

    if (blockIdx.x >= H * (L / TQ)) {
        // ---------------- CLS chunk block (1024 threads) ----------------
        float* ksm = sm;                   // 128*65
        float* q0  = ksm + CKEYS*65;       // 64
        float* ew  = q0 + HD;              // 128
        float* red = ew + CKEYS;           // 136

        int b2 = blockIdx.x - H * (L / TQ);
        int h = b2 >> 4, c = b2 & 15;
        int base = c * CKEYS;

        if (tid < HD) q0[tid] = g_q[(size_t)(h*L)*HD + tid];
        for (int idx = tid; idx < CKEYS*HD; idx += 1024) {
            int key = idx >> 6, d = idx & 63;
            ksm[key*65 + d] = g_k[(size_t)(h*L + base + key)*HD + d];
        }
        __syncthreads();

        float s = 0.f;
        if (tid < CKEYS) {
            #pragma unroll
            for (int d = 0; d < HD; d++) s += ksm[tid*65 + d] * q0[d];
            s = (mask[base + tid] != 0) ? s * SCALE : -1e30f;
            red[tid] = s;
        }
        __syncthreads();
        if (tid < 32) {
            float m = fmaxf(fmaxf(red[tid], red[tid+32]), fmaxf(red[tid+64], red[tid+96]));
            #pragma unroll
            for (int o = 16; o > 0; o >>= 1) m = fmaxf(m, __shfl_xor_sync(0xffffffffu, m, o));
            if (tid == 0) red[128] = m;
        }
        __syncthreads();
        float m_c = red[128];
        if (tid < CKEYS) { float e = expf(s - m_c); ew[tid] = e; red[tid] = e; }
        __syncthreads();
        if (tid < 32) {
            float su = red[tid] + red[tid+32] + red[tid+64] + red[tid+96];
            #pragma unroll
            for (int o = 16; o > 0; o >>= 1) su += __shfl_xor_sync(0xffffffffu, su, o);
            if (tid == 0) red[129] = su;
        }
        __syncthreads();
        float s_c = red[129];

        // output: group g (0..15) sums keys g*8..g*8+7 over dim d = tid&63
        int d = tid & 63, grp = tid >> 6;
        const float* vb = g_v + (size_t)(h*L + base + grp*8)*HD + d;
        float acc = 0.f;
        #pragma unroll
        for (int kk = 0; kk < 8; kk++)
            acc += ew[grp*8 + kk] * vb[(size_t)kk*HD];
        __syncthreads();           // ksm reads done; reuse as partial buffer
        float* pacc = ksm;         // 1024 floats
        pacc[tid] = acc;
        __syncthreads();
        if (tid < HD) {
            float t = 0.f;
            #pragma unroll
            for (int g = 0; g < 16; g++) t += pacc[g*64 + tid];
            g_cls_o[(size_t)(h*NCHUNK + c)*HD + tid] = t;
            if (tid == 0) { g_cls_m[h*NCHUNK + c] = m_c; g_cls_s[h*NCHUNK + c] = s_c; }
        }
        return;
    }

    // ---------------- sliding-window tile block ----------------
    float* ks = sm;                        // WROWS * WSTRIDE
    float* qs = ks + WROWS * WSTRIDE;      // TQ * 64
    float* ws = qs + TQ * HD;              // TQ * 128
    int*   rv = (int*)(ws + TQ * WIN);     // WROWS

    int h  = blockIdx.x / (L / TQ);
    int qt = blockIdx.x % (L / TQ);
    int l0 = qt * TQ;
    int lo = l0 - 64;

    for (int idx = tid; idx < WROWS; idx += 1024) {
        int lr = lo + idx;
        rv[idx] = (lr >= 0 && lr < L) ? (mask[lr] != 0) : 0;
    }
    for (int idx = tid; idx < WROWS * HD; idx += 1024) {
        int r = idx >> 6, d = idx & 63;
        int lr = lo + r;
        bool val = (lr >= 0 && lr < L);
        ks[r*WSTRIDE + d] = val ? g_k[(h*L + (val ? lr : 0))*HD + d] : 0.0f;
    }
    for (int idx = tid; idx < TQ * HD; idx += 1024) {
        qs[idx] = g_q[(h*L + l0)*HD + idx];
    }
    __syncthreads();

    int wq   = tid >> 5;
    int lane = tid & 31;
    int l = l0 + wq;

    const float4* qs4 = (const float4*)(qs + wq*HD);
    const float4* kp0 = (const float4*)(ks + (wq + lane      )*WSTRIDE);
    const float4* kp1 = (const float4*)(ks + (wq + lane +  32)*WSTRIDE);
    const float4* kp2 = (const float4*)(ks + (wq + lane +  64)*WSTRIDE);
    const float4* kp3 = (const float4*)(ks + (wq + lane +  96)*WSTRIDE);
    float sc[4] = {0.f, 0.f, 0.f, 0.f};
    #pragma unroll
    for (int d4 = 0; d4 < 16; d4++) {
        float4 qq = qs4[d4];
        float4 k0 = kp0[d4], k1 = kp1[d4], k2 = kp2[d4], k3 = kp3[d4];
        sc[0] += k0.x*qq.x + k0.y*qq.y + k0.z*qq.z + k0.w*qq.w;
        sc[1] += k1.x*qq.x + k1.y*qq.y + k1.z*qq.z + k1.w*qq.w;
        sc[2] += k2.x*qq.x + k2.y*qq.y + k2.z*qq.z + k2.w*qq.w;
        sc[3] += k3.x*qq.x + k3.y*qq.y + k3.z*qq.z + k3.w*qq.w;
    }
    #pragma unroll
    for (int w4 = 0; w4 < 4; w4++)
        sc[w4] = rv[wq + lane + w4*32] ? sc[w4] * SCALE : -1e30f;

    float m = fmaxf(fmaxf(sc[0], sc[1]), fmaxf(sc[2], sc[3]));
    #pragma unroll
    for (int o = 16; o > 0; o >>= 1) m = fmaxf(m, __shfl_xor_sync(0xffffffffu, m, o));
    float e[4], sum = 0.f;
    #pragma unroll
    for (int w4 = 0; w4 < 4; w4++) { e[w4] = expf(sc[w4] - m); sum += e[w4]; }
    #pragma unroll
    for (int o = 16; o > 0; o >>= 1) sum += __shfl_xor_sync(0xffffffffu, sum, o);
    float inv = 1.0f / sum;
    #pragma unroll
    for (int w4 = 0; w4 < 4; w4++) ws[wq*WIN + lane + w4*32] = e[w4] * inv;
    __syncwarp();

    const int wpair = lane >> 4;
    const int chunk = lane & 15;
    float4 a4 = {0.f, 0.f, 0.f, 0.f};
    const float* vbase = g_v + (size_t)h*L*HD + chunk*4;
    #pragma unroll 4
    for (int w = 0; w < WIN; w += 2) {
        float wt = ws[wq*WIN + w + wpair];
        int lr = lo + wq + w + wpair;
        lr = lr < 0 ? 0 : (lr > L-1 ? L-1 : lr);
        float4 v = *(const float4*)(vbase + (size_t)lr*HD);
        a4.x += wt * v.x;
        a4.y += wt * v.y;
        a4.z += wt * v.z;
        a4.w += wt * v.w;
    }
    a4.x += __shfl_xor_sync(0xffffffffu, a4.x, 16);
    a4.y += __shfl_xor_sync(0xffffffffu, a4.y, 16);
    a4.z += __shfl_xor_sync(0xffffffffu, a4.z, 16);
    a4.w += __shfl_xor_sync(0xffffffffu, a4.w, 16);

    if (wpair == 0) {
        __half2 hA, hB;
        hA.x = __float2half_rn(a4.x); hA.y = __float2half_rn(a4.y);
        hB.x = __float2half_rn(a4.z); hB.y = __float2half_rn(a4.w);
        size_t o = (size_t)l*DM + h*HD + chunk*4;
        *(__half2*)(g_Cf + o)     = hA;
        *(__half2*)(g_Cf + o + 2) = hB;
    }
}

// ====================== launch =================================================
extern "C" void kernel_launch(void* const* d_in, const int* in_sizes, int n_in,
                              void* d_out, int out_size) {
    (void)in_sizes; (void)n_in; (void)out_size;
    const float* emb   = (const float*)d_in[0];
    const int*   mask  = (const int*)  d_in[1];
    const float* W_qkv = (const float*)d_in[2];
    const float* b_qkv = (const float*)d_in[3];
    const float* W_o   = (const float*)d_in[4];
    const float* b_o   = (const float*)d_in[5];
    float* out = (float*)d_out;

    __half *p_Af, *p_Wqf, *p_Wof, *p_Cf;
    cudaGetSymbolAddress((void**)&p_Af,  g_Af);
    cudaGetSymbolAddress((void**)&p_Wqf, g_Wqf);
    cudaGetSymbolAddress((void**)&p_Wof, g_Wof);
    cudaGetSymbolAddress((void**)&p_Cf,  g_Cf);

    constexpr int GSMEM128 = FNST * (128 + 128) * SMSTRIDE * 2;           // 73728 B
    constexpr int GSMEM64  = FNST * (64  + 128) * SMSTRIDE * 2 + DM * 2;  // 56832 B
    cudaFuncSetAttribute((const void*)gemm_f16<128,true,false>,
                         cudaFuncAttributeMaxDynamicSharedMemorySize, GSMEM128);
    cudaFuncSetAttribute((const void*)gemm_f16<64,false,true>,
                         cudaFuncAttributeMaxDynamicSharedMemorySize, GSMEM64);
    constexpr int SMEM_WIN = (WROWS*WSTRIDE + TQ*HD + TQ*WIN) * 4 + WROWS * 4;
    cudaFuncSetAttribute(window_attn_kernel,
                         cudaFuncAttributeMaxDynamicSharedMemorySize, SMEM_WIN);

    // 1. fused prep: emb->f16 + both weight transposes
    prep_kernel<<<NB_A + NB_WQ + NB_WO, 256>>>(emb, W_qkv, W_o);

    // 2. QKV GEMM with fused RoPE + head split
    gemm_f16<128,true,false><<<dim3((3*DM)/128, L/128), 256, GSMEM128>>>(
        p_Af, p_Wqf, b_qkv, nullptr, 3*DM, DM);

    // 3. window attention + CLS chunks in one launch
    window_attn_kernel<<<H * (L/TQ) + H * NCHUNK, 1024, SMEM_WIN>>>(mask);

    // 4. output projection with in-kernel CLS combine (patches row 0)
    gemm_f16<64,false,true><<<dim3(DM/128, L/64), 256, GSMEM64>>>(
        p_Cf, p_Wof, b_o, out, DM, DM);
}

// round 15
// speedup vs baseline: 3.0478x; 1.0236x over previous
#include <cuda_runtime.h>
#include <cuda_fp16.h>
#include <math.h>
#include <stdint.h>

#define L    2048
#define DM   768
#define H    12
#define HD   64
#define WIN  128
#define TQ   32
#define WROWS 160
#define NCHUNK 16
#define CKEYS  128
#define WSTRIDE 68

static constexpr float SCALE = 0.03608439182435161f;  // 1/sqrt(768)
static constexpr float ROPE_C = 0.41524101186092029f; // log2(10000)/32

// ====================== scratch ================================================
__device__ float g_q[H * L * HD];
__device__ float g_k[H * L * HD];
__device__ float g_v[H * L * HD];
__device__ float g_cls_m[H * NCHUNK];
__device__ float g_cls_s[H * NCHUNK];
__device__ float g_cls_o[H * NCHUNK * HD];

__device__ __half g_Af[L * DM];
__device__ __half g_Wqf[3*DM*DM];
__device__ __half g_Wof[DM*DM];
__device__ __half g_Cf[L * DM];

// ====================== fused prep kernel ======================================
#define NB_A  ((L*DM)/256)
#define NB_WQ ((3*DM/32)*(DM/32))
#define NB_WO ((DM/32)*(DM/32))

__global__ void __launch_bounds__(256) prep_kernel(
        const float* __restrict__ emb, const float* __restrict__ W_qkv,
        const float* __restrict__ W_o) {
    __shared__ float t[32][33];
    int b = blockIdx.x;
    int tid = threadIdx.x;

    if (b < NB_A) {
        int i = b * 256 + tid;
        g_Af[i] = __float2half_rn(emb[i]);
        return;
    }
    const float* W;
    __half* T;
    int K = DM, N, b2;
    if (b < NB_A + NB_WQ) {
        b2 = b - NB_A;  W = W_qkv;  T = g_Wqf;  N = 3*DM;
    } else {
        b2 = b - NB_A - NB_WQ;  W = W_o;  T = g_Wof;  N = DM;
    }
    int nblk = N / 32;
    int n0 = (b2 % nblk) * 32, k0 = (b2 / nblk) * 32;
    int tx = tid & 31, ty = tid >> 5;
    #pragma unroll
    for (int i = ty; i < 32; i += 8)
        t[i][tx] = W[(size_t)(k0 + i) * N + n0 + tx];
    __syncthreads();
    #pragma unroll
    for (int i = ty; i < 32; i += 8)
        T[(size_t)(n0 + i) * K + k0 + tx] = __float2half_rn(t[tx][i]);
}

// ====================== mma.sync helpers ======================================
__device__ __forceinline__ uint32_t smem_u32(const void* p) {
    uint32_t a;
    asm("{ .reg .u64 t; cvta.to.shared.u64 t, %1; cvt.u32.u64 %0, t; }" : "=r"(a) : "l"(p));
    return a;
}
__device__ __forceinline__ void ldsm_x4(uint32_t& r0, uint32_t& r1, uint32_t& r2, uint32_t& r3,
                                        uint32_t addr) {
    asm volatile("ldmatrix.sync.aligned.m8n8.x4.shared.b16 {%0,%1,%2,%3}, [%4];"
                 : "=r"(r0), "=r"(r1), "=r"(r2), "=r"(r3) : "r"(addr));
}
__device__ __forceinline__ void mma_f16(float* d, const uint32_t* a, const uint32_t* b) {
    asm volatile("mma.sync.aligned.m16n8k16.row.col.f32.f16.f16.f32 "
                 "{%0,%1,%2,%3}, {%4,%5,%6,%7}, {%8,%9}, {%0,%1,%2,%3};"
                 : "+f"(d[0]), "+f"(d[1]), "+f"(d[2]), "+f"(d[3])
                 : "r"(a[0]), "r"(a[1]), "r"(a[2]), "r"(a[3]), "r"(b[0]), "r"(b[1]));
}
#define CP_ASYNC_16(dst, src) \
    asm volatile("cp.async.cg.shared.global [%0], [%1], 16;" :: "r"(dst), "l"(src))
#define CP_COMMIT() asm volatile("cp.async.commit_group;" ::: "memory")
#define CP_WAIT_0() asm volatile("cp.async.wait_group 0;" ::: "memory")
template<int N> __device__ __forceinline__ void cp_wait() {
    asm volatile("cp.async.wait_group %0;" :: "n"(N) : "memory");
}

// ====================== HMMA fp16 GEMM (BK=64 stages, NST-deep) ===============
#define SMSTRIDE 72

template<int BM, int NST, bool ROPE, bool COMB>
__global__ void __launch_bounds__(256, 2)
gemm_f16(const __half* __restrict__ A, const __half* __restrict__ B,
         const float* __restrict__ bias, float* __restrict__ C,
         int N, int K) {
    constexpr int MI  = BM / 32;
    constexpr int ACH = BM / 32;
    constexpr int A_STAGE = BM * SMSTRIDE;
    constexpr int B_STAGE = 128 * SMSTRIDE;

    extern __shared__ __align__(16) __half dsm[];
    __half* As = dsm;
    __half* Bs = dsm + NST * A_STAGE;
    __half* combo = dsm + NST * (A_STAGE + B_STAGE);   // 768 halves (COMB only)

    const int tid  = threadIdx.x;
    const int wid  = tid >> 5;
    const int lane = tid & 31;
    const int bn = blockIdx.x, bm = blockIdx.y;
    const int wm = (wid >> 2) * (BM / 2);
    const int wn = (wid & 3) * 32;

    const int KT = K >> 6;
    const bool patch = COMB && (bm == 0);

    // PDL: wait for producer kernel's memory before reading its outputs
    cudaGridDependencySynchronize();

    if (patch) {
        for (int idx = tid; idx < DM; idx += 256) {
            int h = idx >> 6, d = idx & 63;
            float m = -1e30f;
            #pragma unroll
            for (int c = 0; c < NCHUNK; c++) m = fmaxf(m, g_cls_m[h*NCHUNK + c]);
            float den = 0.f, num = 0.f;
            #pragma unroll
            for (int c = 0; c < NCHUNK; c++) {
                float w = expf(g_cls_m[h*NCHUNK + c] - m);
                den += g_cls_s[h*NCHUNK + c] * w;
                num += g_cls_o[(size_t)(h*NCHUNK + c)*HD + d] * w;
            }
            combo[idx] = __float2half_rn(num / den);
        }
    }

    float acc[MI][4][4] = {};

    auto load_stage = [&](int kt, int buf) {
        const __half* Ag = A + (size_t)bm * BM * K + kt * 64;
        const __half* Bg = B + (size_t)bn * 128 * K + kt * 64;
        uint32_t a_s = smem_u32(As + buf * A_STAGE);
        uint32_t b_s = smem_u32(Bs + buf * B_STAGE);
        #pragma unroll
        for (int i = 0; i < ACH; i++) {
            int ch = tid + i * 256;
            int r = ch >> 3, cc = (ch & 7) * 8;
            CP_ASYNC_16(a_s + (uint32_t)(r * SMSTRIDE + cc) * 2, Ag + (size_t)r * K + cc);
        }
        #pragma unroll
        for (int i = 0; i < 4; i++) {
            int ch = tid + i * 256;
            int r = ch >> 3, cc = (ch & 7) * 8;
            CP_ASYNC_16(b_s + (uint32_t)(r * SMSTRIDE + cc) * 2, Bg + (size_t)r * K + cc);
        }
    };

    #pragma unroll
    for (int s = 0; s < NST; s++) { load_stage(s < KT ? s : KT-1, s); CP_COMMIT(); }

    for (int kt = 0; kt < KT; kt++) {
        const int buf = kt % NST;
        cp_wait<NST - 1>();
        __syncthreads();

        if (patch) {
            if (tid < 8) {
                int cc = tid * 8;
                *(uint4*)(As + buf * A_STAGE + cc) = *(const uint4*)(combo + kt * 64 + cc);
            }
            __syncthreads();
        }

        const uint32_t a_base = smem_u32(As + buf * A_STAGE);
        const uint32_t b_base = smem_u32(Bs + buf * B_STAGE);

        #pragma unroll
        for (int ks = 0; ks < 4; ks++) {
            uint32_t af[MI][4], bf[4][2];
            const int acol = ks * 16 + ((lane & 16) ? 8 : 0);
            const int bgrp = lane >> 3;
            #pragma unroll
            for (int mi = 0; mi < MI; mi++) {
                int row = wm + mi * 16 + (lane & 7) + ((lane & 8) ? 8 : 0);
                ldsm_x4(af[mi][0], af[mi][1], af[mi][2], af[mi][3],
                        a_base + (uint32_t)(row * SMSTRIDE + acol) * 2);
            }
            #pragma unroll
            for (int njp = 0; njp < 2; njp++) {
                int row = wn + (njp * 2 + (bgrp >> 1)) * 8 + (lane & 7);
                int col = ks * 16 + (bgrp & 1) * 8;
                uint32_t r0, r1, r2, r3;
                ldsm_x4(r0, r1, r2, r3, b_base + (uint32_t)(row * SMSTRIDE + col) * 2);
                bf[njp*2][0] = r0;  bf[njp*2][1] = r1;
                bf[njp*2+1][0] = r2; bf[njp*2+1][1] = r3;
            }
            #pragma unroll
            for (int mi = 0; mi < MI; mi++)
                #pragma unroll
                for (int nj = 0; nj < 4; nj++)
                    mma_f16(acc[mi][nj], af[mi], bf[nj]);
        }

        __syncthreads();
        int nkt = kt + NST < KT ? kt + NST : KT - 1;
        load_stage(nkt, buf);
        CP_COMMIT();
    }

    if (!ROPE) {
        #pragma unroll
        for (int nj = 0; nj < 4; nj++) {
            int gcol = bn * 128 + wn + nj * 8 + (lane & 3) * 2;
            float2 bv = *(const float2*)(bias + gcol);
            #pragma unroll
            for (int mi = 0; mi < MI; mi++) {
                int grow = bm * BM + wm + mi * 16 + (lane >> 2);
                float2 v0 = { acc[mi][nj][0] + bv.x, acc[mi][nj][1] + bv.y };
                float2 v1 = { acc[mi][nj][2] + bv.x, acc[mi][nj][3] + bv.y };
                *(float2*)(C + (size_t)grow * N + gcol)       = v0;
                *(float2*)(C + (size_t)(grow + 8) * N + gcol) = v1;
            }
        }
    } else {
        CP_WAIT_0();
        __syncthreads();
        float* ep = (float*)dsm;   // [128][132] fp32

        #pragma unroll
        for (int nj = 0; nj < 4; nj++) {
            int colq = wn + nj * 8 + (lane & 3) * 2;
            float2 bv = *(const float2*)(bias + bn * 128 + colq);
            #pragma unroll
            for (int mi = 0; mi < MI; mi++) {
                int row = wm + mi * 16 + (lane >> 2);
                ep[row * 132 + colq]           = acc[mi][nj][0] + bv.x;
                ep[row * 132 + colq + 1]       = acc[mi][nj][1] + bv.y;
                ep[(row + 8) * 132 + colq]     = acc[mi][nj][2] + bv.x;
                ep[(row + 8) * 132 + colq + 1] = acc[mi][nj][3] + bv.y;
            }
        }
        __syncthreads();

        const int rr  = tid >> 3;
        const int sub = tid & 7;
        const int hh  = sub >> 2;
        const int qq  = sub & 3;
        const int sec = bn / 6;
        const int hd  = (bn % 6) * 2 + hh;
        float* dst = (sec == 0) ? g_q : (sec == 1) ? g_k : g_v;

        float invf[8];
        if (sec < 2) {
            #pragma unroll
            for (int e = 0; e < 8; e++)
                invf[e] = exp2f(-(float)(qq * 8 + e) * ROPE_C);
        }

        #pragma unroll
        for (int rg = 0; rg < 4; rg++) {
            int r = rg * 32 + rr;
            int l = bm * 128 + r;
            const float* er = ep + r * 132 + hh * 64 + qq * 8;
            float x1[8], x2[8];
            *(float4*)&x1[0] = *(const float4*)er;
            *(float4*)&x1[4] = *(const float4*)(er + 4);
            *(float4*)&x2[0] = *(const float4*)(er + 32);
            *(float4*)&x2[4] = *(const float4*)(er + 36);
            float o1[8], o2[8];
            if (sec == 2) {
                #pragma unroll
                for (int e = 0; e < 8; e++) { o1[e] = x1[e]; o2[e] = x2[e]; }
            } else {
                #pragma unroll
                for (int e = 0; e < 8; e++) {
                    float s, c;
                    sincosf((float)l * invf[e], &s, &c);
                    o1[e] = x1[e] * c - x2[e] * s;
                    o2[e] = x1[e] * s + x2[e] * c;
                }
            }
            float* dp = dst + ((size_t)hd * L + l) * HD + qq * 8;
            *(float4*)dp        = *(float4*)&o1[0];
            *(float4*)(dp + 4)  = *(float4*)&o1[4];
            *(float4*)(dp + 32) = *(float4*)&o2[0];
            *(float4*)(dp + 36) = *(float4*)&o2[4];
        }
    }
}

// ====================== window attention + CLS chunks (one launch) ============
__global__ void __launch_bounds__(1024) window_attn_kernel(const int* __restrict__ mask) {
    extern __shared__ float sm[];
    int tid = threadIdx.x;

    cudaGridDependencySynchronize();   // PDL: wait for gemm1 outputs

    if (blockIdx.x >= H * (L / TQ)) {
        // ---------------- CLS chunk block ----------------
        float* ksm = sm;
        float* q0  = ksm + CKEYS*65;
        float* ew  = q0 + HD;
        float* red = ew + CKEYS;

        int b2 = blockIdx.x - H * (L / TQ);
        int h = b2 >> 4, c = b2 & 15;
        int base = c * CKEYS;

        if (tid < HD) q0[tid] = g_q[(size_t)(h*L)*HD + tid];
        for (int idx = tid; idx < CKEYS*HD; idx += 1024) {
            int key = idx >> 6, d = idx & 63;
            ksm[key*65 + d] = g_k[(size_t)(h*L + base + key)*HD + d];
        }
        __syncthreads();

        float s = 0.f;
        if (tid < CKEYS) {
            #pragma unroll
            for (int d = 0; d < HD; d++) s += ksm[tid*65 + d] * q0[d];
            s = (mask[base + tid] != 0) ? s * SCALE : -1e30f;
            red[tid] = s;
        }
        __syncthreads();
        if (tid < 32) {
            float m = fmaxf(fmaxf(red[tid], red[tid+32]), fmaxf(red[tid+64], red[tid+96]));
            #pragma unroll
            for (int o = 16; o > 0; o >>= 1) m = fmaxf(m, __shfl_xor_sync(0xffffffffu, m, o));
            if (tid == 0) red[128] = m;
        }
        __syncthreads();
        float m_c = red[128];
        if (tid < CKEYS) { float e = expf(s - m_c); ew[tid] = e; red[tid] = e; }
        __syncthreads();
        if (tid < 32) {
            float su = red[tid] + red[tid+32] + red[tid+64] + red[tid+96];
            #pragma unroll
            for (int o = 16; o > 0; o >>= 1) su += __shfl_xor_sync(0xffffffffu, su, o);
            if (tid == 0) red[129] = su;
        }
        __syncthreads();
        float s_c = red[129];

        int d = tid & 63, grp = tid >> 6;
        const float* vb = g_v + (size_t)(h*L + base + grp*8)*HD + d;
        float acc = 0.f;
        #pragma unroll
        for (int kk = 0; kk < 8; kk++)
            acc += ew[grp*8 + kk] * vb[(size_t)kk*HD];
        __syncthreads();
        float* pacc = ksm;
        pacc[tid] = acc;
        __syncthreads();
        if (tid < HD) {
            float t = 0.f;
            #pragma unroll
            for (int g = 0; g < 16; g++) t += pacc[g*64 + tid];
            g_cls_o[(size_t)(h*NCHUNK + c)*HD + tid] = t;
            if (tid == 0) { g_cls_m[h*NCHUNK + c] = m_c; g_cls_s[h*NCHUNK + c] = s_c; }
        }
        return;
    }

    // ---------------- sliding-window tile block ----------------
    float* ks = sm;
    float* qs = ks + WROWS * WSTRIDE;
    float* ws = qs + TQ * HD;
    int*   rv = (int*)(ws + TQ * WIN);

    int h  = blockIdx.x / (L / TQ);
    int qt = blockIdx.x % (L / TQ);
    int l0 = qt * TQ;
    int lo = l0 - 64;

    for (int idx = tid; idx < WROWS; idx += 1024) {
        int lr = lo + idx;
        rv[idx] = (lr >= 0 && lr < L) ? (mask[lr] != 0) : 0;
    }
    for (int idx = tid; idx < WROWS * HD; idx += 1024) {
        int r = idx >> 6, d = idx & 63;
        int lr = lo + r;
        bool val = (lr >= 0 && lr < L);
        ks[r*WSTRIDE + d] = val ? g_k[(h*L + (val ? lr : 0))*HD + d] : 0.0f;
    }
    for (int idx = tid; idx < TQ * HD; idx += 1024) {
        qs[idx] = g_q[(h*L + l0)*HD + idx];
    }
    __syncthreads();

    int wq   = tid >> 5;
    int lane = tid & 31;
    int l = l0 + wq;

    const float4* qs4 = (const float4*)(qs + wq*HD);
    const float4* kp0 = (const float4*)(ks + (wq + lane      )*WSTRIDE);
    const float4* kp1 = (const float4*)(ks + (wq + lane +  32)*WSTRIDE);
    const float4* kp2 = (const float4*)(ks + (wq + lane +  64)*WSTRIDE);
    const float4* kp3 = (const float4*)(ks + (wq + lane +  96)*WSTRIDE);
    float sc[4] = {0.f, 0.f, 0.f, 0.f};
    #pragma unroll
    for (int d4 = 0; d4 < 16; d4++) {
        float4 qq = qs4[d4];
        float4 k0 = kp0[d4], k1 = kp1[d4], k2 = kp2[d4], k3 = kp3[d4];
        sc[0] += k0.x*qq.x + k0.y*qq.y + k0.z*qq.z + k0.w*qq.w;
        sc[1] += k1.x*qq.x + k1.y*qq.y + k1.z*qq.z + k1.w*qq.w;
        sc[2] += k2.x*qq.x + k2.y*qq.y + k2.z*qq.z + k2.w*qq.w;
        sc[3] += k3.x*qq.x + k3.y*qq.y + k3.z*qq.z + k3.w*qq.w;
    }
    #pragma unroll
    for (int w4 = 0; w4 < 4; w4++)
        sc[w4] = rv[wq + lane + w4*32] ? sc[w4] * SCALE : -1e30f;

    float m = fmaxf(fmaxf(sc[0], sc[1]), fmaxf(sc[2], sc[3]));
    #pragma unroll
    for (int o = 16; o > 0; o >>= 1) m = fmaxf(m, __shfl_xor_sync(0xffffffffu, m, o));
    float e[4], sum = 0.f;
    #pragma unroll
    for (int w4 = 0; w4 < 4; w4++) { e[w4] = expf(sc[w4] - m); sum += e[w4]; }
    #pragma unroll
    for (int o = 16; o > 0; o >>= 1) sum += __shfl_xor_sync(0xffffffffu, sum, o);
    float inv = 1.0f / sum;
    #pragma unroll
    for (int w4 = 0; w4 < 4; w4++) ws[wq*WIN + lane + w4*32] = e[w4] * inv;
    __syncwarp();

    const int wpair = lane >> 4;
    const int chunk = lane & 15;
    float4 a4 = {0.f, 0.f, 0.f, 0.f};
    const float* vbase = g_v + (size_t)h*L*HD + chunk*4;
    #pragma unroll 4
    for (int w = 0; w < WIN; w += 2) {
        float wt = ws[wq*WIN + w + wpair];
        int lr = lo + wq + w + wpair;
        lr = lr < 0 ? 0 : (lr > L-1 ? L-1 : lr);
        float4 v = *(const float4*)(vbase + (size_t)lr*HD);
        a4.x += wt * v.x;
        a4.y += wt * v.y;
        a4.z += wt * v.z;
        a4.w += wt * v.w;
    }
    a4.x += __shfl_xor_sync(0xffffffffu, a4.x, 16);
    a4.y += __shfl_xor_sync(0xffffffffu, a4.y, 16);
    a4.z += __shfl_xor_sync(0xffffffffu, a4.z, 16);
    a4.w += __shfl_xor_sync(0xffffffffu, a4.w, 16);

    if (wpair == 0) {
        __half2 hA, hB;
        hA.x = __float2half_rn(a4.x); hA.y = __float2half_rn(a4.y);
        hB.x = __float2half_rn(a4.z); hB.y = __float2half_rn(a4.w);
        size_t o = (size_t)l*DM + h*HD + chunk*4;
        *(__half2*)(g_Cf + o)     = hA;
        *(__half2*)(g_Cf + o + 2) = hB;
    }
}

// ====================== launch =================================================
extern "C" void kernel_launch(void* const* d_in, const int* in_sizes, int n_in,
                              void* d_out, int out_size) {
    (void)in_sizes; (void)n_in; (void)out_size;
    const float* emb   = (const float*)d_in[0];
    const int*   mask  = (const int*)  d_in[1];
    const float* W_qkv = (const float*)d_in[2];
    const float* b_qkv = (const float*)d_in[3];
    const float* W_o   = (const float*)d_in[4];
    const float* b_o   = (const float*)d_in[5];
    float* out = (float*)d_out;

    __half *p_Af, *p_Wqf, *p_Wof, *p_Cf;
    cudaGetSymbolAddress((void**)&p_Af,  g_Af);
    cudaGetSymbolAddress((void**)&p_Wqf, g_Wqf);
    cudaGetSymbolAddress((void**)&p_Wof, g_Wof);
    cudaGetSymbolAddress((void**)&p_Cf,  g_Cf);

    constexpr int GSMEM1 = 2 * (128 + 128) * SMSTRIDE * 2;               // 73728 B
    constexpr int GSMEM2 = 3 * (64  + 128) * SMSTRIDE * 2 + DM * 2;      // 84480 B
    cudaFuncSetAttribute((const void*)gemm_f16<128,2,true,false>,
                         cudaFuncAttributeMaxDynamicSharedMemorySize, GSMEM1);
    cudaFuncSetAttribute((const void*)gemm_f16<64,3,false,true>,
                         cudaFuncAttributeMaxDynamicSharedMemorySize, GSMEM2);
    constexpr int SMEM_WIN = (WROWS*WSTRIDE + TQ*HD + TQ*WIN) * 4 + WROWS * 4;
    cudaFuncSetAttribute(window_attn_kernel,
                         cudaFuncAttributeMaxDynamicSharedMemorySize, SMEM_WIN);

    cudaLaunchAttribute pdl[1];
    pdl[0].id = cudaLaunchAttributeProgrammaticStreamSerialization;
    pdl[0].val.programmaticStreamSerializationAllowed = 1;

    // 1. fused prep (normal launch)
    prep_kernel<<<NB_A + NB_WQ + NB_WO, 256>>>(emb, W_qkv, W_o);

    // 2. QKV GEMM + fused RoPE (PDL on prep)
    {
        cudaLaunchConfig_t cfg = {};
        cfg.gridDim = dim3((3*DM)/128, L/128);
        cfg.blockDim = dim3(256);
        cfg.dynamicSmemBytes = GSMEM1;
        cfg.attrs = pdl; cfg.numAttrs = 1;
        const __half* Aa = p_Af; const __half* Bb = p_Wqf;
        const float* bb = b_qkv; float* cc = nullptr;
        int NN = 3*DM, KK = DM;
        cudaLaunchKernelEx(&cfg, gemm_f16<128,2,true,false>, Aa, Bb, bb, cc, NN, KK);
    }

    // 3. window attention + CLS chunks (PDL on gemm1)
    {
        cudaLaunchConfig_t cfg = {};
        cfg.gridDim = dim3(H * (L/TQ) + H * NCHUNK);
        cfg.blockDim = dim3(1024);
        cfg.dynamicSmemBytes = SMEM_WIN;
        cfg.attrs = pdl; cfg.numAttrs = 1;
        const int* mm = mask;
        cudaLaunchKernelEx(&cfg, window_attn_kernel, mm);
    }

    // 4. output projection + in-kernel CLS combine (PDL on window)
    {
        cudaLaunchConfig_t cfg = {};
        cfg.gridDim = dim3(DM/128, L/64);
        cfg.blockDim = dim3(256);
        cfg.dynamicSmemBytes = GSMEM2;
        cfg.attrs = pdl; cfg.numAttrs = 1;
        const __half* Aa = p_Cf; const __half* Bb = p_Wof;
        const float* bb = b_o; float* cc = out;
        int NN = DM, KK = DM;
        cudaLaunchKernelEx(&cfg, gemm_f16<64,3,false,true>, Aa, Bb, bb, cc, NN, KK);
    }
}

// round 16
// speedup vs baseline: 4.1026x; 1.3461x over previous
#include <cuda_runtime.h>
#include <cuda_fp16.h>
#include <math.h>
#include <stdint.h>

#define L    2048
#define DM   768
#define H    12
#define HD   64
#define WIN  128
#define TQ   32
#define WROWS 160
#define NCHUNK 16
#define CKEYS  128
#define SPSTR 161     // floats per score-panel row (160 + 1 pad)

static constexpr float SCALE = 0.03608439182435161f;  // 1/sqrt(768)
static constexpr float ROPE_C = 0.41524101186092029f; // log2(10000)/32

// ====================== scratch ================================================
__device__ float g_q[H * L * HD];
__device__ float g_k[H * L * HD];
__device__ float g_v[H * L * HD];
__device__ __half g_qh[H * L * HD];      // fp16 copies for tensor-core scores
__device__ __half g_kh[H * L * HD];
__device__ float g_cls_m[H * NCHUNK];
__device__ float g_cls_s[H * NCHUNK];
__device__ float g_cls_o[H * NCHUNK * HD];

__device__ __half g_Af[L * DM];
__device__ __half g_Wqf[3*DM*DM];
__device__ __half g_Wof[DM*DM];
__device__ __half g_Cf[L * DM];

// ====================== fused prep kernel ======================================
#define NB_A  ((L*DM)/256)
#define NB_WQ ((3*DM/32)*(DM/32))
#define NB_WO ((DM/32)*(DM/32))

__global__ void __launch_bounds__(256) prep_kernel(
        const float* __restrict__ emb, const float* __restrict__ W_qkv,
        const float* __restrict__ W_o) {
    __shared__ float t[32][33];
    int b = blockIdx.x;
    int tid = threadIdx.x;

    if (b < NB_A) {
        int i = b * 256 + tid;
        g_Af[i] = __float2half_rn(emb[i]);
        return;
    }
    const float* W;
    __half* T;
    int K = DM, N, b2;
    if (b < NB_A + NB_WQ) {
        b2 = b - NB_A;  W = W_qkv;  T = g_Wqf;  N = 3*DM;
    } else {
        b2 = b - NB_A - NB_WQ;  W = W_o;  T = g_Wof;  N = DM;
    }
    int nblk = N / 32;
    int n0 = (b2 % nblk) * 32, k0 = (b2 / nblk) * 32;
    int tx = tid & 31, ty = tid >> 5;
    #pragma unroll
    for (int i = ty; i < 32; i += 8)
        t[i][tx] = W[(size_t)(k0 + i) * N + n0 + tx];
    __syncthreads();
    #pragma unroll
    for (int i = ty; i < 32; i += 8)
        T[(size_t)(n0 + i) * K + k0 + tx] = __float2half_rn(t[tx][i]);
}

// ====================== mma.sync helpers ======================================
__device__ __forceinline__ uint32_t smem_u32(const void* p) {
    uint32_t a;
    asm("{ .reg .u64 t; cvta.to.shared.u64 t, %1; cvt.u32.u64 %0, t; }" : "=r"(a) : "l"(p));
    return a;
}
__device__ __forceinline__ void ldsm_x4(uint32_t& r0, uint32_t& r1, uint32_t& r2, uint32_t& r3,
                                        uint32_t addr) {
    asm volatile("ldmatrix.sync.aligned.m8n8.x4.shared.b16 {%0,%1,%2,%3}, [%4];"
                 : "=r"(r0), "=r"(r1), "=r"(r2), "=r"(r3) : "r"(addr));
}
__device__ __forceinline__ void mma_f16(float* d, const uint32_t* a, const uint32_t* b) {
    asm volatile("mma.sync.aligned.m16n8k16.row.col.f32.f16.f16.f32 "
                 "{%0,%1,%2,%3}, {%4,%5,%6,%7}, {%8,%9}, {%0,%1,%2,%3};"
                 : "+f"(d[0]), "+f"(d[1]), "+f"(d[2]), "+f"(d[3])
                 : "r"(a[0]), "r"(a[1]), "r"(a[2]), "r"(a[3]), "r"(b[0]), "r"(b[1]));
}
#define CP_ASYNC_16(dst, src) \
    asm volatile("cp.async.cg.shared.global [%0], [%1], 16;" :: "r"(dst), "l"(src))
#define CP_COMMIT() asm volatile("cp.async.commit_group;" ::: "memory")
#define CP_WAIT_0() asm volatile("cp.async.wait_group 0;" ::: "memory")
template<int N> __device__ __forceinline__ void cp_wait() {
    asm volatile("cp.async.wait_group %0;" :: "n"(N) : "memory");
}

// ====================== HMMA fp16 GEMM (BK=64 stages) =========================
#define SMSTRIDE 72

template<int BM, int NST, bool ROPE, bool COMB>
__global__ void __launch_bounds__(256, 2)
gemm_f16(const __half* __restrict__ A, const __half* __restrict__ B,
         const float* __restrict__ bias, float* __restrict__ C,
         int N, int K) {
    constexpr int MI  = BM / 32;
    constexpr int ACH = BM / 32;
    constexpr int A_STAGE = BM * SMSTRIDE;
    constexpr int B_STAGE = 128 * SMSTRIDE;

    extern __shared__ __align__(16) __half dsm[];
    __half* As = dsm;
    __half* Bs = dsm + NST * A_STAGE;
    __half* combo = dsm + NST * (A_STAGE + B_STAGE);

    const int tid  = threadIdx.x;
    const int wid  = tid >> 5;
    const int lane = tid & 31;
    const int bn = blockIdx.x, bm = blockIdx.y;
    const int wm = (wid >> 2) * (BM / 2);
    const int wn = (wid & 3) * 32;

    const int KT = K >> 6;
    const bool patch = COMB && (bm == 0);

    cudaGridDependencySynchronize();

    if (patch) {
        for (int idx = tid; idx < DM; idx += 256) {
            int h = idx >> 6, d = idx & 63;
            float m = -1e30f;
            #pragma unroll
            for (int c = 0; c < NCHUNK; c++) m = fmaxf(m, g_cls_m[h*NCHUNK + c]);
            float den = 0.f, num = 0.f;
            #pragma unroll
            for (int c = 0; c < NCHUNK; c++) {
                float w = expf(g_cls_m[h*NCHUNK + c] - m);
                den += g_cls_s[h*NCHUNK + c] * w;
                num += g_cls_o[(size_t)(h*NCHUNK + c)*HD + d] * w;
            }
            combo[idx] = __float2half_rn(num / den);
        }
    }

    float acc[MI][4][4] = {};

    auto load_stage = [&](int kt, int buf) {
        const __half* Ag = A + (size_t)bm * BM * K + kt * 64;
        const __half* Bg = B + (size_t)bn * 128 * K + kt * 64;
        uint32_t a_s = smem_u32(As + buf * A_STAGE);
        uint32_t b_s = smem_u32(Bs + buf * B_STAGE);
        #pragma unroll
        for (int i = 0; i < ACH; i++) {
            int ch = tid + i * 256;
            int r = ch >> 3, cc = (ch & 7) * 8;
            CP_ASYNC_16(a_s + (uint32_t)(r * SMSTRIDE + cc) * 2, Ag + (size_t)r * K + cc);
        }
        #pragma unroll
        for (int i = 0; i < 4; i++) {
            int ch = tid + i * 256;
            int r = ch >> 3, cc = (ch & 7) * 8;
            CP_ASYNC_16(b_s + (uint32_t)(r * SMSTRIDE + cc) * 2, Bg + (size_t)r * K + cc);
        }
    };

    #pragma unroll
    for (int s = 0; s < NST; s++) { load_stage(s < KT ? s : KT-1, s); CP_COMMIT(); }

    for (int kt = 0; kt < KT; kt++) {
        const int buf = kt % NST;
        cp_wait<NST - 1>();
        __syncthreads();

        if (patch) {
            if (tid < 8) {
                int cc = tid * 8;
                *(uint4*)(As + buf * A_STAGE + cc) = *(const uint4*)(combo + kt * 64 + cc);
            }
            __syncthreads();
        }

        const uint32_t a_base = smem_u32(As + buf * A_STAGE);
        const uint32_t b_base = smem_u32(Bs + buf * B_STAGE);

        #pragma unroll
        for (int ks = 0; ks < 4; ks++) {
            uint32_t af[MI][4], bf[4][2];
            const int acol = ks * 16 + ((lane & 16) ? 8 : 0);
            const int bgrp = lane >> 3;
            #pragma unroll
            for (int mi = 0; mi < MI; mi++) {
                int row = wm + mi * 16 + (lane & 7) + ((lane & 8) ? 8 : 0);
                ldsm_x4(af[mi][0], af[mi][1], af[mi][2], af[mi][3],
                        a_base + (uint32_t)(row * SMSTRIDE + acol) * 2);
            }
            #pragma unroll
            for (int njp = 0; njp < 2; njp++) {
                int row = wn + (njp * 2 + (bgrp >> 1)) * 8 + (lane & 7);
                int col = ks * 16 + (bgrp & 1) * 8;
                uint32_t r0, r1, r2, r3;
                ldsm_x4(r0, r1, r2, r3, b_base + (uint32_t)(row * SMSTRIDE + col) * 2);
                bf[njp*2][0] = r0;  bf[njp*2][1] = r1;
                bf[njp*2+1][0] = r2; bf[njp*2+1][1] = r3;
            }
            #pragma unroll
            for (int mi = 0; mi < MI; mi++)
                #pragma unroll
                for (int nj = 0; nj < 4; nj++)
                    mma_f16(acc[mi][nj], af[mi], bf[nj]);
        }

        __syncthreads();
        int nkt = kt + NST < KT ? kt + NST : KT - 1;
        load_stage(nkt, buf);
        CP_COMMIT();
    }

    if (!ROPE) {
        #pragma unroll
        for (int nj = 0; nj < 4; nj++) {
            int gcol = bn * 128 + wn + nj * 8 + (lane & 3) * 2;
            float2 bv = *(const float2*)(bias + gcol);
            #pragma unroll
            for (int mi = 0; mi < MI; mi++) {
                int grow = bm * BM + wm + mi * 16 + (lane >> 2);
                float2 v0 = { acc[mi][nj][0] + bv.x, acc[mi][nj][1] + bv.y };
                float2 v1 = { acc[mi][nj][2] + bv.x, acc[mi][nj][3] + bv.y };
                *(float2*)(C + (size_t)grow * N + gcol)       = v0;
                *(float2*)(C + (size_t)(grow + 8) * N + gcol) = v1;
            }
        }
    } else {
        CP_WAIT_0();
        __syncthreads();
        float* ep = (float*)dsm;   // [128][132] fp32

        #pragma unroll
        for (int nj = 0; nj < 4; nj++) {
            int colq = wn + nj * 8 + (lane & 3) * 2;
            float2 bv = *(const float2*)(bias + bn * 128 + colq);
            #pragma unroll
            for (int mi = 0; mi < MI; mi++) {
                int row = wm + mi * 16 + (lane >> 2);
                ep[row * 132 + colq]           = acc[mi][nj][0] + bv.x;
                ep[row * 132 + colq + 1]       = acc[mi][nj][1] + bv.y;
                ep[(row + 8) * 132 + colq]     = acc[mi][nj][2] + bv.x;
                ep[(row + 8) * 132 + colq + 1] = acc[mi][nj][3] + bv.y;
            }
        }
        __syncthreads();

        const int rr  = tid >> 3;
        const int sub = tid & 7;
        const int hh  = sub >> 2;
        const int qq  = sub & 3;
        const int sec = bn / 6;
        const int hd  = (bn % 6) * 2 + hh;
        float* dst = (sec == 0) ? g_q : (sec == 1) ? g_k : g_v;
        __half* dsth = (sec == 0) ? g_qh : g_kh;

        float invf[8];
        if (sec < 2) {
            #pragma unroll
            for (int e = 0; e < 8; e++)
                invf[e] = exp2f(-(float)(qq * 8 + e) * ROPE_C);
        }

        #pragma unroll
        for (int rg = 0; rg < 4; rg++) {
            int r = rg * 32 + rr;
            int l = bm * 128 + r;
            const float* er = ep + r * 132 + hh * 64 + qq * 8;
            float x1[8], x2[8];
            *(float4*)&x1[0] = *(const float4*)er;
            *(float4*)&x1[4] = *(const float4*)(er + 4);
            *(float4*)&x2[0] = *(const float4*)(er + 32);
            *(float4*)&x2[4] = *(const float4*)(er + 36);
            float o1[8], o2[8];
            if (sec == 2) {
                #pragma unroll
                for (int e = 0; e < 8; e++) { o1[e] = x1[e]; o2[e] = x2[e]; }
            } else {
                #pragma unroll
                for (int e = 0; e < 8; e++) {
                    float s, c;
                    sincosf((float)l * invf[e], &s, &c);
                    o1[e] = x1[e] * c - x2[e] * s;
                    o2[e] = x1[e] * s + x2[e] * c;
                }
            }
            size_t off = ((size_t)hd * L + l) * HD + qq * 8;
            float* dp = dst + off;
            *(float4*)dp        = *(float4*)&o1[0];
            *(float4*)(dp + 4)  = *(float4*)&o1[4];
            *(float4*)(dp + 32) = *(float4*)&o2[0];
            *(float4*)(dp + 36) = *(float4*)&o2[4];
            if (sec < 2) {
                __half2 hp[4];
                hp[0] = __floats2half2_rn(o1[0], o1[1]);
                hp[1] = __floats2half2_rn(o1[2], o1[3]);
                hp[2] = __floats2half2_rn(o1[4], o1[5]);
                hp[3] = __floats2half2_rn(o1[6], o1[7]);
                *(uint2*)(dsth + off)     = *(uint2*)&hp[0];
                *(uint2*)(dsth + off + 4) = *(uint2*)&hp[2];
                hp[0] = __floats2half2_rn(o2[0], o2[1]);
                hp[1] = __floats2half2_rn(o2[2], o2[3]);
                hp[2] = __floats2half2_rn(o2[4], o2[5]);
                hp[3] = __floats2half2_rn(o2[6], o2[7]);
                *(uint2*)(dsth + off + 32) = *(uint2*)&hp[0];
                *(uint2*)(dsth + off + 36) = *(uint2*)&hp[2];
            }
        }
    }
}

// ====================== window attention (tensor-core scores) + CLS ===========
__global__ void __launch_bounds__(1024) window_attn_kernel(const int* __restrict__ mask) {
    extern __shared__ __align__(16) char smw[];
    int tid = threadIdx.x;

    cudaGridDependencySynchronize();

    if (blockIdx.x >= H * (L / TQ)) {
        // ---------------- CLS chunk block (fp32 path) ----------------
        float* sm  = (float*)smw;
        float* ksm = sm;
        float* q0  = ksm + CKEYS*65;
        float* ew  = q0 + HD;
        float* red = ew + CKEYS;

        int b2 = blockIdx.x - H * (L / TQ);
        int h = b2 >> 4, c = b2 & 15;
        int base = c * CKEYS;

        if (tid < HD) q0[tid] = g_q[(size_t)(h*L)*HD + tid];
        for (int idx = tid; idx < CKEYS*HD; idx += 1024) {
            int key = idx >> 6, d = idx & 63;
            ksm[key*65 + d] = g_k[(size_t)(h*L + base + key)*HD + d];
        }
        __syncthreads();

        float s = 0.f;
        if (tid < CKEYS) {
            #pragma unroll
            for (int d = 0; d < HD; d++) s += ksm[tid*65 + d] * q0[d];
            s = (mask[base + tid] != 0) ? s * SCALE : -1e30f;
            red[tid] = s;
        }
        __syncthreads();
        if (tid < 32) {
            float m = fmaxf(fmaxf(red[tid], red[tid+32]), fmaxf(red[tid+64], red[tid+96]));
            #pragma unroll
            for (int o = 16; o > 0; o >>= 1) m = fmaxf(m, __shfl_xor_sync(0xffffffffu, m, o));
            if (tid == 0) red[128] = m;
        }
        __syncthreads();
        float m_c = red[128];
        if (tid < CKEYS) { float e = expf(s - m_c); ew[tid] = e; red[tid] = e; }
        __syncthreads();
        if (tid < 32) {
            float su = red[tid] + red[tid+32] + red[tid+64] + red[tid+96];
            #pragma unroll
            for (int o = 16; o > 0; o >>= 1) su += __shfl_xor_sync(0xffffffffu, su, o);
            if (tid == 0) red[129] = su;
        }
        __syncthreads();
        float s_c = red[129];

        int d = tid & 63, grp = tid >> 6;
        const float* vb = g_v + (size_t)(h*L + base + grp*8)*HD + d;
        float acc = 0.f;
        #pragma unroll
        for (int kk = 0; kk < 8; kk++)
            acc += ew[grp*8 + kk] * vb[(size_t)kk*HD];
        __syncthreads();
        float* pacc = ksm;
        pacc[tid] = acc;
        __syncthreads();
        if (tid < HD) {
            float t = 0.f;
            #pragma unroll
            for (int g = 0; g < 16; g++) t += pacc[g*64 + tid];
            g_cls_o[(size_t)(h*NCHUNK + c)*HD + tid] = t;
            if (tid == 0) { g_cls_m[h*NCHUNK + c] = m_c; g_cls_s[h*NCHUNK + c] = s_c; }
        }
        return;
    }

    // ---------------- sliding-window tile block ----------------
    __half* ks_h = (__half*)smw;                 // 160 * 72 halves
    __half* qs_h = ks_h + WROWS * SMSTRIDE;      // 32 * 72 halves
    float*  sp   = (float*)(qs_h + TQ * SMSTRIDE); // 32 * 161 floats (score panel)
    int*    rv   = (int*)(sp + TQ * SPSTR);      // 160 ints

    int h  = blockIdx.x / (L / TQ);
    int qt = blockIdx.x % (L / TQ);
    int l0 = qt * TQ;
    int lo = l0 - 64;

    for (int idx = tid; idx < WROWS; idx += 1024) {
        int lr = lo + idx;
        rv[idx] = (lr >= 0 && lr < L) ? (mask[lr] != 0) : 0;
    }
    // K fp16: 160 rows x 64 halves (clamped rows; invalid masked later)
    for (int idx = tid; idx < WROWS * 8; idx += 1024) {
        int r = idx >> 3, c = (idx & 7) * 8;
        int lr = lo + r;
        lr = lr < 0 ? 0 : (lr > L-1 ? L-1 : lr);
        *(uint4*)(ks_h + r * SMSTRIDE + c) =
            *(const uint4*)(g_kh + ((size_t)(h*L + lr))*HD + c);
    }
    // Q fp16: 32 rows
    if (tid < TQ * 8) {
        int r = tid >> 3, c = (tid & 7) * 8;
        *(uint4*)(qs_h + r * SMSTRIDE + c) =
            *(const uint4*)(g_qh + ((size_t)(h*L + l0 + r))*HD + c);
    }
    __syncthreads();

    int wid  = tid >> 5;
    int lane = tid & 31;

    // ---- score panel S'[32][160] = Q @ K^T via mma.sync (20 warps) ----
    if (wid < 20) {
        int mi = wid & 1, njp = wid >> 1;
        float acc2[2][4] = {};
        uint32_t a_base = smem_u32(qs_h);
        uint32_t b_base = smem_u32(ks_h);
        #pragma unroll
        for (int kst = 0; kst < 4; kst++) {
            uint32_t af[4];
            int arow = mi*16 + (lane & 7) + ((lane & 8) ? 8 : 0);
            int acol = kst*16 + ((lane & 16) ? 8 : 0);
            ldsm_x4(af[0], af[1], af[2], af[3],
                    a_base + (uint32_t)(arow * SMSTRIDE + acol) * 2);
            int bgrp = lane >> 3;
            int brow = njp*16 + (bgrp >> 1) * 8 + (lane & 7);
            int bcol = kst*16 + (bgrp & 1) * 8;
            uint32_t r0, r1, r2, r3;
            ldsm_x4(r0, r1, r2, r3, b_base + (uint32_t)(brow * SMSTRIDE + bcol) * 2);
            uint32_t bf0[2] = {r0, r1}, bf1[2] = {r2, r3};
            mma_f16(acc2[0], af, bf0);
            mma_f16(acc2[1], af, bf1);
        }
        #pragma unroll
        for (int j8 = 0; j8 < 2; j8++) {
            int col = njp*16 + j8*8 + (lane & 3) * 2;
            int row = mi*16 + (lane >> 2);
            sp[row * SPSTR + col]         = acc2[j8][0];
            sp[row * SPSTR + col + 1]     = acc2[j8][1];
            sp[(row+8) * SPSTR + col]     = acc2[j8][2];
            sp[(row+8) * SPSTR + col + 1] = acc2[j8][3];
        }
    }
    __syncthreads();

    // ---- per-warp softmax on band sp[wq][wq+w] ----
    int wq = wid;
    int l = l0 + wq;
    float sc[4];
    #pragma unroll
    for (int w4 = 0; w4 < 4; w4++) {
        int r = wq + lane + w4*32;
        sc[w4] = rv[r] ? sp[wq * SPSTR + r] * SCALE : -1e30f;
    }
    float m = fmaxf(fmaxf(sc[0], sc[1]), fmaxf(sc[2], sc[3]));
    #pragma unroll
    for (int o = 16; o > 0; o >>= 1) m = fmaxf(m, __shfl_xor_sync(0xffffffffu, m, o));
    float e[4], sum = 0.f;
    #pragma unroll
    for (int w4 = 0; w4 < 4; w4++) { e[w4] = expf(sc[w4] - m); sum += e[w4]; }
    #pragma unroll
    for (int o = 16; o > 0; o >>= 1) sum += __shfl_xor_sync(0xffffffffu, sum, o);
    float inv = 1.0f / sum;
    #pragma unroll
    for (int w4 = 0; w4 < 4; w4++)
        sp[wq * SPSTR + wq + lane + w4*32] = e[w4] * inv;
    __syncwarp();

    // ---- V accumulation (paired-lane float4) ----
    const int wpair = lane >> 4;
    const int chunk = lane & 15;
    float4 a4 = {0.f, 0.f, 0.f, 0.f};
    const float* vbase = g_v + (size_t)h*L*HD + chunk*4;
    const float* wrow = sp + wq * SPSTR + wq;
    #pragma unroll 4
    for (int w = 0; w < WIN; w += 2) {
        float wt = wrow[w + wpair];
        int lr = lo + wq + w + wpair;
        lr = lr < 0 ? 0 : (lr > L-1 ? L-1 : lr);
        float4 v = *(const float4*)(vbase + (size_t)lr*HD);
        a4.x += wt * v.x;
        a4.y += wt * v.y;
        a4.z += wt * v.z;
        a4.w += wt * v.w;
    }
    a4.x += __shfl_xor_sync(0xffffffffu, a4.x, 16);
    a4.y += __shfl_xor_sync(0xffffffffu, a4.y, 16);
    a4.z += __shfl_xor_sync(0xffffffffu, a4.z, 16);
    a4.w += __shfl_xor_sync(0xffffffffu, a4.w, 16);

    if (wpair == 0) {
        __half2 hA, hB;
        hA.x = __float2half_rn(a4.x); hA.y = __float2half_rn(a4.y);
        hB.x = __float2half_rn(a4.z); hB.y = __float2half_rn(a4.w);
        size_t o = (size_t)l*DM + h*HD + chunk*4;
        *(__half2*)(g_Cf + o)     = hA;
        *(__half2*)(g_Cf + o + 2) = hB;
    }
}

// ====================== launch =================================================
extern "C" void kernel_launch(void* const* d_in, const int* in_sizes, int n_in,
                              void* d_out, int out_size) {
    (void)in_sizes; (void)n_in; (void)out_size;
    const float* emb   = (const float*)d_in[0];
    const int*   mask  = (const int*)  d_in[1];
    const float* W_qkv = (const float*)d_in[2];
    const float* b_qkv = (const float*)d_in[3];
    const float* W_o   = (const float*)d_in[4];
    const float* b_o   = (const float*)d_in[5];
    float* out = (float*)d_out;

    __half *p_Af, *p_Wqf, *p_Wof, *p_Cf;
    cudaGetSymbolAddress((void**)&p_Af,  g_Af);
    cudaGetSymbolAddress((void**)&p_Wqf, g_Wqf);
    cudaGetSymbolAddress((void**)&p_Wof, g_Wof);
    cudaGetSymbolAddress((void**)&p_Cf,  g_Cf);

    constexpr int GSMEM1 = 2 * (128 + 128) * SMSTRIDE * 2;           // 73728 B
    constexpr int GSMEM2 = 2 * (64  + 128) * SMSTRIDE * 2 + DM * 2;  // 56832 B
    cudaFuncSetAttribute((const void*)gemm_f16<128,2,true,false>,
                         cudaFuncAttributeMaxDynamicSharedMemorySize, GSMEM1);
    cudaFuncSetAttribute((const void*)gemm_f16<64,2,false,true>,
                         cudaFuncAttributeMaxDynamicSharedMemorySize, GSMEM2);
    // window smem: K 160*72*2 + Q 32*72*2 + sp 32*161*4 + rv 160*4
    constexpr int SMEM_WIN = (WROWS + TQ) * SMSTRIDE * 2 + TQ * SPSTR * 4 + WROWS * 4;
    cudaFuncSetAttribute(window_attn_kernel,
                         cudaFuncAttributeMaxDynamicSharedMemorySize, SMEM_WIN);

    cudaLaunchAttribute pdl[1];
    pdl[0].id = cudaLaunchAttributeProgrammaticStreamSerialization;
    pdl[0].val.programmaticStreamSerializationAllowed = 1;

    // 1. fused prep
    prep_kernel<<<NB_A + NB_WQ + NB_WO, 256>>>(emb, W_qkv, W_o);

    // 2. QKV GEMM + fused RoPE (writes fp32 q/k/v + fp16 q/k)
    {
        cudaLaunchConfig_t cfg = {};
        cfg.gridDim = dim3((3*DM)/128, L/128);
        cfg.blockDim = dim3(256);
        cfg.dynamicSmemBytes = GSMEM1;
        cfg.attrs = pdl; cfg.numAttrs = 1;
        const __half* Aa = p_Af; const __half* Bb = p_Wqf;
        const float* bb = b_qkv; float* cc = nullptr;
        int NN = 3*DM, KK = DM;
        cudaLaunchKernelEx(&cfg, gemm_f16<128,2,true,false>, Aa, Bb, bb, cc, NN, KK);
    }

    // 3. window attention (tensor-core scores) + CLS chunks
    {
        cudaLaunchConfig_t cfg = {};
        cfg.gridDim = dim3(H * (L/TQ) + H * NCHUNK);
        cfg.blockDim = dim3(1024);
        cfg.dynamicSmemBytes = SMEM_WIN;
        cfg.attrs = pdl; cfg.numAttrs = 1;
        const int* mm = mask;
        cudaLaunchKernelEx(&cfg, window_attn_kernel, mm);
    }

    // 4. output projection + in-kernel CLS combine
    {
        cudaLaunchConfig_t cfg = {};
        cfg.gridDim = dim3(DM/128, L/64);
        cfg.blockDim = dim3(256);
        cfg.dynamicSmemBytes = GSMEM2;
        cfg.attrs = pdl; cfg.numAttrs = 1;
        const __half* Aa = p_Cf; const __half* Bb = p_Wof;
        const float* bb = b_o; float* cc = out;
        int NN = DM, KK = DM;
        cudaLaunchKernelEx(&cfg, gemm_f16<64,2,false,true>, Aa, Bb, bb, cc, NN, KK);
    }
}

// round 17
// speedup vs baseline: 5.6966x; 1.3885x over previous
#include <cuda_runtime.h>
#include <cuda_fp16.h>
#include <math.h>
#include <stdint.h>

#define L    2048
#define DM   768
#define H    12
#define HD   64
#define WIN  128
#define TQ   32
#define WROWS 160
#define NCHUNK 16
#define CKEYS  128
#define SPSTR 161     // floats per score-panel row
#define PPSTR 168     // halves per weight-panel row (160 + 8 pad)

static constexpr float SCALE = 0.03608439182435161f;  // 1/sqrt(768)
static constexpr float ROPE_C = 0.41524101186092029f; // log2(10000)/32

// ====================== scratch ================================================
__device__ __half g_qh[H * L * HD];
__device__ __half g_kh[H * L * HD];
__device__ __half g_vh[H * L * HD];
__device__ float g_cls_m[H * NCHUNK];
__device__ float g_cls_s[H * NCHUNK];
__device__ float g_cls_o[H * NCHUNK * HD];

__device__ __half g_Af[L * DM];
__device__ __half g_Wqf[3*DM*DM];
__device__ __half g_Wof[DM*DM];
__device__ __half g_Cf[L * DM];

// ====================== fused prep kernel ======================================
#define NB_A  ((L*DM)/256)
#define NB_WQ ((3*DM/32)*(DM/32))
#define NB_WO ((DM/32)*(DM/32))

__global__ void __launch_bounds__(256) prep_kernel(
        const float* __restrict__ emb, const float* __restrict__ W_qkv,
        const float* __restrict__ W_o) {
    __shared__ float t[32][33];
    int b = blockIdx.x;
    int tid = threadIdx.x;

    if (b < NB_A) {
        int i = b * 256 + tid;
        g_Af[i] = __float2half_rn(emb[i]);
        return;
    }
    const float* W;
    __half* T;
    int K = DM, N, b2;
    if (b < NB_A + NB_WQ) {
        b2 = b - NB_A;  W = W_qkv;  T = g_Wqf;  N = 3*DM;
    } else {
        b2 = b - NB_A - NB_WQ;  W = W_o;  T = g_Wof;  N = DM;
    }
    int nblk = N / 32;
    int n0 = (b2 % nblk) * 32, k0 = (b2 / nblk) * 32;
    int tx = tid & 31, ty = tid >> 5;
    #pragma unroll
    for (int i = ty; i < 32; i += 8)
        t[i][tx] = W[(size_t)(k0 + i) * N + n0 + tx];
    __syncthreads();
    #pragma unroll
    for (int i = ty; i < 32; i += 8)
        T[(size_t)(n0 + i) * K + k0 + tx] = __float2half_rn(t[tx][i]);
}

// ====================== mma.sync helpers ======================================
__device__ __forceinline__ uint32_t smem_u32(const void* p) {
    uint32_t a;
    asm("{ .reg .u64 t; cvta.to.shared.u64 t, %1; cvt.u32.u64 %0, t; }" : "=r"(a) : "l"(p));
    return a;
}
__device__ __forceinline__ void ldsm_x4(uint32_t& r0, uint32_t& r1, uint32_t& r2, uint32_t& r3,
                                        uint32_t addr) {
    asm volatile("ldmatrix.sync.aligned.m8n8.x4.shared.b16 {%0,%1,%2,%3}, [%4];"
                 : "=r"(r0), "=r"(r1), "=r"(r2), "=r"(r3) : "r"(addr));
}
__device__ __forceinline__ void ldsm_x2_trans(uint32_t& r0, uint32_t& r1, uint32_t addr) {
    asm volatile("ldmatrix.sync.aligned.m8n8.x2.trans.shared.b16 {%0,%1}, [%2];"
                 : "=r"(r0), "=r"(r1) : "r"(addr));
}
__device__ __forceinline__ void mma_f16(float* d, const uint32_t* a, const uint32_t* b) {
    asm volatile("mma.sync.aligned.m16n8k16.row.col.f32.f16.f16.f32 "
                 "{%0,%1,%2,%3}, {%4,%5,%6,%7}, {%8,%9}, {%0,%1,%2,%3};"
                 : "+f"(d[0]), "+f"(d[1]), "+f"(d[2]), "+f"(d[3])
                 : "r"(a[0]), "r"(a[1]), "r"(a[2]), "r"(a[3]), "r"(b[0]), "r"(b[1]));
}
#define CP_ASYNC_16(dst, src) \
    asm volatile("cp.async.cg.shared.global [%0], [%1], 16;" :: "r"(dst), "l"(src))
#define CP_COMMIT() asm volatile("cp.async.commit_group;" ::: "memory")
#define CP_WAIT_0() asm volatile("cp.async.wait_group 0;" ::: "memory")
template<int N> __device__ __forceinline__ void cp_wait() {
    asm volatile("cp.async.wait_group %0;" :: "n"(N) : "memory");
}

// ====================== HMMA fp16 GEMM (BK=64 stages) =========================
#define SMSTRIDE 72

template<int BM, int NST, bool ROPE, bool COMB>
__global__ void __launch_bounds__(256, 2)
gemm_f16(const __half* __restrict__ A, const __half* __restrict__ B,
         const float* __restrict__ bias, float* __restrict__ C,
         int N, int K) {
    constexpr int MI  = BM / 32;
    constexpr int ACH = BM / 32;
    constexpr int A_STAGE = BM * SMSTRIDE;
    constexpr int B_STAGE = 128 * SMSTRIDE;

    extern __shared__ __align__(16) __half dsm[];
    __half* As = dsm;
    __half* Bs = dsm + NST * A_STAGE;
    __half* combo = dsm + NST * (A_STAGE + B_STAGE);

    const int tid  = threadIdx.x;
    const int wid  = tid >> 5;
    const int lane = tid & 31;
    const int bn = blockIdx.x, bm = blockIdx.y;
    const int wm = (wid >> 2) * (BM / 2);
    const int wn = (wid & 3) * 32;

    const int KT = K >> 6;
    const bool patch = COMB && (bm == 0);

    cudaGridDependencySynchronize();

    if (patch) {
        for (int idx = tid; idx < DM; idx += 256) {
            int h = idx >> 6, d = idx & 63;
            float m = -1e30f;
            #pragma unroll
            for (int c = 0; c < NCHUNK; c++) m = fmaxf(m, g_cls_m[h*NCHUNK + c]);
            float den = 0.f, num = 0.f;
            #pragma unroll
            for (int c = 0; c < NCHUNK; c++) {
                float w = expf(g_cls_m[h*NCHUNK + c] - m);
                den += g_cls_s[h*NCHUNK + c] * w;
                num += g_cls_o[(size_t)(h*NCHUNK + c)*HD + d] * w;
            }
            combo[idx] = __float2half_rn(num / den);
        }
    }

    float acc[MI][4][4] = {};

    auto load_stage = [&](int kt, int buf) {
        const __half* Ag = A + (size_t)bm * BM * K + kt * 64;
        const __half* Bg = B + (size_t)bn * 128 * K + kt * 64;
        uint32_t a_s = smem_u32(As + buf * A_STAGE);
        uint32_t b_s = smem_u32(Bs + buf * B_STAGE);
        #pragma unroll
        for (int i = 0; i < ACH; i++) {
            int ch = tid + i * 256;
            int r = ch >> 3, cc = (ch & 7) * 8;
            CP_ASYNC_16(a_s + (uint32_t)(r * SMSTRIDE + cc) * 2, Ag + (size_t)r * K + cc);
        }
        #pragma unroll
        for (int i = 0; i < 4; i++) {
            int ch = tid + i * 256;
            int r = ch >> 3, cc = (ch & 7) * 8;
            CP_ASYNC_16(b_s + (uint32_t)(r * SMSTRIDE + cc) * 2, Bg + (size_t)r * K + cc);
        }
    };

    #pragma unroll
    for (int s = 0; s < NST; s++) { load_stage(s < KT ? s : KT-1, s); CP_COMMIT(); }

    for (int kt = 0; kt < KT; kt++) {
        const int buf = kt % NST;
        cp_wait<NST - 1>();
        __syncthreads();

        if (patch) {
            if (tid < 8) {
                int cc = tid * 8;
                *(uint4*)(As + buf * A_STAGE + cc) = *(const uint4*)(combo + kt * 64 + cc);
            }
            __syncthreads();
        }

        const uint32_t a_base = smem_u32(As + buf * A_STAGE);
        const uint32_t b_base = smem_u32(Bs + buf * B_STAGE);

        #pragma unroll
        for (int ks = 0; ks < 4; ks++) {
            uint32_t af[MI][4], bf[4][2];
            const int acol = ks * 16 + ((lane & 16) ? 8 : 0);
            const int bgrp = lane >> 3;
            #pragma unroll
            for (int mi = 0; mi < MI; mi++) {
                int row = wm + mi * 16 + (lane & 7) + ((lane & 8) ? 8 : 0);
                ldsm_x4(af[mi][0], af[mi][1], af[mi][2], af[mi][3],
                        a_base + (uint32_t)(row * SMSTRIDE + acol) * 2);
            }
            #pragma unroll
            for (int njp = 0; njp < 2; njp++) {
                int row = wn + (njp * 2 + (bgrp >> 1)) * 8 + (lane & 7);
                int col = ks * 16 + (bgrp & 1) * 8;
                uint32_t r0, r1, r2, r3;
                ldsm_x4(r0, r1, r2, r3, b_base + (uint32_t)(row * SMSTRIDE + col) * 2);
                bf[njp*2][0] = r0;  bf[njp*2][1] = r1;
                bf[njp*2+1][0] = r2; bf[njp*2+1][1] = r3;
            }
            #pragma unroll
            for (int mi = 0; mi < MI; mi++)
                #pragma unroll
                for (int nj = 0; nj < 4; nj++)
                    mma_f16(acc[mi][nj], af[mi], bf[nj]);
        }

        __syncthreads();
        int nkt = kt + NST < KT ? kt + NST : KT - 1;
        load_stage(nkt, buf);
        CP_COMMIT();
    }

    if (!ROPE) {
        #pragma unroll
        for (int nj = 0; nj < 4; nj++) {
            int gcol = bn * 128 + wn + nj * 8 + (lane & 3) * 2;
            float2 bv = *(const float2*)(bias + gcol);
            #pragma unroll
            for (int mi = 0; mi < MI; mi++) {
                int grow = bm * BM + wm + mi * 16 + (lane >> 2);
                float2 v0 = { acc[mi][nj][0] + bv.x, acc[mi][nj][1] + bv.y };
                float2 v1 = { acc[mi][nj][2] + bv.x, acc[mi][nj][3] + bv.y };
                *(float2*)(C + (size_t)grow * N + gcol)       = v0;
                *(float2*)(C + (size_t)(grow + 8) * N + gcol) = v1;
            }
        }
    } else {
        CP_WAIT_0();
        __syncthreads();
        float* ep = (float*)dsm;   // [128][132] fp32

        #pragma unroll
        for (int nj = 0; nj < 4; nj++) {
            int colq = wn + nj * 8 + (lane & 3) * 2;
            float2 bv = *(const float2*)(bias + bn * 128 + colq);
            #pragma unroll
            for (int mi = 0; mi < MI; mi++) {
                int row = wm + mi * 16 + (lane >> 2);
                ep[row * 132 + colq]           = acc[mi][nj][0] + bv.x;
                ep[row * 132 + colq + 1]       = acc[mi][nj][1] + bv.y;
                ep[(row + 8) * 132 + colq]     = acc[mi][nj][2] + bv.x;
                ep[(row + 8) * 132 + colq + 1] = acc[mi][nj][3] + bv.y;
            }
        }
        __syncthreads();

        const int rr  = tid >> 3;
        const int sub = tid & 7;
        const int hh  = sub >> 2;
        const int qq  = sub & 3;
        const int sec = bn / 6;            // 0=q 1=k 2=v
        const int hd  = (bn % 6) * 2 + hh;
        __half* dsth = (sec == 0) ? g_qh : (sec == 1) ? g_kh : g_vh;

        float invf[8];
        if (sec < 2) {
            #pragma unroll
            for (int e = 0; e < 8; e++)
                invf[e] = exp2f(-(float)(qq * 8 + e) * ROPE_C);
        }

        #pragma unroll
        for (int rg = 0; rg < 4; rg++) {
            int r = rg * 32 + rr;
            int l = bm * 128 + r;
            const float* er = ep + r * 132 + hh * 64 + qq * 8;
            float x1[8], x2[8];
            *(float4*)&x1[0] = *(const float4*)er;
            *(float4*)&x1[4] = *(const float4*)(er + 4);
            *(float4*)&x2[0] = *(const float4*)(er + 32);
            *(float4*)&x2[4] = *(const float4*)(er + 36);
            float o1[8], o2[8];
            if (sec == 2) {
                #pragma unroll
                for (int e = 0; e < 8; e++) { o1[e] = x1[e]; o2[e] = x2[e]; }
            } else {
                #pragma unroll
                for (int e = 0; e < 8; e++) {
                    float s, c;
                    sincosf((float)l * invf[e], &s, &c);
                    o1[e] = x1[e] * c - x2[e] * s;
                    o2[e] = x1[e] * s + x2[e] * c;
                }
            }
            size_t off = ((size_t)hd * L + l) * HD + qq * 8;
            __half2 hp[4];
            hp[0] = __floats2half2_rn(o1[0], o1[1]);
            hp[1] = __floats2half2_rn(o1[2], o1[3]);
            hp[2] = __floats2half2_rn(o1[4], o1[5]);
            hp[3] = __floats2half2_rn(o1[6], o1[7]);
            *(uint2*)(dsth + off)     = *(uint2*)&hp[0];
            *(uint2*)(dsth + off + 4) = *(uint2*)&hp[2];
            hp[0] = __floats2half2_rn(o2[0], o2[1]);
            hp[1] = __floats2half2_rn(o2[2], o2[3]);
            hp[2] = __floats2half2_rn(o2[4], o2[5]);
            hp[3] = __floats2half2_rn(o2[6], o2[7]);
            *(uint2*)(dsth + off + 32) = *(uint2*)&hp[0];
            *(uint2*)(dsth + off + 36) = *(uint2*)&hp[2];
        }
    }
}

// ====================== window attention (full tensor-core) + CLS =============
__global__ void __launch_bounds__(1024) window_attn_kernel(const int* __restrict__ mask) {
    extern __shared__ __align__(16) char smw[];
    int tid = threadIdx.x;

    cudaGridDependencySynchronize();

    if (blockIdx.x >= H * (L / TQ)) {
        // ---------------- CLS chunk block ----------------
        float* sm  = (float*)smw;
        float* ksm = sm;
        float* q0  = ksm + CKEYS*65;
        float* ew  = q0 + HD;
        float* red = ew + CKEYS;

        int b2 = blockIdx.x - H * (L / TQ);
        int h = b2 >> 4, c = b2 & 15;
        int base = c * CKEYS;

        if (tid < HD) q0[tid] = __half2float(g_qh[(size_t)(h*L)*HD + tid]);
        for (int idx = tid; idx < CKEYS*HD; idx += 1024) {
            int key = idx >> 6, d = idx & 63;
            ksm[key*65 + d] = __half2float(g_kh[(size_t)(h*L + base + key)*HD + d]);
        }
        __syncthreads();

        float s = 0.f;
        if (tid < CKEYS) {
            #pragma unroll
            for (int d = 0; d < HD; d++) s += ksm[tid*65 + d] * q0[d];
            s = (mask[base + tid] != 0) ? s * SCALE : -1e30f;
            red[tid] = s;
        }
        __syncthreads();
        if (tid < 32) {
            float m = fmaxf(fmaxf(red[tid], red[tid+32]), fmaxf(red[tid+64], red[tid+96]));
            #pragma unroll
            for (int o = 16; o > 0; o >>= 1) m = fmaxf(m, __shfl_xor_sync(0xffffffffu, m, o));
            if (tid == 0) red[128] = m;
        }
        __syncthreads();
        float m_c = red[128];
        if (tid < CKEYS) { float e = expf(s - m_c); ew[tid] = e; red[tid] = e; }
        __syncthreads();
        if (tid < 32) {
            float su = red[tid] + red[tid+32] + red[tid+64] + red[tid+96];
            #pragma unroll
            for (int o = 16; o > 0; o >>= 1) su += __shfl_xor_sync(0xffffffffu, su, o);
            if (tid == 0) red[129] = su;
        }
        __syncthreads();
        float s_c = red[129];

        int d = tid & 63, grp = tid >> 6;
        const __half* vb = g_vh + (size_t)(h*L + base + grp*8)*HD + d;
        float acc = 0.f;
        #pragma unroll
        for (int kk = 0; kk < 8; kk++)
            acc += ew[grp*8 + kk] * __half2float(vb[(size_t)kk*HD]);
        __syncthreads();
        float* pacc = ksm;
        pacc[tid] = acc;
        __syncthreads();
        if (tid < HD) {
            float t = 0.f;
            #pragma unroll
            for (int g = 0; g < 16; g++) t += pacc[g*64 + tid];
            g_cls_o[(size_t)(h*NCHUNK + c)*HD + tid] = t;
            if (tid == 0) { g_cls_m[h*NCHUNK + c] = m_c; g_cls_s[h*NCHUNK + c] = s_c; }
        }
        return;
    }

    // ---------------- sliding-window tile block ----------------
    __half* ks_h = (__half*)smw;                     // 160 * 72
    __half* qs_h = ks_h + WROWS * SMSTRIDE;          // 32 * 72
    __half* vs_h = qs_h + TQ * SMSTRIDE;             // 160 * 72
    float*  sp   = (float*)(vs_h + WROWS * SMSTRIDE);// 32 * 161 fp32
    __half* pp   = (__half*)(sp + TQ * SPSTR);       // 32 * 168 fp16
    int*    rv   = (int*)(pp + TQ * PPSTR);          // 160

    int h  = blockIdx.x / (L / TQ);
    int qt = blockIdx.x % (L / TQ);
    int l0 = qt * TQ;
    int lo = l0 - 64;

    for (int idx = tid; idx < WROWS; idx += 1024) {
        int lr = lo + idx;
        rv[idx] = (lr >= 0 && lr < L) ? (mask[lr] != 0) : 0;
    }
    // K and V fp16 (clamped rows; invalid masked via softmax)
    for (int idx = tid; idx < WROWS * 16; idx += 1024) {
        int kv = idx >= WROWS * 8;
        int i2 = idx - kv * WROWS * 8;
        int r = i2 >> 3, c = (i2 & 7) * 8;
        int lr = lo + r;
        lr = lr < 0 ? 0 : (lr > L-1 ? L-1 : lr);
        const __half* src = kv ? g_vh : g_kh;
        __half* dst = kv ? vs_h : ks_h;
        *(uint4*)(dst + r * SMSTRIDE + c) =
            *(const uint4*)(src + ((size_t)(h*L + lr))*HD + c);
    }
    if (tid < TQ * 8) {
        int r = tid >> 3, c = (tid & 7) * 8;
        *(uint4*)(qs_h + r * SMSTRIDE + c) =
            *(const uint4*)(g_qh + ((size_t)(h*L + l0 + r))*HD + c);
    }
    __syncthreads();

    int wid  = tid >> 5;
    int lane = tid & 31;

    // ---- scores S'[32][160] = Q @ K^T (20 warps) ----
    if (wid < 20) {
        int mi = wid & 1, njp = wid >> 1;
        float acc2[2][4] = {};
        uint32_t a_base = smem_u32(qs_h);
        uint32_t b_base = smem_u32(ks_h);
        #pragma unroll
        for (int kst = 0; kst < 4; kst++) {
            uint32_t af[4];
            int arow = mi*16 + (lane & 7) + ((lane & 8) ? 8 : 0);
            int acol = kst*16 + ((lane & 16) ? 8 : 0);
            ldsm_x4(af[0], af[1], af[2], af[3],
                    a_base + (uint32_t)(arow * SMSTRIDE + acol) * 2);
            int bgrp = lane >> 3;
            int brow = njp*16 + (bgrp >> 1) * 8 + (lane & 7);
            int bcol = kst*16 + (bgrp & 1) * 8;
            uint32_t r0, r1, r2, r3;
            ldsm_x4(r0, r1, r2, r3, b_base + (uint32_t)(brow * SMSTRIDE + bcol) * 2);
            uint32_t bf0[2] = {r0, r1}, bf1[2] = {r2, r3};
            mma_f16(acc2[0], af, bf0);
            mma_f16(acc2[1], af, bf1);
        }
        #pragma unroll
        for (int j8 = 0; j8 < 2; j8++) {
            int col = njp*16 + j8*8 + (lane & 3) * 2;
            int row = mi*16 + (lane >> 2);
            sp[row * SPSTR + col]         = acc2[j8][0];
            sp[row * SPSTR + col + 1]     = acc2[j8][1];
            sp[(row+8) * SPSTR + col]     = acc2[j8][2];
            sp[(row+8) * SPSTR + col + 1] = acc2[j8][3];
        }
    }
    __syncthreads();

    // ---- per-warp softmax; write weight panel P (fp16, zeros outside band) ----
    int wq = wid;
    float sc[4];
    #pragma unroll
    for (int w4 = 0; w4 < 4; w4++) {
        int r = wq + lane + w4*32;
        sc[w4] = rv[r] ? sp[wq * SPSTR + r] * SCALE : -1e30f;
    }
    float m = fmaxf(fmaxf(sc[0], sc[1]), fmaxf(sc[2], sc[3]));
    #pragma unroll
    for (int o = 16; o > 0; o >>= 1) m = fmaxf(m, __shfl_xor_sync(0xffffffffu, m, o));
    float e[4], sum = 0.f;
    #pragma unroll
    for (int w4 = 0; w4 < 4; w4++) { e[w4] = expf(sc[w4] - m); sum += e[w4]; }
    #pragma unroll
    for (int o = 16; o > 0; o >>= 1) sum += __shfl_xor_sync(0xffffffffu, sum, o);
    float inv = 1.0f / sum;
    #pragma unroll
    for (int w4 = 0; w4 < 4; w4++)
        pp[wq * PPSTR + wq + lane + w4*32] = __float2half_rn(e[w4] * inv);
    // zero the 32 out-of-band positions: r in [0,wq) U [wq+128,160)
    {
        int rz = wq + 128 + lane;
        rz = rz >= 160 ? rz - 160 : rz;
        pp[wq * PPSTR + rz] = __float2half_rn(0.f);
    }
    __syncthreads();

    // ---- PV: out[32][64] = P[32][160] @ V[160][64] (16 warps) ----
    if (wid < 16) {
        int mi = wid & 1, nj8 = wid >> 1;     // m16 tile, n8 tile
        int d0 = nj8 * 8;
        float acc4[4] = {};
        uint32_t p_base = smem_u32(pp);
        uint32_t v_base = smem_u32(vs_h);
        #pragma unroll
        for (int kst = 0; kst < 10; kst++) {
            uint32_t af[4];
            int arow = mi*16 + (lane & 7) + ((lane & 8) ? 8 : 0);
            int acol = kst*16 + ((lane & 16) ? 8 : 0);
            ldsm_x4(af[0], af[1], af[2], af[3],
                    p_base + (uint32_t)(arow * PPSTR + acol) * 2);
            int vrow = kst*16 + (lane & 15);
            uint32_t b0, b1;
            ldsm_x2_trans(b0, b1, v_base + (uint32_t)(vrow * SMSTRIDE + d0) * 2);
            uint32_t bf[2] = {b0, b1};
            mma_f16(acc4, af, bf);
        }
        int row = l0 + mi*16 + (lane >> 2);
        int col = h*HD + d0 + (lane & 3) * 2;
        __half2 c01 = __floats2half2_rn(acc4[0], acc4[1]);
        __half2 c23 = __floats2half2_rn(acc4[2], acc4[3]);
        *(__half2*)(g_Cf + (size_t)row * DM + col)       = c01;
        *(__half2*)(g_Cf + (size_t)(row + 8) * DM + col) = c23;
    }
}

// ====================== launch =================================================
extern "C" void kernel_launch(void* const* d_in, const int* in_sizes, int n_in,
                              void* d_out, int out_size) {
    (void)in_sizes; (void)n_in; (void)out_size;
    const float* emb   = (const float*)d_in[0];
    const int*   mask  = (const int*)  d_in[1];
    const float* W_qkv = (const float*)d_in[2];
    const float* b_qkv = (const float*)d_in[3];
    const float* W_o   = (const float*)d_in[4];
    const float* b_o   = (const float*)d_in[5];
    float* out = (float*)d_out;

    __half *p_Af, *p_Wqf, *p_Wof, *p_Cf;
    cudaGetSymbolAddress((void**)&p_Af,  g_Af);
    cudaGetSymbolAddress((void**)&p_Wqf, g_Wqf);
    cudaGetSymbolAddress((void**)&p_Wof, g_Wof);
    cudaGetSymbolAddress((void**)&p_Cf,  g_Cf);

    constexpr int GSMEM1 = 2 * (128 + 128) * SMSTRIDE * 2;           // 73728 B
    constexpr int GSMEM2 = 2 * (64  + 128) * SMSTRIDE * 2 + DM * 2;  // 56832 B
    cudaFuncSetAttribute((const void*)gemm_f16<128,2,true,false>,
                         cudaFuncAttributeMaxDynamicSharedMemorySize, GSMEM1);
    cudaFuncSetAttribute((const void*)gemm_f16<64,2,false,true>,
                         cudaFuncAttributeMaxDynamicSharedMemorySize, GSMEM2);
    // window smem: K/V 2*160*72*2 + Q 32*72*2 + sp 32*161*4 + pp 32*168*2 + rv 160*4
    constexpr int SMEM_WIN = (2*WROWS + TQ) * SMSTRIDE * 2
                           + TQ * SPSTR * 4 + TQ * PPSTR * 2 + WROWS * 4;
    cudaFuncSetAttribute(window_attn_kernel,
                         cudaFuncAttributeMaxDynamicSharedMemorySize, SMEM_WIN);

    cudaLaunchAttribute pdl[1];
    pdl[0].id = cudaLaunchAttributeProgrammaticStreamSerialization;
    pdl[0].val.programmaticStreamSerializationAllowed = 1;

    // 1. fused prep
    prep_kernel<<<NB_A + NB_WQ + NB_WO, 256>>>(emb, W_qkv, W_o);

    // 2. QKV GEMM + fused RoPE (fp16 q/k/v outputs)
    {
        cudaLaunchConfig_t cfg = {};
        cfg.gridDim = dim3((3*DM)/128, L/128);
        cfg.blockDim = dim3(256);
        cfg.dynamicSmemBytes = GSMEM1;
        cfg.attrs = pdl; cfg.numAttrs = 1;
        const __half* Aa = p_Af; const __half* Bb = p_Wqf;
        const float* bb = b_qkv; float* cc = nullptr;
        int NN = 3*DM, KK = DM;
        cudaLaunchKernelEx(&cfg, gemm_f16<128,2,true,false>, Aa, Bb, bb, cc, NN, KK);
    }

    // 3. window attention (full tensor-core) + CLS chunks
    {
        cudaLaunchConfig_t cfg = {};
        cfg.gridDim = dim3(H * (L/TQ) + H * NCHUNK);
        cfg.blockDim = dim3(1024);
        cfg.dynamicSmemBytes = SMEM_WIN;
        cfg.attrs = pdl; cfg.numAttrs = 1;
        const int* mm = mask;
        cudaLaunchKernelEx(&cfg, window_attn_kernel, mm);
    }

    // 4. output projection + in-kernel CLS combine
    {
        cudaLaunchConfig_t cfg = {};
        cfg.gridDim = dim3(DM/128, L/64);
        cfg.blockDim = dim3(256);
        cfg.dynamicSmemBytes = GSMEM2;
        cfg.attrs = pdl; cfg.numAttrs = 1;
        const __half* Aa = p_Cf; const __half* Bb = p_Wof;
        const float* bb = b_o; float* cc = out;
        int NN = DM, KK = DM;
        cudaLaunchKernelEx(&cfg, gemm_f16<64,2,false,true>, Aa, Bb, bb, cc, NN, KK);
    }
}